// round 4
// baseline (speedup 1.0000x reference)
#include <cuda_runtime.h>
#include <math.h>

// Problem constants
#define BB 8
#define KK 1024
#define DD 256
#define HH 8
#define RR 4
#define LL 1028      // RR + KK
#define HD 32
#define IMGF 224.0f
#define MAXPF 1023.0f

typedef unsigned long long u64;

// ---------------- packed f32x2 helpers -------------------------------------
__device__ __forceinline__ u64 ffma2(u64 a, u64 b, u64 c) {
    u64 d;
    asm("fma.rn.f32x2 %0, %1, %2, %3;" : "=l"(d) : "l"(a), "l"(b), "l"(c));
    return d;
}
__device__ __forceinline__ u64 pack2(float lo, float hi) {
    u64 r;
    asm("mov.b64 %0, {%1, %2};" : "=l"(r) : "f"(lo), "f"(hi));
    return r;
}
__device__ __forceinline__ float2 unpack2(u64 v) {
    float2 r;
    asm("mov.b64 {%0, %1}, %2;" : "=f"(r.x), "=f"(r.y) : "l"(v));
    return r;
}

// ---------------- scratch (device globals; no allocation allowed) ----------
__device__ float g_xfull[BB * LL * DD];        // post-embed, post-rope (pre-LN)
__device__ float g_xn[BB * LL * DD];           // LN(x)
__device__ int   g_allowed[BB * LL];           // key-allowed mask
__device__ int   g_isctx[BB * KK];             // per-token selector
__device__ int   g_kidx[BB * LL];              // compacted allowed-key list
__device__ int   g_kcnt[BB];                   // count per batch
__device__ int   g_qidx[BB * KK];              // queries sorted ctx-first
__device__ float g_qkv_c[BB * LL * 3 * DD];    // ctx block QKV
__device__ float g_qkv_t[BB * LL * 3 * DD];    // tgt block QKV
__device__ float g_attn[BB * KK * DD];         // selected attention out (pre-Wo)
__device__ float g_tmp[BB * KK * DD];          // attn @ Wo_sel + bo_sel
__device__ float g_x2[BB * KK * DD];           // x + attn_out (residual 1)
__device__ float g_x2n[BB * KK * DD];          // LN(x2)
__device__ float g_h1[BB * KK * 4 * DD];       // gelu(mlp1)

// ---------------- prep: embed add + rope2d + LN ---------------------------
__global__ __launch_bounds__(256) void prep_kernel(
    const float* __restrict__ x, const int* __restrict__ coords,
    const int* __restrict__ ctxid, const float* __restrict__ tgt_e,
    const float* __restrict__ ctx_e, const float* __restrict__ regs,
    const float* __restrict__ rope, const float* __restrict__ ng,
    const float* __restrict__ nb)
{
    int blk = blockIdx.x;
    int b = blk / LL;
    int l = blk - b * LL;
    int d = threadIdx.x;

    __shared__ float srow[DD];
    __shared__ float red[2][8];

    float v;
    int ic = 1;
    if (l < RR) {
        v = regs[l * DD + d] + ctx_e[d];
    } else {
        int k = l - RR;
        ic = ctxid[b * KK + k] > 0;
        v = x[((size_t)(b * KK + k)) * DD + d] + (ic ? ctx_e[d] : tgt_e[d]);
    }
    srow[d] = v;
    __syncthreads();

    float rv = v;
    if (l >= RR) {
        int k = l - RR;
        int cy = coords[(size_t)(b * KK + k) * 2 + 0];
        int cx = coords[(size_t)(b * KK + k) * 2 + 1];
        float cny = fminf(fmaxf(((float)cy / IMGF) * MAXPF, 0.f), MAXPF);
        float cnx = fminf(fmaxf(((float)cx / IMGF) * MAXPF, 0.f), MAXPF);
        int yi = (int)cny;
        int xi = (int)cnx;
        int j; const float* cp;
        if (d < 128) { j = d >> 1;         cp = rope + ((size_t)xi * 64 + j) * 2; }
        else         { j = (d - 128) >> 1; cp = rope + ((size_t)yi * 64 + j) * 2; }
        float c = cp[0], s = cp[1];
        float p0 = srow[d & ~1];
        float p1 = srow[d | 1];
        rv = (d & 1) ? (p0 * s + p1 * c) : (p0 * c - p1 * s);
    }

    g_xfull[((size_t)(b * LL + l)) * DD + d] = rv;
    if (d == 0) {
        g_allowed[b * LL + l] = (l < RR) ? 1 : ic;
        if (l >= RR) g_isctx[b * KK + (l - RR)] = ic;
    }

    // LayerNorm over 256
    float s1 = rv, s2 = rv * rv;
    #pragma unroll
    for (int o = 16; o; o >>= 1) {
        s1 += __shfl_down_sync(0xffffffffu, s1, o);
        s2 += __shfl_down_sync(0xffffffffu, s2, o);
    }
    int wid = d >> 5, lane = d & 31;
    if (lane == 0) { red[0][wid] = s1; red[1][wid] = s2; }
    __syncthreads();
    if (d == 0) {
        float t1 = 0.f, t2 = 0.f;
        #pragma unroll
        for (int i = 0; i < 8; i++) { t1 += red[0][i]; t2 += red[1][i]; }
        red[0][0] = t1; red[1][0] = t2;
    }
    __syncthreads();
    float mean = red[0][0] * (1.f / DD);
    float var  = red[1][0] * (1.f / DD) - mean * mean;
    float rstd = rsqrtf(var + 1e-5f);
    g_xn[((size_t)(b * LL + l)) * DD + d] = (rv - mean) * rstd * ng[d] + nb[d];
}

// ---------------- compaction: allowed-key list + ctx-first query order -----
__global__ __launch_bounds__(128) void compact_kernel()
{
    int b = blockIdx.x;
    __shared__ int sa[LL];
    __shared__ int si[KK];
    for (int i = threadIdx.x; i < LL; i += blockDim.x) sa[i] = g_allowed[b * LL + i];
    for (int i = threadIdx.x; i < KK; i += blockDim.x) si[i] = g_isctx[b * KK + i];
    __syncthreads();
    if (threadIdx.x == 0) {
        int c = 0;
        for (int l = 0; l < LL; l++)
            if (sa[l]) g_kidx[b * LL + c++] = l;
        g_kcnt[b] = c;
    } else if (threadIdx.x == 32) {
        int c = 0;
        for (int k = 0; k < KK; k++)
            if (si[k]) g_qidx[b * KK + c++] = k;
        for (int k = 0; k < KK; k++)
            if (!si[k]) g_qidx[b * KK + c++] = k;
    }
}

// ---------------- packed fp32 tiled GEMM: C = A @ W^T + bias (+epilogue) ---
// EPI: 0 = bias only; 1 = bias + exact gelu; 2 = bias + residual add.
#define BM 64
#define BN 64
#define BKS 16

template <int EPI>
__global__ __launch_bounds__(256) void gemm_packed(
    const float* __restrict__ A, const float* __restrict__ W,
    const float* __restrict__ bias, const float* __restrict__ res,
    float* __restrict__ C, int M, int N, int Kd)
{
    __shared__ float As[BKS][BM + 4];
    __shared__ u64 Wd[BKS][BN + 2];   // duplicated (w,w) pairs

    int tid = threadIdx.x;
    int m0 = blockIdx.y * BM;
    int n0 = blockIdx.x * BN;
    int rowg = (tid >> 4) << 2;   // 0..60 (4 rows)
    int colg = (tid & 15) << 2;   // 0..60 (4 cols)
    int lrow = tid >> 2;          // 0..63
    int lk4  = tid & 3;           // 0..3

    const u64 z2 = pack2(0.f, 0.f);
    u64 acc[2][4];                 // [row-pair][col]
    #pragma unroll
    for (int p = 0; p < 2; p++)
        #pragma unroll
        for (int j = 0; j < 4; j++) acc[p][j] = z2;

    for (int k0 = 0; k0 < Kd; k0 += BKS) {
        {
            int gm = m0 + lrow;
            float4 av = make_float4(0.f, 0.f, 0.f, 0.f);
            if (gm < M) av = *(const float4*)(A + (size_t)gm * Kd + k0 + lk4 * 4);
            As[lk4 * 4 + 0][lrow] = av.x;
            As[lk4 * 4 + 1][lrow] = av.y;
            As[lk4 * 4 + 2][lrow] = av.z;
            As[lk4 * 4 + 3][lrow] = av.w;
        }
        {
            int gn = n0 + lrow;
            float4 wv = *(const float4*)(W + (size_t)gn * Kd + k0 + lk4 * 4);
            Wd[lk4 * 4 + 0][lrow] = pack2(wv.x, wv.x);
            Wd[lk4 * 4 + 1][lrow] = pack2(wv.y, wv.y);
            Wd[lk4 * 4 + 2][lrow] = pack2(wv.z, wv.z);
            Wd[lk4 * 4 + 3][lrow] = pack2(wv.w, wv.w);
        }
        __syncthreads();

        #pragma unroll
        for (int kk = 0; kk < BKS; kk++) {
            ulonglong2 av = *(const ulonglong2*)&As[kk][rowg];   // rows (rowg,+1),(+2,+3)
            ulonglong2 w01 = *(const ulonglong2*)&Wd[kk][colg];
            ulonglong2 w23 = *(const ulonglong2*)&Wd[kk][colg + 2];
            acc[0][0] = ffma2(av.x, w01.x, acc[0][0]);
            acc[0][1] = ffma2(av.x, w01.y, acc[0][1]);
            acc[0][2] = ffma2(av.x, w23.x, acc[0][2]);
            acc[0][3] = ffma2(av.x, w23.y, acc[0][3]);
            acc[1][0] = ffma2(av.y, w01.x, acc[1][0]);
            acc[1][1] = ffma2(av.y, w01.y, acc[1][1]);
            acc[1][2] = ffma2(av.y, w23.x, acc[1][2]);
            acc[1][3] = ffma2(av.y, w23.y, acc[1][3]);
        }
        __syncthreads();
    }

    #pragma unroll
    for (int p = 0; p < 2; p++) {
        int gm0 = m0 + rowg + 2 * p;
        #pragma unroll
        for (int j = 0; j < 4; j++) {
            int gn = n0 + colg + j;
            float bv = bias[gn];
            float2 f = unpack2(acc[p][j]);
            float v0 = f.x + bv, v1 = f.y + bv;
            if (EPI == 1) {
                v0 = 0.5f * v0 * (1.0f + erff(v0 * 0.70710678118654752f));
                v1 = 0.5f * v1 * (1.0f + erff(v1 * 0.70710678118654752f));
            }
            if (gm0 < M) {
                float o0 = v0;
                if (EPI == 2) o0 += res[(size_t)gm0 * N + gn];
                C[(size_t)gm0 * N + gn] = o0;
            }
            if (gm0 + 1 < M) {
                float o1 = v1;
                if (EPI == 2) o1 += res[(size_t)(gm0 + 1) * N + gn];
                C[(size_t)(gm0 + 1) * N + gn] = o1;
            }
        }
    }
}

// ---------------- DUAL fp32 GEMM (per-row weight select) for Wo ------------
__global__ __launch_bounds__(256) void gemm_dual(
    const float* __restrict__ A, const float* __restrict__ W0,
    const float* __restrict__ W1, const int* __restrict__ rowsel,
    const float* __restrict__ b0, const float* __restrict__ b1,
    float* __restrict__ C, int M, int N, int Kd)
{
    __shared__ float As[BKS][BM + 4];
    __shared__ float Ws[2][BKS][BN + 4];

    int tid = threadIdx.x;
    int m0 = blockIdx.y * BM;
    int n0 = blockIdx.x * BN;
    int rowg = (tid >> 4) << 2;
    int colg = (tid & 15) << 2;
    int lrow = tid >> 2;
    int lk4  = tid & 3;

    int seli[4];
    #pragma unroll
    for (int i = 0; i < 4; i++) {
        int gm = m0 + rowg + i;
        if (gm >= M) gm = M - 1;
        seli[i] = rowsel[gm] ? 0 : 1;
    }

    float acc[4][4] = {};

    for (int k0 = 0; k0 < Kd; k0 += BKS) {
        {
            int gm = m0 + lrow;
            float4 av = make_float4(0.f, 0.f, 0.f, 0.f);
            if (gm < M) av = *(const float4*)(A + (size_t)gm * Kd + k0 + lk4 * 4);
            As[lk4 * 4 + 0][lrow] = av.x;
            As[lk4 * 4 + 1][lrow] = av.y;
            As[lk4 * 4 + 2][lrow] = av.z;
            As[lk4 * 4 + 3][lrow] = av.w;
        }
        {
            int gn = n0 + lrow;
            float4 wv = *(const float4*)(W0 + (size_t)gn * Kd + k0 + lk4 * 4);
            Ws[0][lk4 * 4 + 0][lrow] = wv.x;
            Ws[0][lk4 * 4 + 1][lrow] = wv.y;
            Ws[0][lk4 * 4 + 2][lrow] = wv.z;
            Ws[0][lk4 * 4 + 3][lrow] = wv.w;
            float4 w2 = *(const float4*)(W1 + (size_t)gn * Kd + k0 + lk4 * 4);
            Ws[1][lk4 * 4 + 0][lrow] = w2.x;
            Ws[1][lk4 * 4 + 1][lrow] = w2.y;
            Ws[1][lk4 * 4 + 2][lrow] = w2.z;
            Ws[1][lk4 * 4 + 3][lrow] = w2.w;
        }
        __syncthreads();

        #pragma unroll
        for (int kk = 0; kk < BKS; kk++) {
            float a[4];
            #pragma unroll
            for (int i = 0; i < 4; i++) a[i] = As[kk][rowg + i];
            #pragma unroll
            for (int i = 0; i < 4; i++) {
                const float* wp = &Ws[seli[i]][kk][colg];
                #pragma unroll
                for (int j = 0; j < 4; j++)
                    acc[i][j] += a[i] * wp[j];
            }
        }
        __syncthreads();
    }

    #pragma unroll
    for (int i = 0; i < 4; i++) {
        int gm = m0 + rowg + i;
        if (gm >= M) continue;
        const float* bp = (seli[i] == 0) ? b0 : b1;
        #pragma unroll
        for (int j = 0; j < 4; j++) {
            int gn = n0 + colg + j;
            C[(size_t)gm * N + gn] = acc[i][j] + bp[gn];
        }
    }
}

// ---------------- attention: compacted keys, packed f32x2, sel-sorted ------
__global__ __launch_bounds__(128) void attn_kernel(
    const float* __restrict__ bqkv_c, const float* __restrict__ bqkv_t)
{
    int qc = blockIdx.x;     // 0..7 (128 queries each, sel-sorted order)
    int h  = blockIdx.y;
    int b  = blockIdx.z;
    int tid = threadIdx.x;

    int token = g_qidx[b * KK + qc * 128 + tid];
    int sel   = g_isctx[b * KK + token];               // 1 => ctx block
    int sel_first = g_isctx[b * KK + g_qidx[b * KK + qc * 128]];
    int sel_last  = g_isctx[b * KK + g_qidx[b * KK + qc * 128 + 127]];
    bool uni = (sel_first == sel_last);
    int bank = uni ? 0 : (sel ? 0 : 1);

    const float* qkv  = sel ? g_qkv_c : g_qkv_t;
    const float* bqkv = sel ? bqkv_c  : bqkv_t;

    const float scale = 0.1767766952966369f;           // 1/sqrt(32)
    u64 q2[16];
    {
        const float* qp = qkv + ((size_t)(b * LL + RR + token)) * (3 * DD) + h * HD;
        #pragma unroll
        for (int i = 0; i < 16; i++)
            q2[i] = pack2(qp[2 * i] * scale, qp[2 * i + 1] * scale);
    }

    const u64 z2 = pack2(0.f, 0.f);
    float m = -1e30f, ssum = 0.f;
    u64 acc2[16];
    #pragma unroll
    for (int i = 0; i < 16; i++) acc2[i] = z2;

    __shared__ u64 sK[2][32][16];
    __shared__ u64 sV[2][32][16];

    int cnt = g_kcnt[b];

    for (int t0 = 0; t0 < cnt; t0 += 32) {
        int cnt_tile = min(32, cnt - t0);
        __syncthreads();
        // staging: 256 (kk,i4) slots; thread covers idx = tid*2 + jj
        #pragma unroll
        for (int jj = 0; jj < 2; jj++) {
            int idx = tid * 2 + jj;
            int kk = idx >> 3, i4 = idx & 7;
            if (kk < cnt_tile) {
                int l = g_kidx[b * LL + t0 + kk];
                size_t base = ((size_t)(b * LL + l)) * (3 * DD) + h * HD + i4 * 4;
                if (uni) {
                    const float* src = sel_first ? g_qkv_c : g_qkv_t;
                    *(float4*)&sK[0][kk][i4 * 2] = *(const float4*)(src + base + DD);
                    *(float4*)&sV[0][kk][i4 * 2] = *(const float4*)(src + base + 2 * DD);
                } else {
                    *(float4*)&sK[0][kk][i4 * 2] = *(const float4*)(g_qkv_c + base + DD);
                    *(float4*)&sK[1][kk][i4 * 2] = *(const float4*)(g_qkv_t + base + DD);
                    *(float4*)&sV[0][kk][i4 * 2] = *(const float4*)(g_qkv_c + base + 2 * DD);
                    *(float4*)&sV[1][kk][i4 * 2] = *(const float4*)(g_qkv_t + base + 2 * DD);
                }
            }
        }
        __syncthreads();

        for (int kk = 0; kk < cnt_tile; kk++) {
            // score = q . k  (packed)
            u64 s2 = z2;
            #pragma unroll
            for (int i = 0; i < 8; i++) {
                ulonglong2 kv = *(const ulonglong2*)&sK[bank][kk][i * 2];
                s2 = ffma2(q2[2 * i], kv.x, s2);
                s2 = ffma2(q2[2 * i + 1], kv.y, s2);
            }
            float2 sf = unpack2(s2);
            float s = sf.x + sf.y;

            if (s <= m) {
                float p = __expf(s - m);
                ssum += p;
                u64 pp = pack2(p, p);
                #pragma unroll
                for (int i = 0; i < 8; i++) {
                    ulonglong2 vv = *(const ulonglong2*)&sV[bank][kk][i * 2];
                    acc2[2 * i]     = ffma2(pp, vv.x, acc2[2 * i]);
                    acc2[2 * i + 1] = ffma2(pp, vv.y, acc2[2 * i + 1]);
                }
            } else {
                float corr = __expf(m - s);
                ssum = ssum * corr + 1.f;
                u64 cc = pack2(corr, corr);
                #pragma unroll
                for (int i = 0; i < 8; i++) {
                    ulonglong2 vv = *(const ulonglong2*)&sV[bank][kk][i * 2];
                    acc2[2 * i]     = ffma2(cc, acc2[2 * i], vv.x);
                    acc2[2 * i + 1] = ffma2(cc, acc2[2 * i + 1], vv.y);
                }
                m = s;
            }
        }
    }

    // appended bias-only key (always allowed, last position): k = bk, v = bv
    {
        float s = 0.f;
        #pragma unroll
        for (int i = 0; i < 16; i++) {
            float2 qf = unpack2(q2[i]);
            s += qf.x * bqkv[DD + h * HD + 2 * i] + qf.y * bqkv[DD + h * HD + 2 * i + 1];
        }
        if (s <= m) {
            float p = __expf(s - m);
            ssum += p;
            #pragma unroll
            for (int i = 0; i < 16; i++) {
                float2 a = unpack2(acc2[i]);
                acc2[i] = pack2(a.x + p * bqkv[2 * DD + h * HD + 2 * i],
                                a.y + p * bqkv[2 * DD + h * HD + 2 * i + 1]);
            }
        } else {
            float corr = __expf(m - s);
            ssum = ssum * corr + 1.f;
            #pragma unroll
            for (int i = 0; i < 16; i++) {
                float2 a = unpack2(acc2[i]);
                acc2[i] = pack2(a.x * corr + bqkv[2 * DD + h * HD + 2 * i],
                                a.y * corr + bqkv[2 * DD + h * HD + 2 * i + 1]);
            }
            m = s;
        }
    }

    float inv = 1.f / ssum;
    float* op = g_attn + ((size_t)(b * KK + token)) * DD + h * HD;
    #pragma unroll
    for (int i = 0; i < 8; i++) {
        float2 a0 = unpack2(acc2[2 * i]);
        float2 a1 = unpack2(acc2[2 * i + 1]);
        float4 o = make_float4(a0.x * inv, a0.y * inv, a1.x * inv, a1.y * inv);
        *(float4*)(op + i * 4) = o;
    }
}

// ---------------- residual add + LN (for MLP input) ------------------------
__global__ __launch_bounds__(256) void resln_kernel(
    const float* __restrict__ gn, const float* __restrict__ bn)
{
    int mrow = blockIdx.x;           // 0..8191
    int d = threadIdx.x;
    int b = mrow >> 10, k = mrow & 1023;

    __shared__ float red[2][8];
    float v = g_xfull[((size_t)(b * LL + RR + k)) * DD + d] + g_tmp[(size_t)mrow * DD + d];
    g_x2[(size_t)mrow * DD + d] = v;

    float s1 = v, s2 = v * v;
    #pragma unroll
    for (int o = 16; o; o >>= 1) {
        s1 += __shfl_down_sync(0xffffffffu, s1, o);
        s2 += __shfl_down_sync(0xffffffffu, s2, o);
    }
    int wid = d >> 5, lane = d & 31;
    if (lane == 0) { red[0][wid] = s1; red[1][wid] = s2; }
    __syncthreads();
    if (d == 0) {
        float t1 = 0.f, t2 = 0.f;
        #pragma unroll
        for (int i = 0; i < 8; i++) { t1 += red[0][i]; t2 += red[1][i]; }
        red[0][0] = t1; red[1][0] = t2;
    }
    __syncthreads();
    float mean = red[0][0] * (1.f / DD);
    float var  = red[1][0] * (1.f / DD) - mean * mean;
    float rstd = rsqrtf(var + 1e-5f);
    g_x2n[(size_t)mrow * DD + d] = (v - mean) * rstd * gn[d] + bn[d];
}

// ---------------- launch ----------------------------------------------------
static void* sym(const void* s)
{
    void* p = nullptr;
    cudaGetSymbolAddress(&p, s);
    return p;
}

extern "C" void kernel_launch(void* const* d_in, const int* in_sizes, int n_in,
                              void* d_out, int out_size)
{
    const float* x          = (const float*)d_in[0];
    const int*   coords     = (const int*)d_in[1];
    const int*   ctxid      = (const int*)d_in[2];
    const float* tgt_e      = (const float*)d_in[3];
    const float* ctx_e      = (const float*)d_in[4];
    const float* regs       = (const float*)d_in[5];
    const float* rope       = (const float*)d_in[6];
    const float* norm_g     = (const float*)d_in[7];
    const float* norm_b     = (const float*)d_in[8];
    const float* ctx_Wqkv   = (const float*)d_in[9];
    const float* ctx_bqkv   = (const float*)d_in[10];
    const float* ctx_Wo     = (const float*)d_in[11];
    const float* ctx_bo     = (const float*)d_in[12];
    const float* tgt_Wqkv   = (const float*)d_in[13];
    const float* tgt_bqkv   = (const float*)d_in[14];
    const float* tgt_Wo     = (const float*)d_in[15];
    const float* tgt_bo     = (const float*)d_in[16];
    const float* mlpn_g     = (const float*)d_in[17];
    const float* mlpn_b     = (const float*)d_in[18];
    const float* mlp_W1     = (const float*)d_in[19];
    const float* mlp_b1     = (const float*)d_in[20];
    const float* mlp_W2     = (const float*)d_in[21];
    const float* mlp_b2     = (const float*)d_in[22];
    float* out = (float*)d_out;

    float* p_xn   = (float*)sym(g_xn);
    float* p_qc   = (float*)sym(g_qkv_c);
    float* p_qt   = (float*)sym(g_qkv_t);
    float* p_attn = (float*)sym(g_attn);
    float* p_tmp  = (float*)sym(g_tmp);
    float* p_x2   = (float*)sym(g_x2);
    float* p_x2n  = (float*)sym(g_x2n);
    float* p_h1   = (float*)sym(g_h1);
    int*   p_sel  = (int*)sym(g_isctx);

    // 1) embed + rope + LN
    prep_kernel<<<BB * LL, 256>>>(x, coords, ctxid, tgt_e, ctx_e, regs, rope,
                                  norm_g, norm_b);

    // 1b) compaction (allowed keys; ctx-first query order)
    compact_kernel<<<BB, 128>>>();

    // 2) QKV for both blocks (dense over all L rows)
    {
        dim3 g((3 * DD) / BN, (BB * LL + BM - 1) / BM);
        gemm_packed<0><<<g, 256>>>(p_xn, ctx_Wqkv, ctx_bqkv, nullptr, p_qc,
                                   BB * LL, 3 * DD, DD);
        gemm_packed<0><<<g, 256>>>(p_xn, tgt_Wqkv, tgt_bqkv, nullptr, p_qt,
                                   BB * LL, 3 * DD, DD);
    }

    // 3) attention (compacted keys, packed math, sel-sorted queries)
    {
        dim3 g(KK / 128, HH, BB);
        attn_kernel<<<g, 128>>>(ctx_bqkv, tgt_bqkv);
    }

    // 4) Wo with per-row weight selection
    {
        dim3 g(DD / BN, (BB * KK) / BM);
        gemm_dual<<<g, 256>>>(p_attn, ctx_Wo, tgt_Wo, p_sel,
                              ctx_bo, tgt_bo, p_tmp, BB * KK, DD, DD);
    }

    // 5) residual + LN
    resln_kernel<<<BB * KK, 256>>>(mlpn_g, mlpn_b);

    // 6) MLP up + gelu
    {
        dim3 g((4 * DD) / BN, (BB * KK) / BM);
        gemm_packed<1><<<g, 256>>>(p_x2n, mlp_W1, mlp_b1, nullptr, p_h1,
                                   BB * KK, 4 * DD, DD);
    }

    // 7) MLP down + residual -> output
    {
        dim3 g(DD / BN, (BB * KK) / BM);
        gemm_packed<2><<<g, 256>>>(p_h1, mlp_W2, mlp_b2, p_x2, out,
                                   BB * KK, DD, 4 * DD);
    }
}

// round 7
// speedup vs baseline: 1.4131x; 1.4131x over previous
#include <cuda_runtime.h>
#include <math.h>

// Problem constants
#define BB 8
#define KK 1024
#define DD 256
#define HH 8
#define RR 4
#define LL 1028      // RR + KK
#define HD 32
#define IMGF 224.0f
#define MAXPF 1023.0f

typedef unsigned long long u64;

// ---------------- packed f32x2 helpers -------------------------------------
__device__ __forceinline__ u64 ffma2(u64 a, u64 b, u64 c) {
    u64 d;
    asm("fma.rn.f32x2 %0, %1, %2, %3;" : "=l"(d) : "l"(a), "l"(b), "l"(c));
    return d;
}
__device__ __forceinline__ u64 pack2(float lo, float hi) {
    u64 r;
    asm("mov.b64 %0, {%1, %2};" : "=l"(r) : "f"(lo), "f"(hi));
    return r;
}
__device__ __forceinline__ float2 unpack2(u64 v) {
    float2 r;
    asm("mov.b64 {%0, %1}, %2;" : "=f"(r.x), "=f"(r.y) : "l"(v));
    return r;
}

// ---------------- scratch (device globals; no allocation allowed) ----------
__device__ float g_xfull[BB * LL * DD];        // post-embed, post-rope (pre-LN)
__device__ float g_xn[BB * LL * DD];           // LN(x)
__device__ int   g_allowed[BB * LL];           // key-allowed mask
__device__ int   g_isctx[BB * KK];             // per-token selector
__device__ int   g_kidx[BB * LL];              // compacted allowed-key list
__device__ int   g_kcnt[BB];                   // count per batch
__device__ int   g_qidx[BB * KK];              // queries sorted ctx-first
__device__ float g_qkv_c[BB * LL * 3 * DD];    // ctx block QKV
__device__ float g_qkv_t[BB * LL * 3 * DD];    // tgt block QKV
__device__ float g_attn[BB * KK * DD];         // selected attention out (pre-Wo)
__device__ float g_tmp[BB * KK * DD];          // attn @ Wo_sel + bo_sel
__device__ float g_x2[BB * KK * DD];           // x + attn_out (residual 1)
__device__ float g_x2n[BB * KK * DD];          // LN(x2)
__device__ float g_h1[BB * KK * 4 * DD];       // gelu(mlp1)

// ---------------- prep: embed add + rope2d + LN ---------------------------
__global__ __launch_bounds__(256) void prep_kernel(
    const float* __restrict__ x, const int* __restrict__ coords,
    const int* __restrict__ ctxid, const float* __restrict__ tgt_e,
    const float* __restrict__ ctx_e, const float* __restrict__ regs,
    const float* __restrict__ rope, const float* __restrict__ ng,
    const float* __restrict__ nb)
{
    int blk = blockIdx.x;
    int b = blk / LL;
    int l = blk - b * LL;
    int d = threadIdx.x;

    __shared__ float srow[DD];
    __shared__ float red[2][8];

    float v;
    int ic = 1;
    if (l < RR) {
        v = regs[l * DD + d] + ctx_e[d];
    } else {
        int k = l - RR;
        ic = ctxid[b * KK + k] > 0;
        v = x[((size_t)(b * KK + k)) * DD + d] + (ic ? ctx_e[d] : tgt_e[d]);
    }
    srow[d] = v;
    __syncthreads();

    float rv = v;
    if (l >= RR) {
        int k = l - RR;
        int cy = coords[(size_t)(b * KK + k) * 2 + 0];
        int cx = coords[(size_t)(b * KK + k) * 2 + 1];
        float cny = fminf(fmaxf(((float)cy / IMGF) * MAXPF, 0.f), MAXPF);
        float cnx = fminf(fmaxf(((float)cx / IMGF) * MAXPF, 0.f), MAXPF);
        int yi = (int)cny;
        int xi = (int)cnx;
        int j; const float* cp;
        if (d < 128) { j = d >> 1;         cp = rope + ((size_t)xi * 64 + j) * 2; }
        else         { j = (d - 128) >> 1; cp = rope + ((size_t)yi * 64 + j) * 2; }
        float c = cp[0], s = cp[1];
        float p0 = srow[d & ~1];
        float p1 = srow[d | 1];
        rv = (d & 1) ? (p0 * s + p1 * c) : (p0 * c - p1 * s);
    }

    g_xfull[((size_t)(b * LL + l)) * DD + d] = rv;
    if (d == 0) {
        g_allowed[b * LL + l] = (l < RR) ? 1 : ic;
        if (l >= RR) g_isctx[b * KK + (l - RR)] = ic;
    }

    // LayerNorm over 256
    float s1 = rv, s2 = rv * rv;
    #pragma unroll
    for (int o = 16; o; o >>= 1) {
        s1 += __shfl_down_sync(0xffffffffu, s1, o);
        s2 += __shfl_down_sync(0xffffffffu, s2, o);
    }
    int wid = d >> 5, lane = d & 31;
    if (lane == 0) { red[0][wid] = s1; red[1][wid] = s2; }
    __syncthreads();
    if (d == 0) {
        float t1 = 0.f, t2 = 0.f;
        #pragma unroll
        for (int i = 0; i < 8; i++) { t1 += red[0][i]; t2 += red[1][i]; }
        red[0][0] = t1; red[1][0] = t2;
    }
    __syncthreads();
    float mean = red[0][0] * (1.f / DD);
    float var  = red[1][0] * (1.f / DD) - mean * mean;
    float rstd = rsqrtf(var + 1e-5f);
    g_xn[((size_t)(b * LL + l)) * DD + d] = (rv - mean) * rstd * ng[d] + nb[d];
}

// ---------------- compaction: allowed-key list + ctx-first query order -----
__global__ __launch_bounds__(128) void compact_kernel()
{
    int b = blockIdx.x;
    __shared__ int sa[LL];
    __shared__ int si[KK];
    for (int i = threadIdx.x; i < LL; i += blockDim.x) sa[i] = g_allowed[b * LL + i];
    for (int i = threadIdx.x; i < KK; i += blockDim.x) si[i] = g_isctx[b * KK + i];
    __syncthreads();
    if (threadIdx.x == 0) {
        int c = 0;
        for (int l = 0; l < LL; l++)
            if (sa[l]) g_kidx[b * LL + c++] = l;
        g_kcnt[b] = c;
    } else if (threadIdx.x == 32) {
        int c = 0;
        for (int k = 0; k < KK; k++)
            if (si[k]) g_qidx[b * KK + c++] = k;
        for (int k = 0; k < KK; k++)
            if (!si[k]) g_qidx[b * KK + c++] = k;
    }
}

// ---------------- f32x2 tiled GEMM: C = A @ W^T + bias (+epilogue) ---------
// Accumulator u64 = adjacent output-column pair (no W duplication in SMEM).
// A operand replicated per-register via mov.b64 {a,a}.
// EPI: 0 = bias only; 1 = bias + exact gelu; 2 = bias + residual add.
#define GM 64
#define GN 128
#define GK 16

template <int EPI>
__global__ __launch_bounds__(256) void gemm_f2(
    const float* __restrict__ A, const float* __restrict__ W,
    const float* __restrict__ bias, const float* __restrict__ res,
    float* __restrict__ C, int M, int N, int Kd)
{
    __shared__ float As[GK][GM + 4];
    __shared__ float Ws[GK][GN + 8];

    int tid = threadIdx.x;
    int m0 = blockIdx.y * GM;
    int n0 = blockIdx.x * GN;
    int rowg = (tid >> 4) << 2;   // 0..60  (4 rows)
    int colg = (tid & 15) << 3;   // 0..120 (8 cols = 4 col-pairs)
    int lrow = tid >> 2;          // 0..63
    int lk4  = tid & 3;           // 0..3

    const u64 z2 = pack2(0.f, 0.f);
    u64 acc[4][4];                 // [row][col-pair]
    #pragma unroll
    for (int i = 0; i < 4; i++)
        #pragma unroll
        for (int j = 0; j < 4; j++) acc[i][j] = z2;

    for (int k0 = 0; k0 < Kd; k0 += GK) {
        // stage A: 64 rows x 16 k (one float4 per thread), transposed As[k][m]
        {
            int gm = m0 + lrow;
            float4 av = make_float4(0.f, 0.f, 0.f, 0.f);
            if (gm < M) av = *(const float4*)(A + (size_t)gm * Kd + k0 + lk4 * 4);
            As[lk4 * 4 + 0][lrow] = av.x;
            As[lk4 * 4 + 1][lrow] = av.y;
            As[lk4 * 4 + 2][lrow] = av.z;
            As[lk4 * 4 + 3][lrow] = av.w;
        }
        // stage W: 128 rows x 16 k (two float4 per thread), transposed Ws[k][n]
        #pragma unroll
        for (int r = 0; r < 2; r++) {
            int ln = lrow + 64 * r;
            int gn = n0 + ln;
            float4 wv = *(const float4*)(W + (size_t)gn * Kd + k0 + lk4 * 4);
            Ws[lk4 * 4 + 0][ln] = wv.x;
            Ws[lk4 * 4 + 1][ln] = wv.y;
            Ws[lk4 * 4 + 2][ln] = wv.z;
            Ws[lk4 * 4 + 3][ln] = wv.w;
        }
        __syncthreads();

        #pragma unroll
        for (int kk = 0; kk < GK; kk++) {
            float4 af = *(const float4*)&As[kk][rowg];
            u64 a2[4];
            a2[0] = pack2(af.x, af.x);
            a2[1] = pack2(af.y, af.y);
            a2[2] = pack2(af.z, af.z);
            a2[3] = pack2(af.w, af.w);
            // 8 consecutive cols as 4 u64 col-pairs (plain float SMEM, 2x16B)
            ulonglong2 w01 = *(const ulonglong2*)&Ws[kk][colg];
            ulonglong2 w23 = *(const ulonglong2*)&Ws[kk][colg + 4];
            #pragma unroll
            for (int i = 0; i < 4; i++) {
                acc[i][0] = ffma2(a2[i], w01.x, acc[i][0]);
                acc[i][1] = ffma2(a2[i], w01.y, acc[i][1]);
                acc[i][2] = ffma2(a2[i], w23.x, acc[i][2]);
                acc[i][3] = ffma2(a2[i], w23.y, acc[i][3]);
            }
        }
        __syncthreads();
    }

    // bias for the 8 columns this thread owns
    float bv[8];
    #pragma unroll
    for (int j = 0; j < 8; j++) bv[j] = bias[n0 + colg + j];

    #pragma unroll
    for (int i = 0; i < 4; i++) {
        int gm = m0 + rowg + i;
        if (gm >= M) continue;
        float o[8];
        #pragma unroll
        for (int j = 0; j < 4; j++) {
            float2 f = unpack2(acc[i][j]);
            o[2 * j]     = f.x + bv[2 * j];
            o[2 * j + 1] = f.y + bv[2 * j + 1];
        }
        if (EPI == 1) {
            #pragma unroll
            for (int j = 0; j < 8; j++)
                o[j] = 0.5f * o[j] * (1.0f + erff(o[j] * 0.70710678118654752f));
        }
        if (EPI == 2) {
            const float* rp = res + (size_t)gm * N + n0 + colg;
            float4 r0 = *(const float4*)(rp);
            float4 r1 = *(const float4*)(rp + 4);
            o[0] += r0.x; o[1] += r0.y; o[2] += r0.z; o[3] += r0.w;
            o[4] += r1.x; o[5] += r1.y; o[6] += r1.z; o[7] += r1.w;
        }
        float* cp = C + (size_t)gm * N + n0 + colg;
        *(float4*)(cp)     = make_float4(o[0], o[1], o[2], o[3]);
        *(float4*)(cp + 4) = make_float4(o[4], o[5], o[6], o[7]);
    }
}

// ---------------- DUAL fp32 GEMM (per-row weight select) for Wo ------------
#define BM 64
#define BN 64
#define BKS 16

__global__ __launch_bounds__(256) void gemm_dual(
    const float* __restrict__ A, const float* __restrict__ W0,
    const float* __restrict__ W1, const int* __restrict__ rowsel,
    const float* __restrict__ b0, const float* __restrict__ b1,
    float* __restrict__ C, int M, int N, int Kd)
{
    __shared__ float As[BKS][BM + 4];
    __shared__ float Ws[2][BKS][BN + 4];

    int tid = threadIdx.x;
    int m0 = blockIdx.y * BM;
    int n0 = blockIdx.x * BN;
    int rowg = (tid >> 4) << 2;
    int colg = (tid & 15) << 2;
    int lrow = tid >> 2;
    int lk4  = tid & 3;

    int seli[4];
    #pragma unroll
    for (int i = 0; i < 4; i++) {
        int gm = m0 + rowg + i;
        if (gm >= M) gm = M - 1;
        seli[i] = rowsel[gm] ? 0 : 1;
    }

    float acc[4][4] = {};

    for (int k0 = 0; k0 < Kd; k0 += BKS) {
        {
            int gm = m0 + lrow;
            float4 av = make_float4(0.f, 0.f, 0.f, 0.f);
            if (gm < M) av = *(const float4*)(A + (size_t)gm * Kd + k0 + lk4 * 4);
            As[lk4 * 4 + 0][lrow] = av.x;
            As[lk4 * 4 + 1][lrow] = av.y;
            As[lk4 * 4 + 2][lrow] = av.z;
            As[lk4 * 4 + 3][lrow] = av.w;
        }
        {
            int gn = n0 + lrow;
            float4 wv = *(const float4*)(W0 + (size_t)gn * Kd + k0 + lk4 * 4);
            Ws[0][lk4 * 4 + 0][lrow] = wv.x;
            Ws[0][lk4 * 4 + 1][lrow] = wv.y;
            Ws[0][lk4 * 4 + 2][lrow] = wv.z;
            Ws[0][lk4 * 4 + 3][lrow] = wv.w;
            float4 w2 = *(const float4*)(W1 + (size_t)gn * Kd + k0 + lk4 * 4);
            Ws[1][lk4 * 4 + 0][lrow] = w2.x;
            Ws[1][lk4 * 4 + 1][lrow] = w2.y;
            Ws[1][lk4 * 4 + 2][lrow] = w2.z;
            Ws[1][lk4 * 4 + 3][lrow] = w2.w;
        }
        __syncthreads();

        #pragma unroll
        for (int kk = 0; kk < BKS; kk++) {
            float a[4];
            #pragma unroll
            for (int i = 0; i < 4; i++) a[i] = As[kk][rowg + i];
            #pragma unroll
            for (int i = 0; i < 4; i++) {
                const float* wp = &Ws[seli[i]][kk][colg];
                #pragma unroll
                for (int j = 0; j < 4; j++)
                    acc[i][j] += a[i] * wp[j];
            }
        }
        __syncthreads();
    }

    #pragma unroll
    for (int i = 0; i < 4; i++) {
        int gm = m0 + rowg + i;
        if (gm >= M) continue;
        const float* bp = (seli[i] == 0) ? b0 : b1;
        #pragma unroll
        for (int j = 0; j < 4; j++) {
            int gn = n0 + colg + j;
            C[(size_t)gm * N + gn] = acc[i][j] + bp[gn];
        }
    }
}

// ---------------- attention: compacted keys, packed f32x2, sel-sorted ------
__global__ __launch_bounds__(128) void attn_kernel(
    const float* __restrict__ bqkv_c, const float* __restrict__ bqkv_t)
{
    int qc = blockIdx.x;     // 0..7 (128 queries each, sel-sorted order)
    int h  = blockIdx.y;
    int b  = blockIdx.z;
    int tid = threadIdx.x;

    int token = g_qidx[b * KK + qc * 128 + tid];
    int sel   = g_isctx[b * KK + token];               // 1 => ctx block
    int sel_first = g_isctx[b * KK + g_qidx[b * KK + qc * 128]];
    int sel_last  = g_isctx[b * KK + g_qidx[b * KK + qc * 128 + 127]];
    bool uni = (sel_first == sel_last);
    int bank = uni ? 0 : (sel ? 0 : 1);

    const float* qkv  = sel ? g_qkv_c : g_qkv_t;
    const float* bqkv = sel ? bqkv_c  : bqkv_t;

    const float scale = 0.1767766952966369f;           // 1/sqrt(32)
    u64 q2[16];
    {
        const float* qp = qkv + ((size_t)(b * LL + RR + token)) * (3 * DD) + h * HD;
        #pragma unroll
        for (int i = 0; i < 16; i++)
            q2[i] = pack2(qp[2 * i] * scale, qp[2 * i + 1] * scale);
    }

    const u64 z2 = pack2(0.f, 0.f);
    float m = -1e30f, ssum = 0.f;
    u64 acc2[16];
    #pragma unroll
    for (int i = 0; i < 16; i++) acc2[i] = z2;

    __shared__ u64 sK[2][32][16];
    __shared__ u64 sV[2][32][16];

    int cnt = g_kcnt[b];

    for (int t0 = 0; t0 < cnt; t0 += 32) {
        int cnt_tile = min(32, cnt - t0);
        __syncthreads();
        #pragma unroll
        for (int jj = 0; jj < 2; jj++) {
            int idx = tid * 2 + jj;
            int kk = idx >> 3, i4 = idx & 7;
            if (kk < cnt_tile) {
                int l = g_kidx[b * LL + t0 + kk];
                size_t base = ((size_t)(b * LL + l)) * (3 * DD) + h * HD + i4 * 4;
                if (uni) {
                    const float* src = sel_first ? g_qkv_c : g_qkv_t;
                    *(float4*)&sK[0][kk][i4 * 2] = *(const float4*)(src + base + DD);
                    *(float4*)&sV[0][kk][i4 * 2] = *(const float4*)(src + base + 2 * DD);
                } else {
                    *(float4*)&sK[0][kk][i4 * 2] = *(const float4*)(g_qkv_c + base + DD);
                    *(float4*)&sK[1][kk][i4 * 2] = *(const float4*)(g_qkv_t + base + DD);
                    *(float4*)&sV[0][kk][i4 * 2] = *(const float4*)(g_qkv_c + base + 2 * DD);
                    *(float4*)&sV[1][kk][i4 * 2] = *(const float4*)(g_qkv_t + base + 2 * DD);
                }
            }
        }
        __syncthreads();

        for (int kk = 0; kk < cnt_tile; kk++) {
            u64 s2 = z2;
            #pragma unroll
            for (int i = 0; i < 8; i++) {
                ulonglong2 kv = *(const ulonglong2*)&sK[bank][kk][i * 2];
                s2 = ffma2(q2[2 * i], kv.x, s2);
                s2 = ffma2(q2[2 * i + 1], kv.y, s2);
            }
            float2 sf = unpack2(s2);
            float s = sf.x + sf.y;

            if (s <= m) {
                float p = __expf(s - m);
                ssum += p;
                u64 pp = pack2(p, p);
                #pragma unroll
                for (int i = 0; i < 8; i++) {
                    ulonglong2 vv = *(const ulonglong2*)&sV[bank][kk][i * 2];
                    acc2[2 * i]     = ffma2(pp, vv.x, acc2[2 * i]);
                    acc2[2 * i + 1] = ffma2(pp, vv.y, acc2[2 * i + 1]);
                }
            } else {
                float corr = __expf(m - s);
                ssum = ssum * corr + 1.f;
                u64 cc = pack2(corr, corr);
                #pragma unroll
                for (int i = 0; i < 8; i++) {
                    ulonglong2 vv = *(const ulonglong2*)&sV[bank][kk][i * 2];
                    acc2[2 * i]     = ffma2(cc, acc2[2 * i], vv.x);
                    acc2[2 * i + 1] = ffma2(cc, acc2[2 * i + 1], vv.y);
                }
                m = s;
            }
        }
    }

    // appended bias-only key (always allowed, last position): k = bk, v = bv
    {
        float s = 0.f;
        #pragma unroll
        for (int i = 0; i < 16; i++) {
            float2 qf = unpack2(q2[i]);
            s += qf.x * bqkv[DD + h * HD + 2 * i] + qf.y * bqkv[DD + h * HD + 2 * i + 1];
        }
        if (s <= m) {
            float p = __expf(s - m);
            ssum += p;
            #pragma unroll
            for (int i = 0; i < 16; i++) {
                float2 a = unpack2(acc2[i]);
                acc2[i] = pack2(a.x + p * bqkv[2 * DD + h * HD + 2 * i],
                                a.y + p * bqkv[2 * DD + h * HD + 2 * i + 1]);
            }
        } else {
            float corr = __expf(m - s);
            ssum = ssum * corr + 1.f;
            #pragma unroll
            for (int i = 0; i < 16; i++) {
                float2 a = unpack2(acc2[i]);
                acc2[i] = pack2(a.x * corr + bqkv[2 * DD + h * HD + 2 * i],
                                a.y * corr + bqkv[2 * DD + h * HD + 2 * i + 1]);
            }
            m = s;
        }
    }

    float inv = 1.f / ssum;
    float* op = g_attn + ((size_t)(b * KK + token)) * DD + h * HD;
    #pragma unroll
    for (int i = 0; i < 8; i++) {
        float2 a0 = unpack2(acc2[2 * i]);
        float2 a1 = unpack2(acc2[2 * i + 1]);
        float4 o = make_float4(a0.x * inv, a0.y * inv, a1.x * inv, a1.y * inv);
        *(float4*)(op + i * 4) = o;
    }
}

// ---------------- residual add + LN (for MLP input) ------------------------
__global__ __launch_bounds__(256) void resln_kernel(
    const float* __restrict__ gn, const float* __restrict__ bn)
{
    int mrow = blockIdx.x;           // 0..8191
    int d = threadIdx.x;
    int b = mrow >> 10, k = mrow & 1023;

    __shared__ float red[2][8];
    float v = g_xfull[((size_t)(b * LL + RR + k)) * DD + d] + g_tmp[(size_t)mrow * DD + d];
    g_x2[(size_t)mrow * DD + d] = v;

    float s1 = v, s2 = v * v;
    #pragma unroll
    for (int o = 16; o; o >>= 1) {
        s1 += __shfl_down_sync(0xffffffffu, s1, o);
        s2 += __shfl_down_sync(0xffffffffu, s2, o);
    }
    int wid = d >> 5, lane = d & 31;
    if (lane == 0) { red[0][wid] = s1; red[1][wid] = s2; }
    __syncthreads();
    if (d == 0) {
        float t1 = 0.f, t2 = 0.f;
        #pragma unroll
        for (int i = 0; i < 8; i++) { t1 += red[0][i]; t2 += red[1][i]; }
        red[0][0] = t1; red[1][0] = t2;
    }
    __syncthreads();
    float mean = red[0][0] * (1.f / DD);
    float var  = red[1][0] * (1.f / DD) - mean * mean;
    float rstd = rsqrtf(var + 1e-5f);
    g_x2n[(size_t)mrow * DD + d] = (v - mean) * rstd * gn[d] + bn[d];
}

// ---------------- launch ----------------------------------------------------
static void* sym(const void* s)
{
    void* p = nullptr;
    cudaGetSymbolAddress(&p, s);
    return p;
}

extern "C" void kernel_launch(void* const* d_in, const int* in_sizes, int n_in,
                              void* d_out, int out_size)
{
    const float* x          = (const float*)d_in[0];
    const int*   coords     = (const int*)d_in[1];
    const int*   ctxid      = (const int*)d_in[2];
    const float* tgt_e      = (const float*)d_in[3];
    const float* ctx_e      = (const float*)d_in[4];
    const float* regs       = (const float*)d_in[5];
    const float* rope       = (const float*)d_in[6];
    const float* norm_g     = (const float*)d_in[7];
    const float* norm_b     = (const float*)d_in[8];
    const float* ctx_Wqkv   = (const float*)d_in[9];
    const float* ctx_bqkv   = (const float*)d_in[10];
    const float* ctx_Wo     = (const float*)d_in[11];
    const float* ctx_bo     = (const float*)d_in[12];
    const float* tgt_Wqkv   = (const float*)d_in[13];
    const float* tgt_bqkv   = (const float*)d_in[14];
    const float* tgt_Wo     = (const float*)d_in[15];
    const float* tgt_bo     = (const float*)d_in[16];
    const float* mlpn_g     = (const float*)d_in[17];
    const float* mlpn_b     = (const float*)d_in[18];
    const float* mlp_W1     = (const float*)d_in[19];
    const float* mlp_b1     = (const float*)d_in[20];
    const float* mlp_W2     = (const float*)d_in[21];
    const float* mlp_b2     = (const float*)d_in[22];
    float* out = (float*)d_out;

    float* p_xn   = (float*)sym(g_xn);
    float* p_qc   = (float*)sym(g_qkv_c);
    float* p_qt   = (float*)sym(g_qkv_t);
    float* p_attn = (float*)sym(g_attn);
    float* p_tmp  = (float*)sym(g_tmp);
    float* p_x2   = (float*)sym(g_x2);
    float* p_x2n  = (float*)sym(g_x2n);
    float* p_h1   = (float*)sym(g_h1);
    int*   p_sel  = (int*)sym(g_isctx);

    // 1) embed + rope + LN
    prep_kernel<<<BB * LL, 256>>>(x, coords, ctxid, tgt_e, ctx_e, regs, rope,
                                  norm_g, norm_b);

    // 1b) compaction (allowed keys; ctx-first query order)
    compact_kernel<<<BB, 128>>>();

    // 2) QKV for both blocks (dense over all L rows)
    {
        dim3 g((3 * DD) / GN, (BB * LL + GM - 1) / GM);
        gemm_f2<0><<<g, 256>>>(p_xn, ctx_Wqkv, ctx_bqkv, nullptr, p_qc,
                               BB * LL, 3 * DD, DD);
        gemm_f2<0><<<g, 256>>>(p_xn, tgt_Wqkv, tgt_bqkv, nullptr, p_qt,
                               BB * LL, 3 * DD, DD);
    }

    // 3) attention (compacted keys, packed math, sel-sorted queries)
    {
        dim3 g(KK / 128, HH, BB);
        attn_kernel<<<g, 128>>>(ctx_bqkv, tgt_bqkv);
    }

    // 4) Wo with per-row weight selection
    {
        dim3 g(DD / BN, (BB * KK) / BM);
        gemm_dual<<<g, 256>>>(p_attn, ctx_Wo, tgt_Wo, p_sel,
                              ctx_bo, tgt_bo, p_tmp, BB * KK, DD, DD);
    }

    // 5) residual + LN
    resln_kernel<<<BB * KK, 256>>>(mlpn_g, mlpn_b);

    // 6) MLP up + gelu
    {
        dim3 g((4 * DD) / GN, (BB * KK) / GM);
        gemm_f2<1><<<g, 256>>>(p_x2n, mlp_W1, mlp_b1, nullptr, p_h1,
                               BB * KK, 4 * DD, DD);
    }

    // 7) MLP down + residual -> output
    {
        dim3 g(DD / GN, (BB * KK) / GM);
        gemm_f2<2><<<g, 256>>>(p_h1, mlp_W2, mlp_b2, p_x2, out,
                               BB * KK, DD, 4 * DD);
    }
}

// round 10
// speedup vs baseline: 2.3311x; 1.6497x over previous
#include <cuda_runtime.h>
#include <cuda_bf16.h>
#include <math.h>

// Problem constants
#define BB 8
#define KK 1024
#define DD 256
#define HH 8
#define RR 4
#define LL 1028      // RR + KK
#define HD 32
#define IMGF 224.0f
#define MAXPF 1023.0f

typedef unsigned long long u64;
typedef __nv_bfloat16 bf16;

// ---------------- packed f32x2 helpers (attention) --------------------------
__device__ __forceinline__ u64 ffma2(u64 a, u64 b, u64 c) {
    u64 d;
    asm("fma.rn.f32x2 %0, %1, %2, %3;" : "=l"(d) : "l"(a), "l"(b), "l"(c));
    return d;
}
__device__ __forceinline__ u64 pack2(float lo, float hi) {
    u64 r;
    asm("mov.b64 %0, {%1, %2};" : "=l"(r) : "f"(lo), "f"(hi));
    return r;
}
__device__ __forceinline__ float2 unpack2(u64 v) {
    float2 r;
    asm("mov.b64 {%0, %1}, %2;" : "=f"(r.x), "=f"(r.y) : "l"(v));
    return r;
}

// ---------------- mma.sync helpers (base PTX, compute_103-safe) -------------
__device__ __forceinline__ unsigned smem_u32(const void* p) {
    unsigned a;
    asm("{ .reg .u64 t; cvta.to.shared.u64 t, %1; cvt.u32.u64 %0, t; }"
        : "=r"(a) : "l"(p));
    return a;
}
__device__ __forceinline__ void ldsm4(unsigned* r, unsigned addr) {
    asm volatile("ldmatrix.sync.aligned.m8n8.x4.shared.b16 {%0,%1,%2,%3}, [%4];"
                 : "=r"(r[0]), "=r"(r[1]), "=r"(r[2]), "=r"(r[3]) : "r"(addr));
}
__device__ __forceinline__ void mma16816(float* c, const unsigned* a,
                                         unsigned b0, unsigned b1) {
    asm volatile(
        "mma.sync.aligned.m16n8k16.row.col.f32.bf16.bf16.f32 "
        "{%0,%1,%2,%3}, {%4,%5,%6,%7}, {%8,%9}, {%0,%1,%2,%3};"
        : "+f"(c[0]), "+f"(c[1]), "+f"(c[2]), "+f"(c[3])
        : "r"(a[0]), "r"(a[1]), "r"(a[2]), "r"(a[3]), "r"(b0), "r"(b1));
}

// ---------------- scratch (device globals; no allocation allowed) ----------
__device__ float g_xfull[BB * LL * DD];
__device__ int   g_allowed[BB * LL];
__device__ int   g_isctx[BB * KK];
__device__ int   g_kidx[BB * LL];
__device__ int   g_kcnt[BB];
__device__ int   g_qidx[BB * KK];
__device__ float g_qkv_c[BB * LL * 3 * DD];
__device__ float g_qkv_t[BB * LL * 3 * DD];
__device__ float g_tmp2[BB * KK * 2 * DD];     // attn @ [Wo_c; Wo_t]
__device__ float g_x2[BB * KK * DD];
__device__ float g_zerob[2 * DD];              // zero bias (never written)

// bf16 hi/lo activation buffers
__device__ bf16 g_xn_h[BB * LL * DD],   g_xn_l[BB * LL * DD];
__device__ bf16 g_at_h[BB * KK * DD],   g_at_l[BB * KK * DD];
__device__ bf16 g_x2n_h[BB * KK * DD],  g_x2n_l[BB * KK * DD];
__device__ bf16 g_h1_h[BB * KK * 4 * DD], g_h1_l[BB * KK * 4 * DD];

// bf16 hi/lo weight buffers
__device__ bf16 g_wqc_h[3 * DD * DD], g_wqc_l[3 * DD * DD];
__device__ bf16 g_wqt_h[3 * DD * DD], g_wqt_l[3 * DD * DD];
__device__ bf16 g_wo_h[2 * DD * DD],  g_wo_l[2 * DD * DD];
__device__ bf16 g_w1_h[4 * DD * DD],  g_w1_l[4 * DD * DD];
__device__ bf16 g_w2_h[4 * DD * DD],  g_w2_l[4 * DD * DD];

__device__ __forceinline__ void split_bf16(float v, bf16* hp, bf16* lp) {
    bf16 h = __float2bfloat16(v);
    *hp = h;
    *lp = __float2bfloat16(v - __bfloat162float(h));
}

// ---------------- weight conversion -----------------------------------------
__global__ __launch_bounds__(256) void convw_kernel(
    const float* __restrict__ src, bf16* __restrict__ hi, bf16* __restrict__ lo,
    int n)
{
    int i = blockIdx.x * 256 + threadIdx.x;
    if (i < n) split_bf16(src[i], hi + i, lo + i);
}

// ---------------- prep: embed add + rope2d + LN (-> bf16 hi/lo) ------------
__global__ __launch_bounds__(256) void prep_kernel(
    const float* __restrict__ x, const int* __restrict__ coords,
    const int* __restrict__ ctxid, const float* __restrict__ tgt_e,
    const float* __restrict__ ctx_e, const float* __restrict__ regs,
    const float* __restrict__ rope, const float* __restrict__ ng,
    const float* __restrict__ nb)
{
    int blk = blockIdx.x;
    int b = blk / LL;
    int l = blk - b * LL;
    int d = threadIdx.x;

    __shared__ float srow[DD];
    __shared__ float red[2][8];

    float v;
    int ic = 1;
    if (l < RR) {
        v = regs[l * DD + d] + ctx_e[d];
    } else {
        int k = l - RR;
        ic = ctxid[b * KK + k] > 0;
        v = x[((size_t)(b * KK + k)) * DD + d] + (ic ? ctx_e[d] : tgt_e[d]);
    }
    srow[d] = v;
    __syncthreads();

    float rv = v;
    if (l >= RR) {
        int k = l - RR;
        int cy = coords[(size_t)(b * KK + k) * 2 + 0];
        int cx = coords[(size_t)(b * KK + k) * 2 + 1];
        float cny = fminf(fmaxf(((float)cy / IMGF) * MAXPF, 0.f), MAXPF);
        float cnx = fminf(fmaxf(((float)cx / IMGF) * MAXPF, 0.f), MAXPF);
        int yi = (int)cny;
        int xi = (int)cnx;
        int j; const float* cp;
        if (d < 128) { j = d >> 1;         cp = rope + ((size_t)xi * 64 + j) * 2; }
        else         { j = (d - 128) >> 1; cp = rope + ((size_t)yi * 64 + j) * 2; }
        float c = cp[0], s = cp[1];
        float p0 = srow[d & ~1];
        float p1 = srow[d | 1];
        rv = (d & 1) ? (p0 * s + p1 * c) : (p0 * c - p1 * s);
    }

    size_t gi = ((size_t)(b * LL + l)) * DD + d;
    g_xfull[gi] = rv;
    if (d == 0) {
        g_allowed[b * LL + l] = (l < RR) ? 1 : ic;
        if (l >= RR) g_isctx[b * KK + (l - RR)] = ic;
    }

    float s1 = rv, s2 = rv * rv;
    #pragma unroll
    for (int o = 16; o; o >>= 1) {
        s1 += __shfl_down_sync(0xffffffffu, s1, o);
        s2 += __shfl_down_sync(0xffffffffu, s2, o);
    }
    int wid = d >> 5, lane = d & 31;
    if (lane == 0) { red[0][wid] = s1; red[1][wid] = s2; }
    __syncthreads();
    if (d == 0) {
        float t1 = 0.f, t2 = 0.f;
        #pragma unroll
        for (int i = 0; i < 8; i++) { t1 += red[0][i]; t2 += red[1][i]; }
        red[0][0] = t1; red[1][0] = t2;
    }
    __syncthreads();
    float mean = red[0][0] * (1.f / DD);
    float var  = red[1][0] * (1.f / DD) - mean * mean;
    float rstd = rsqrtf(var + 1e-5f);
    float xnv = (rv - mean) * rstd * ng[d] + nb[d];
    split_bf16(xnv, g_xn_h + gi, g_xn_l + gi);
}

// ---------------- compaction -------------------------------------------------
__global__ __launch_bounds__(128) void compact_kernel()
{
    int b = blockIdx.x;
    __shared__ int sa[LL];
    __shared__ int si[KK];
    for (int i = threadIdx.x; i < LL; i += blockDim.x) sa[i] = g_allowed[b * LL + i];
    for (int i = threadIdx.x; i < KK; i += blockDim.x) si[i] = g_isctx[b * KK + i];
    __syncthreads();
    if (threadIdx.x == 0) {
        int c = 0;
        for (int l = 0; l < LL; l++)
            if (sa[l]) g_kidx[b * LL + c++] = l;
        g_kcnt[b] = c;
    } else if (threadIdx.x == 32) {
        int c = 0;
        for (int k = 0; k < KK; k++)
            if (si[k]) g_qidx[b * KK + c++] = k;
        for (int k = 0; k < KK; k++)
            if (!si[k]) g_qidx[b * KK + c++] = k;
    }
}

// ---------------- mma.sync bf16-split GEMM -----------------------------------
// D[M,N] = A @ W^T via 3 bf16 phases (hi*hi + lo*hi + hi*lo), fp32 reg accum.
// CTA tile 128x128, 8 warps (4x2), warp tile 32x64, K-chunk 32.
// EPI 0: C = D + bias; EPI 1: Chi/Clo = split(gelu(D+bias)); EPI 2: C = D+bias+res.
#define SSTR 40   // smem row stride in bf16 (80B, conflict-free ldmatrix)

template <int EPI>
__global__ __launch_bounds__(256) void mma_gemm(
    const bf16* __restrict__ Ahi, const bf16* __restrict__ Alo,
    const bf16* __restrict__ Whi, const bf16* __restrict__ Wlo,
    const float* __restrict__ bias, const float* __restrict__ res,
    float* __restrict__ C, bf16* __restrict__ Chi, bf16* __restrict__ Clo,
    int M, int N, int Kd)
{
    __shared__ bf16 sAh[128][SSTR];
    __shared__ bf16 sAl[128][SSTR];
    __shared__ bf16 sWh[128][SSTR];
    __shared__ bf16 sWl[128][SSTR];

    int tid = threadIdx.x;
    int wid = tid >> 5, lane = tid & 31;
    int m0 = blockIdx.y * 128;
    int n0 = blockIdx.x * 128;
    int wm = wid >> 1;           // 0..3 -> m offset wm*32
    int wn = wid & 1;            // 0..1 -> n offset wn*64

    float acc[2][8][4];
    #pragma unroll
    for (int t = 0; t < 2; t++)
        #pragma unroll
        for (int j = 0; j < 8; j++)
            #pragma unroll
            for (int q = 0; q < 4; q++) acc[t][j][q] = 0.f;

    // staging coords: thread -> row tid>>1, 16-elem half (tid&1)
    int srow = tid >> 1;
    int scol = (tid & 1) * 16;
    int agm = m0 + srow;
    bool aok = (agm < M);

    // per-lane ldmatrix row/col adjustment
    int lrow = lane & 15;
    int lcol8 = (lane >> 4) * 8;

    for (int k0 = 0; k0 < Kd; k0 += 32) {
        // ---- stage 4 matrices ----
        {
            const uint4* pa_h = (const uint4*)(Ahi + (size_t)agm * Kd + k0 + scol);
            const uint4* pa_l = (const uint4*)(Alo + (size_t)agm * Kd + k0 + scol);
            uint4 z = make_uint4(0u, 0u, 0u, 0u);
            uint4 vh0 = aok ? pa_h[0] : z;
            uint4 vh1 = aok ? pa_h[1] : z;
            uint4 vl0 = aok ? pa_l[0] : z;
            uint4 vl1 = aok ? pa_l[1] : z;
            *(uint4*)&sAh[srow][scol]     = vh0;
            *(uint4*)&sAh[srow][scol + 8] = vh1;
            *(uint4*)&sAl[srow][scol]     = vl0;
            *(uint4*)&sAl[srow][scol + 8] = vl1;

            const uint4* pw_h = (const uint4*)(Whi + (size_t)(n0 + srow) * Kd + k0 + scol);
            const uint4* pw_l = (const uint4*)(Wlo + (size_t)(n0 + srow) * Kd + k0 + scol);
            uint4 wh0 = pw_h[0], wh1 = pw_h[1];
            uint4 wl0 = pw_l[0], wl1 = pw_l[1];
            *(uint4*)&sWh[srow][scol]     = wh0;
            *(uint4*)&sWh[srow][scol + 8] = wh1;
            *(uint4*)&sWl[srow][scol]     = wl0;
            *(uint4*)&sWl[srow][scol + 8] = wl1;
        }
        __syncthreads();

        #pragma unroll
        for (int ks = 0; ks < 2; ks++) {
            int ko = ks * 16 + lcol8;
            unsigned ah[2][4], al[2][4], w[4][4];
            #pragma unroll
            for (int t = 0; t < 2; t++) {
                ldsm4(ah[t], smem_u32(&sAh[wm * 32 + t * 16 + lrow][ko]));
                ldsm4(al[t], smem_u32(&sAl[wm * 32 + t * 16 + lrow][ko]));
            }
            #pragma unroll
            for (int g = 0; g < 4; g++)
                ldsm4(w[g], smem_u32(&sWh[wn * 64 + g * 16 + lrow][ko]));
            // hi*hi + lo*hi
            #pragma unroll
            for (int t = 0; t < 2; t++)
                #pragma unroll
                for (int g = 0; g < 4; g++) {
                    mma16816(acc[t][g * 2],     ah[t], w[g][0], w[g][2]);
                    mma16816(acc[t][g * 2 + 1], ah[t], w[g][1], w[g][3]);
                    mma16816(acc[t][g * 2],     al[t], w[g][0], w[g][2]);
                    mma16816(acc[t][g * 2 + 1], al[t], w[g][1], w[g][3]);
                }
            // hi*lo
            #pragma unroll
            for (int g = 0; g < 4; g++)
                ldsm4(w[g], smem_u32(&sWl[wn * 64 + g * 16 + lrow][ko]));
            #pragma unroll
            for (int t = 0; t < 2; t++)
                #pragma unroll
                for (int g = 0; g < 4; g++) {
                    mma16816(acc[t][g * 2],     ah[t], w[g][0], w[g][2]);
                    mma16816(acc[t][g * 2 + 1], ah[t], w[g][1], w[g][3]);
                }
        }
        __syncthreads();
    }

    // ---- epilogue from c-fragments ----
    int lr = lane >> 2;
    int lc = (lane & 3) * 2;
    #pragma unroll
    for (int t = 0; t < 2; t++) {
        int r0 = m0 + wm * 32 + t * 16 + lr;
        int r1 = r0 + 8;
        #pragma unroll
        for (int j = 0; j < 8; j++) {
            int gn = n0 + wn * 64 + j * 8 + lc;
            float b0 = bias[gn], b1 = bias[gn + 1];
            float v00 = acc[t][j][0] + b0, v01 = acc[t][j][1] + b1;
            float v10 = acc[t][j][2] + b0, v11 = acc[t][j][3] + b1;
            if (EPI == 1) {
                v00 = 0.5f * v00 * (1.0f + erff(v00 * 0.70710678118654752f));
                v01 = 0.5f * v01 * (1.0f + erff(v01 * 0.70710678118654752f));
                v10 = 0.5f * v10 * (1.0f + erff(v10 * 0.70710678118654752f));
                v11 = 0.5f * v11 * (1.0f + erff(v11 * 0.70710678118654752f));
            }
            if (EPI == 1) {
                if (r0 < M) {
                    size_t i0 = (size_t)r0 * N + gn;
                    bf16 h0, l0, h1, l1;
                    split_bf16(v00, &h0, &l0); split_bf16(v01, &h1, &l1);
                    *(__nv_bfloat162*)&Chi[i0] = __nv_bfloat162(h0, h1);
                    *(__nv_bfloat162*)&Clo[i0] = __nv_bfloat162(l0, l1);
                }
                if (r1 < M) {
                    size_t i1 = (size_t)r1 * N + gn;
                    bf16 h0, l0, h1, l1;
                    split_bf16(v10, &h0, &l0); split_bf16(v11, &h1, &l1);
                    *(__nv_bfloat162*)&Chi[i1] = __nv_bfloat162(h0, h1);
                    *(__nv_bfloat162*)&Clo[i1] = __nv_bfloat162(l0, l1);
                }
            } else {
                if (r0 < M) {
                    size_t i0 = (size_t)r0 * N + gn;
                    if (EPI == 2) { float2 rr = *(const float2*)&res[i0]; v00 += rr.x; v01 += rr.y; }
                    *(float2*)&C[i0] = make_float2(v00, v01);
                }
                if (r1 < M) {
                    size_t i1 = (size_t)r1 * N + gn;
                    if (EPI == 2) { float2 rr = *(const float2*)&res[i1]; v10 += rr.x; v11 += rr.y; }
                    *(float2*)&C[i1] = make_float2(v10, v11);
                }
            }
        }
    }
}

// ---------------- attention (fp32 SIMT, outputs bf16 hi/lo) ------------------
__global__ __launch_bounds__(128) void attn_kernel(
    const float* __restrict__ bqkv_c, const float* __restrict__ bqkv_t)
{
    int qc = blockIdx.x;
    int h  = blockIdx.y;
    int b  = blockIdx.z;
    int tid = threadIdx.x;

    int token = g_qidx[b * KK + qc * 128 + tid];
    int sel   = g_isctx[b * KK + token];
    int sel_first = g_isctx[b * KK + g_qidx[b * KK + qc * 128]];
    int sel_last  = g_isctx[b * KK + g_qidx[b * KK + qc * 128 + 127]];
    bool uni = (sel_first == sel_last);
    int bank = uni ? 0 : (sel ? 0 : 1);

    const float* qkv  = sel ? g_qkv_c : g_qkv_t;
    const float* bqkv = sel ? bqkv_c  : bqkv_t;

    const float scale = 0.1767766952966369f;
    u64 q2[16];
    {
        const float* qp = qkv + ((size_t)(b * LL + RR + token)) * (3 * DD) + h * HD;
        #pragma unroll
        for (int i = 0; i < 16; i++)
            q2[i] = pack2(qp[2 * i] * scale, qp[2 * i + 1] * scale);
    }

    const u64 z2 = pack2(0.f, 0.f);
    float m = -1e30f, ssum = 0.f;
    u64 acc2[16];
    #pragma unroll
    for (int i = 0; i < 16; i++) acc2[i] = z2;

    __shared__ u64 sK[2][32][16];
    __shared__ u64 sV[2][32][16];

    int cnt = g_kcnt[b];

    for (int t0 = 0; t0 < cnt; t0 += 32) {
        int cnt_tile = min(32, cnt - t0);
        __syncthreads();
        #pragma unroll
        for (int jj = 0; jj < 2; jj++) {
            int idx = tid * 2 + jj;
            int kk = idx >> 3, i4 = idx & 7;
            if (kk < cnt_tile) {
                int l = g_kidx[b * LL + t0 + kk];
                size_t base = ((size_t)(b * LL + l)) * (3 * DD) + h * HD + i4 * 4;
                if (uni) {
                    const float* src = sel_first ? g_qkv_c : g_qkv_t;
                    *(float4*)&sK[0][kk][i4 * 2] = *(const float4*)(src + base + DD);
                    *(float4*)&sV[0][kk][i4 * 2] = *(const float4*)(src + base + 2 * DD);
                } else {
                    *(float4*)&sK[0][kk][i4 * 2] = *(const float4*)(g_qkv_c + base + DD);
                    *(float4*)&sK[1][kk][i4 * 2] = *(const float4*)(g_qkv_t + base + DD);
                    *(float4*)&sV[0][kk][i4 * 2] = *(const float4*)(g_qkv_c + base + 2 * DD);
                    *(float4*)&sV[1][kk][i4 * 2] = *(const float4*)(g_qkv_t + base + 2 * DD);
                }
            }
        }
        __syncthreads();

        for (int kk = 0; kk < cnt_tile; kk++) {
            u64 s2 = z2;
            #pragma unroll
            for (int i = 0; i < 8; i++) {
                ulonglong2 kv = *(const ulonglong2*)&sK[bank][kk][i * 2];
                s2 = ffma2(q2[2 * i], kv.x, s2);
                s2 = ffma2(q2[2 * i + 1], kv.y, s2);
            }
            float2 sf = unpack2(s2);
            float s = sf.x + sf.y;

            if (s <= m) {
                float p = __expf(s - m);
                ssum += p;
                u64 pp = pack2(p, p);
                #pragma unroll
                for (int i = 0; i < 8; i++) {
                    ulonglong2 vv = *(const ulonglong2*)&sV[bank][kk][i * 2];
                    acc2[2 * i]     = ffma2(pp, vv.x, acc2[2 * i]);
                    acc2[2 * i + 1] = ffma2(pp, vv.y, acc2[2 * i + 1]);
                }
            } else {
                float corr = __expf(m - s);
                ssum = ssum * corr + 1.f;
                u64 cc = pack2(corr, corr);
                #pragma unroll
                for (int i = 0; i < 8; i++) {
                    ulonglong2 vv = *(const ulonglong2*)&sV[bank][kk][i * 2];
                    acc2[2 * i]     = ffma2(cc, acc2[2 * i], vv.x);
                    acc2[2 * i + 1] = ffma2(cc, acc2[2 * i + 1], vv.y);
                }
                m = s;
            }
        }
    }

    // appended bias-only key
    {
        float s = 0.f;
        #pragma unroll
        for (int i = 0; i < 16; i++) {
            float2 qf = unpack2(q2[i]);
            s += qf.x * bqkv[DD + h * HD + 2 * i] + qf.y * bqkv[DD + h * HD + 2 * i + 1];
        }
        if (s <= m) {
            float p = __expf(s - m);
            ssum += p;
            #pragma unroll
            for (int i = 0; i < 16; i++) {
                float2 a = unpack2(acc2[i]);
                acc2[i] = pack2(a.x + p * bqkv[2 * DD + h * HD + 2 * i],
                                a.y + p * bqkv[2 * DD + h * HD + 2 * i + 1]);
            }
        } else {
            float corr = __expf(m - s);
            ssum = ssum * corr + 1.f;
            #pragma unroll
            for (int i = 0; i < 16; i++) {
                float2 a = unpack2(acc2[i]);
                acc2[i] = pack2(a.x * corr + bqkv[2 * DD + h * HD + 2 * i],
                                a.y * corr + bqkv[2 * DD + h * HD + 2 * i + 1]);
            }
            m = s;
        }
    }

    float inv = 1.f / ssum;
    size_t obase = ((size_t)(b * KK + token)) * DD + h * HD;
    #pragma unroll
    for (int i = 0; i < 16; i++) {
        float2 a = unpack2(acc2[i]);
        split_bf16(a.x * inv, g_at_h + obase + 2 * i,     g_at_l + obase + 2 * i);
        split_bf16(a.y * inv, g_at_h + obase + 2 * i + 1, g_at_l + obase + 2 * i + 1);
    }
}

// ---------------- residual + LN (reads cat Wo output, selects half) ---------
__global__ __launch_bounds__(256) void resln_kernel(
    const float* __restrict__ gn, const float* __restrict__ bn,
    const float* __restrict__ bo_c, const float* __restrict__ bo_t)
{
    int mrow = blockIdx.x;           // 0..8191
    int d = threadIdx.x;
    int b = mrow >> 10, k = mrow & 1023;
    int sel = g_isctx[b * KK + k];

    __shared__ float red[2][8];
    float att = g_tmp2[(size_t)mrow * (2 * DD) + (sel ? 0 : DD) + d]
              + (sel ? bo_c[d] : bo_t[d]);
    float v = g_xfull[((size_t)(b * LL + RR + k)) * DD + d] + att;
    g_x2[(size_t)mrow * DD + d] = v;

    float s1 = v, s2 = v * v;
    #pragma unroll
    for (int o = 16; o; o >>= 1) {
        s1 += __shfl_down_sync(0xffffffffu, s1, o);
        s2 += __shfl_down_sync(0xffffffffu, s2, o);
    }
    int wid = d >> 5, lane = d & 31;
    if (lane == 0) { red[0][wid] = s1; red[1][wid] = s2; }
    __syncthreads();
    if (d == 0) {
        float t1 = 0.f, t2 = 0.f;
        #pragma unroll
        for (int i = 0; i < 8; i++) { t1 += red[0][i]; t2 += red[1][i]; }
        red[0][0] = t1; red[1][0] = t2;
    }
    __syncthreads();
    float mean = red[0][0] * (1.f / DD);
    float var  = red[1][0] * (1.f / DD) - mean * mean;
    float rstd = rsqrtf(var + 1e-5f);
    float xnv = (v - mean) * rstd * gn[d] + bn[d];
    size_t gi = (size_t)mrow * DD + d;
    split_bf16(xnv, g_x2n_h + gi, g_x2n_l + gi);
}

// ---------------- launch ------------------------------------------------------
static void* sym(const void* s)
{
    void* p = nullptr;
    cudaGetSymbolAddress(&p, s);
    return p;
}

extern "C" void kernel_launch(void* const* d_in, const int* in_sizes, int n_in,
                              void* d_out, int out_size)
{
    const float* x          = (const float*)d_in[0];
    const int*   coords     = (const int*)d_in[1];
    const int*   ctxid      = (const int*)d_in[2];
    const float* tgt_e      = (const float*)d_in[3];
    const float* ctx_e      = (const float*)d_in[4];
    const float* regs       = (const float*)d_in[5];
    const float* rope       = (const float*)d_in[6];
    const float* norm_g     = (const float*)d_in[7];
    const float* norm_b     = (const float*)d_in[8];
    const float* ctx_Wqkv   = (const float*)d_in[9];
    const float* ctx_bqkv   = (const float*)d_in[10];
    const float* ctx_Wo     = (const float*)d_in[11];
    const float* ctx_bo     = (const float*)d_in[12];
    const float* tgt_Wqkv   = (const float*)d_in[13];
    const float* tgt_bqkv   = (const float*)d_in[14];
    const float* tgt_Wo     = (const float*)d_in[15];
    const float* tgt_bo     = (const float*)d_in[16];
    const float* mlpn_g     = (const float*)d_in[17];
    const float* mlpn_b     = (const float*)d_in[18];
    const float* mlp_W1     = (const float*)d_in[19];
    const float* mlp_b1     = (const float*)d_in[20];
    const float* mlp_W2     = (const float*)d_in[21];
    const float* mlp_b2     = (const float*)d_in[22];
    float* out = (float*)d_out;

    bf16* wqc_h = (bf16*)sym(g_wqc_h); bf16* wqc_l = (bf16*)sym(g_wqc_l);
    bf16* wqt_h = (bf16*)sym(g_wqt_h); bf16* wqt_l = (bf16*)sym(g_wqt_l);
    bf16* wo_h  = (bf16*)sym(g_wo_h);  bf16* wo_l  = (bf16*)sym(g_wo_l);
    bf16* w1_h  = (bf16*)sym(g_w1_h);  bf16* w1_l  = (bf16*)sym(g_w1_l);
    bf16* w2_h  = (bf16*)sym(g_w2_h);  bf16* w2_l  = (bf16*)sym(g_w2_l);
    bf16* xn_h  = (bf16*)sym(g_xn_h);  bf16* xn_l  = (bf16*)sym(g_xn_l);
    bf16* at_h  = (bf16*)sym(g_at_h);  bf16* at_l  = (bf16*)sym(g_at_l);
    bf16* x2n_h = (bf16*)sym(g_x2n_h); bf16* x2n_l = (bf16*)sym(g_x2n_l);
    bf16* h1_h  = (bf16*)sym(g_h1_h);  bf16* h1_l  = (bf16*)sym(g_h1_l);
    float* p_qc   = (float*)sym(g_qkv_c);
    float* p_qt   = (float*)sym(g_qkv_t);
    float* p_tmp2 = (float*)sym(g_tmp2);
    float* p_x2   = (float*)sym(g_x2);
    float* p_zb   = (float*)sym(g_zerob);

    // 1) embed + rope + LN (-> xfull float, xn bf16 hi/lo)
    prep_kernel<<<BB * LL, 256>>>(x, coords, ctxid, tgt_e, ctx_e, regs, rope,
                                  norm_g, norm_b);
    // 1b) compaction
    compact_kernel<<<BB, 128>>>();

    // 1c) weight conversions (hi/lo bf16)
    convw_kernel<<<(3 * DD * DD + 255) / 256, 256>>>(ctx_Wqkv, wqc_h, wqc_l, 3 * DD * DD);
    convw_kernel<<<(3 * DD * DD + 255) / 256, 256>>>(tgt_Wqkv, wqt_h, wqt_l, 3 * DD * DD);
    convw_kernel<<<(DD * DD + 255) / 256, 256>>>(ctx_Wo, wo_h, wo_l, DD * DD);
    convw_kernel<<<(DD * DD + 255) / 256, 256>>>(tgt_Wo, wo_h + DD * DD, wo_l + DD * DD, DD * DD);
    convw_kernel<<<(4 * DD * DD + 255) / 256, 256>>>(mlp_W1, w1_h, w1_l, 4 * DD * DD);
    convw_kernel<<<(4 * DD * DD + 255) / 256, 256>>>(mlp_W2, w2_h, w2_l, 4 * DD * DD);

    // 2) QKV GEMMs (tensor cores via mma.sync)
    {
        dim3 g(6, (BB * LL + 127) / 128);     // N=768, M=8224
        mma_gemm<0><<<g, 256>>>(xn_h, xn_l, wqc_h, wqc_l, ctx_bqkv,
                                nullptr, p_qc, nullptr, nullptr,
                                BB * LL, 3 * DD, DD);
        mma_gemm<0><<<g, 256>>>(xn_h, xn_l, wqt_h, wqt_l, tgt_bqkv,
                                nullptr, p_qt, nullptr, nullptr,
                                BB * LL, 3 * DD, DD);
    }

    // 3) attention
    {
        dim3 g(KK / 128, HH, BB);
        attn_kernel<<<g, 128>>>(ctx_bqkv, tgt_bqkv);
    }

    // 4) Wo concatenated GEMM: attn @ [Wo_c; Wo_t]^T  -> tmp2 [8192 x 512]
    {
        dim3 g(4, BB * KK / 128);             // N=512, M=8192
        mma_gemm<0><<<g, 256>>>(at_h, at_l, wo_h, wo_l, p_zb,
                                nullptr, p_tmp2, nullptr, nullptr,
                                BB * KK, 2 * DD, DD);
    }

    // 5) residual + LN (selects Wo half + bias per token)
    resln_kernel<<<BB * KK, 256>>>(mlpn_g, mlpn_b, ctx_bo, tgt_bo);

    // 6) MLP up + gelu -> h1 bf16 hi/lo
    {
        dim3 g(8, BB * KK / 128);             // N=1024
        mma_gemm<1><<<g, 256>>>(x2n_h, x2n_l, w1_h, w1_l, mlp_b1,
                                nullptr, nullptr, h1_h, h1_l,
                                BB * KK, 4 * DD, DD);
    }

    // 7) MLP down + residual -> out
    {
        dim3 g(2, BB * KK / 128);             // N=256, Kd=1024
        mma_gemm<2><<<g, 256>>>(h1_h, h1_l, w2_h, w2_l, mlp_b2,
                                p_x2, out, nullptr, nullptr,
                                BB * KK, DD, 4 * DD);
    }
}

// round 11
// speedup vs baseline: 3.1617x; 1.3563x over previous
#include <cuda_runtime.h>
#include <cuda_bf16.h>
#include <math.h>

// Problem constants
#define BB 8
#define KK 1024
#define DD 256
#define HH 8
#define RR 4
#define LL 1028      // RR + KK
#define HD 32
#define IMGF 224.0f
#define MAXPF 1023.0f

typedef unsigned long long u64;
typedef __nv_bfloat16 bf16;

// ---------------- mma.sync helpers (base PTX, compute_103-safe) -------------
__device__ __forceinline__ unsigned smem_u32(const void* p) {
    unsigned a;
    asm("{ .reg .u64 t; cvta.to.shared.u64 t, %1; cvt.u32.u64 %0, t; }"
        : "=r"(a) : "l"(p));
    return a;
}
__device__ __forceinline__ void ldsm4(unsigned* r, unsigned addr) {
    asm volatile("ldmatrix.sync.aligned.m8n8.x4.shared.b16 {%0,%1,%2,%3}, [%4];"
                 : "=r"(r[0]), "=r"(r[1]), "=r"(r[2]), "=r"(r[3]) : "r"(addr));
}
__device__ __forceinline__ void ldsm4t(unsigned* r, unsigned addr) {
    asm volatile("ldmatrix.sync.aligned.m8n8.x4.trans.shared.b16 {%0,%1,%2,%3}, [%4];"
                 : "=r"(r[0]), "=r"(r[1]), "=r"(r[2]), "=r"(r[3]) : "r"(addr));
}
__device__ __forceinline__ void mma16816(float* c, const unsigned* a,
                                         unsigned b0, unsigned b1) {
    asm volatile(
        "mma.sync.aligned.m16n8k16.row.col.f32.bf16.bf16.f32 "
        "{%0,%1,%2,%3}, {%4,%5,%6,%7}, {%8,%9}, {%0,%1,%2,%3};"
        : "+f"(c[0]), "+f"(c[1]), "+f"(c[2]), "+f"(c[3])
        : "r"(a[0]), "r"(a[1]), "r"(a[2]), "r"(a[3]), "r"(b0), "r"(b1));
}
// pack (lo, hi) floats -> bf16x2 (lo in low 16 bits)
__device__ __forceinline__ unsigned bf16pair(float lo, float hi) {
    unsigned r;
    asm("cvt.rn.bf16x2.f32 %0, %1, %2;" : "=r"(r) : "f"(hi), "f"(lo));
    return r;
}
// fast exp for x <= 0 on fma pipe (no MUFU); rel err ~2.4e-6
__device__ __forceinline__ float expapx(float x) {
    x = fmaxf(x, -87.0f);
    float t = x * 1.44269504088896341f;
    float fn = rintf(t);
    int n = (int)fn;
    float r = t - fn;
    float p = fmaf(0.0013333558f, r, 0.0096181291f);
    p = fmaf(p, r, 0.0555041087f);
    p = fmaf(p, r, 0.2402265069f);
    p = fmaf(p, r, 0.6931471806f);
    p = fmaf(p, r, 1.0f);
    return __int_as_float((n + 127) << 23) * p;
}

// ---------------- scratch (device globals; no allocation allowed) ----------
__device__ float g_xfull[BB * LL * DD];
__device__ int   g_allowed[BB * LL];
__device__ int   g_isctx[BB * KK];
__device__ int   g_kidx[BB * LL];
__device__ int   g_kcnt[BB];
__device__ int   g_qidx[BB * KK];
__device__ float g_qkv_c[BB * LL * 3 * DD];
__device__ float g_qkv_t[BB * LL * 3 * DD];
__device__ float g_tmp2[BB * KK * 2 * DD];     // attn @ [Wo_c; Wo_t]
__device__ float g_x2[BB * KK * DD];
__device__ float g_zerob[2 * DD];              // zero bias (never written)

// bf16 hi/lo activation buffers
__device__ bf16 g_xn_h[BB * LL * DD],   g_xn_l[BB * LL * DD];
__device__ bf16 g_at_h[BB * KK * DD],   g_at_l[BB * KK * DD];
__device__ bf16 g_x2n_h[BB * KK * DD],  g_x2n_l[BB * KK * DD];
__device__ bf16 g_h1_h[BB * KK * 4 * DD], g_h1_l[BB * KK * 4 * DD];

// bf16 hi/lo weight buffers
__device__ bf16 g_wqc_h[3 * DD * DD], g_wqc_l[3 * DD * DD];
__device__ bf16 g_wqt_h[3 * DD * DD], g_wqt_l[3 * DD * DD];
__device__ bf16 g_wo_h[2 * DD * DD],  g_wo_l[2 * DD * DD];
__device__ bf16 g_w1_h[4 * DD * DD],  g_w1_l[4 * DD * DD];
__device__ bf16 g_w2_h[4 * DD * DD],  g_w2_l[4 * DD * DD];

// bf16 K/V banks for attention: [bank(0=ctx,1=tgt)][b][h][l][32]
#define KVIDX(bank,b,h,l) (((size_t)(((bank) * BB + (b)) * HH + (h)) * LL + (l)) * HD)
__device__ bf16 g_kh[2 * BB * HH * LL * HD];
__device__ bf16 g_kl[2 * BB * HH * LL * HD];
__device__ bf16 g_kv[2 * BB * HH * LL * HD];

__device__ __forceinline__ void split_bf16(float v, bf16* hp, bf16* lp) {
    bf16 h = __float2bfloat16(v);
    *hp = h;
    *lp = __float2bfloat16(v - __bfloat162float(h));
}

// ---------------- fused weight conversion (all 6 segments, 1M elems) --------
__global__ __launch_bounds__(256) void convw_all(
    const float* __restrict__ s0, const float* __restrict__ s1,
    const float* __restrict__ s2, const float* __restrict__ s3,
    const float* __restrict__ s4, const float* __restrict__ s5)
{
    int i = blockIdx.x * 256 + threadIdx.x;   // < 1048576
    const int N0 = 3 * DD * DD;   // 196608 (x2)
    const int N2 = DD * DD;       // 65536 (x2)
    const int N4 = 4 * DD * DD;   // 262144 (x2)
    if (i < N0) {
        split_bf16(s0[i], g_wqc_h + i, g_wqc_l + i);
    } else if (i < 2 * N0) {
        int j = i - N0;
        split_bf16(s1[j], g_wqt_h + j, g_wqt_l + j);
    } else if (i < 2 * N0 + N2) {
        int j = i - 2 * N0;
        split_bf16(s2[j], g_wo_h + j, g_wo_l + j);
    } else if (i < 2 * N0 + 2 * N2) {
        int j = i - 2 * N0 - N2;
        split_bf16(s3[j], g_wo_h + N2 + j, g_wo_l + N2 + j);
    } else if (i < 2 * N0 + 2 * N2 + N4) {
        int j = i - 2 * N0 - 2 * N2;
        split_bf16(s4[j], g_w1_h + j, g_w1_l + j);
    } else {
        int j = i - 2 * N0 - 2 * N2 - N4;
        split_bf16(s5[j], g_w2_h + j, g_w2_l + j);
    }
}

// ---------------- K/V bank conversion (fp32 qkv -> bf16 banks) --------------
__global__ __launch_bounds__(256) void kv_conv()
{
    int blk = blockIdx.x;                 // bank*BB*LL + b*LL + l
    int bank = blk / (BB * LL);
    int rem = blk - bank * (BB * LL);
    int b = rem / LL;
    int l = rem - b * LL;
    int d = threadIdx.x;                  // 0..255
    const float* src = (bank == 0) ? g_qkv_c : g_qkv_t;
    size_t base = ((size_t)(b * LL + l)) * (3 * DD);
    int h = d >> 5, dd = d & 31;
    size_t o = KVIDX(bank, b, h, l) + dd;
    split_bf16(src[base + DD + d], g_kh + o, g_kl + o);
    g_kv[o] = __float2bfloat16(src[base + 2 * DD + d]);
}

// ---------------- prep: embed add + rope2d + LN (-> bf16 hi/lo) ------------
__global__ __launch_bounds__(256) void prep_kernel(
    const float* __restrict__ x, const int* __restrict__ coords,
    const int* __restrict__ ctxid, const float* __restrict__ tgt_e,
    const float* __restrict__ ctx_e, const float* __restrict__ regs,
    const float* __restrict__ rope, const float* __restrict__ ng,
    const float* __restrict__ nb)
{
    int blk = blockIdx.x;
    int b = blk / LL;
    int l = blk - b * LL;
    int d = threadIdx.x;

    __shared__ float srow[DD];
    __shared__ float red[2][8];

    float v;
    int ic = 1;
    if (l < RR) {
        v = regs[l * DD + d] + ctx_e[d];
    } else {
        int k = l - RR;
        ic = ctxid[b * KK + k] > 0;
        v = x[((size_t)(b * KK + k)) * DD + d] + (ic ? ctx_e[d] : tgt_e[d]);
    }
    srow[d] = v;
    __syncthreads();

    float rv = v;
    if (l >= RR) {
        int k = l - RR;
        int cy = coords[(size_t)(b * KK + k) * 2 + 0];
        int cx = coords[(size_t)(b * KK + k) * 2 + 1];
        float cny = fminf(fmaxf(((float)cy / IMGF) * MAXPF, 0.f), MAXPF);
        float cnx = fminf(fmaxf(((float)cx / IMGF) * MAXPF, 0.f), MAXPF);
        int yi = (int)cny;
        int xi = (int)cnx;
        int j; const float* cp;
        if (d < 128) { j = d >> 1;         cp = rope + ((size_t)xi * 64 + j) * 2; }
        else         { j = (d - 128) >> 1; cp = rope + ((size_t)yi * 64 + j) * 2; }
        float c = cp[0], s = cp[1];
        float p0 = srow[d & ~1];
        float p1 = srow[d | 1];
        rv = (d & 1) ? (p0 * s + p1 * c) : (p0 * c - p1 * s);
    }

    size_t gi = ((size_t)(b * LL + l)) * DD + d;
    g_xfull[gi] = rv;
    if (d == 0) {
        g_allowed[b * LL + l] = (l < RR) ? 1 : ic;
        if (l >= RR) g_isctx[b * KK + (l - RR)] = ic;
    }

    float s1 = rv, s2 = rv * rv;
    #pragma unroll
    for (int o = 16; o; o >>= 1) {
        s1 += __shfl_down_sync(0xffffffffu, s1, o);
        s2 += __shfl_down_sync(0xffffffffu, s2, o);
    }
    int wid = d >> 5, lane = d & 31;
    if (lane == 0) { red[0][wid] = s1; red[1][wid] = s2; }
    __syncthreads();
    if (d == 0) {
        float t1 = 0.f, t2 = 0.f;
        #pragma unroll
        for (int i = 0; i < 8; i++) { t1 += red[0][i]; t2 += red[1][i]; }
        red[0][0] = t1; red[1][0] = t2;
    }
    __syncthreads();
    float mean = red[0][0] * (1.f / DD);
    float var  = red[1][0] * (1.f / DD) - mean * mean;
    float rstd = rsqrtf(var + 1e-5f);
    float xnv = (rv - mean) * rstd * ng[d] + nb[d];
    split_bf16(xnv, g_xn_h + gi, g_xn_l + gi);
}

// ---------------- compaction -------------------------------------------------
__global__ __launch_bounds__(128) void compact_kernel()
{
    int b = blockIdx.x;
    __shared__ int sa[LL];
    __shared__ int si[KK];
    for (int i = threadIdx.x; i < LL; i += blockDim.x) sa[i] = g_allowed[b * LL + i];
    for (int i = threadIdx.x; i < KK; i += blockDim.x) si[i] = g_isctx[b * KK + i];
    __syncthreads();
    if (threadIdx.x == 0) {
        int c = 0;
        for (int l = 0; l < LL; l++)
            if (sa[l]) g_kidx[b * LL + c++] = l;
        g_kcnt[b] = c;
    } else if (threadIdx.x == 32) {
        int c = 0;
        for (int k = 0; k < KK; k++)
            if (si[k]) g_qidx[b * KK + c++] = k;
        for (int k = 0; k < KK; k++)
            if (!si[k]) g_qidx[b * KK + c++] = k;
    }
}

// ---------------- mma.sync bf16-split GEMM (unchanged, verified) -------------
#define SSTR 40   // smem row stride in bf16 (80B, conflict-free ldmatrix)

template <int EPI>
__global__ __launch_bounds__(256) void mma_gemm(
    const bf16* __restrict__ Ahi, const bf16* __restrict__ Alo,
    const bf16* __restrict__ Whi, const bf16* __restrict__ Wlo,
    const float* __restrict__ bias, const float* __restrict__ res,
    float* __restrict__ C, bf16* __restrict__ Chi, bf16* __restrict__ Clo,
    int M, int N, int Kd)
{
    __shared__ bf16 sAh[128][SSTR];
    __shared__ bf16 sAl[128][SSTR];
    __shared__ bf16 sWh[128][SSTR];
    __shared__ bf16 sWl[128][SSTR];

    int tid = threadIdx.x;
    int wid = tid >> 5, lane = tid & 31;
    int m0 = blockIdx.y * 128;
    int n0 = blockIdx.x * 128;
    int wm = wid >> 1;
    int wn = wid & 1;

    float acc[2][8][4];
    #pragma unroll
    for (int t = 0; t < 2; t++)
        #pragma unroll
        for (int j = 0; j < 8; j++)
            #pragma unroll
            for (int q = 0; q < 4; q++) acc[t][j][q] = 0.f;

    int srow = tid >> 1;
    int scol = (tid & 1) * 16;
    int agm = m0 + srow;
    bool aok = (agm < M);

    int lrow = lane & 15;
    int lcol8 = (lane >> 4) * 8;

    for (int k0 = 0; k0 < Kd; k0 += 32) {
        {
            const uint4* pa_h = (const uint4*)(Ahi + (size_t)agm * Kd + k0 + scol);
            const uint4* pa_l = (const uint4*)(Alo + (size_t)agm * Kd + k0 + scol);
            uint4 z = make_uint4(0u, 0u, 0u, 0u);
            uint4 vh0 = aok ? pa_h[0] : z;
            uint4 vh1 = aok ? pa_h[1] : z;
            uint4 vl0 = aok ? pa_l[0] : z;
            uint4 vl1 = aok ? pa_l[1] : z;
            *(uint4*)&sAh[srow][scol]     = vh0;
            *(uint4*)&sAh[srow][scol + 8] = vh1;
            *(uint4*)&sAl[srow][scol]     = vl0;
            *(uint4*)&sAl[srow][scol + 8] = vl1;

            const uint4* pw_h = (const uint4*)(Whi + (size_t)(n0 + srow) * Kd + k0 + scol);
            const uint4* pw_l = (const uint4*)(Wlo + (size_t)(n0 + srow) * Kd + k0 + scol);
            uint4 wh0 = pw_h[0], wh1 = pw_h[1];
            uint4 wl0 = pw_l[0], wl1 = pw_l[1];
            *(uint4*)&sWh[srow][scol]     = wh0;
            *(uint4*)&sWh[srow][scol + 8] = wh1;
            *(uint4*)&sWl[srow][scol]     = wl0;
            *(uint4*)&sWl[srow][scol + 8] = wl1;
        }
        __syncthreads();

        #pragma unroll
        for (int ks = 0; ks < 2; ks++) {
            int ko = ks * 16 + lcol8;
            unsigned ah[2][4], al[2][4], w[4][4];
            #pragma unroll
            for (int t = 0; t < 2; t++) {
                ldsm4(ah[t], smem_u32(&sAh[wm * 32 + t * 16 + lrow][ko]));
                ldsm4(al[t], smem_u32(&sAl[wm * 32 + t * 16 + lrow][ko]));
            }
            #pragma unroll
            for (int g = 0; g < 4; g++)
                ldsm4(w[g], smem_u32(&sWh[wn * 64 + g * 16 + lrow][ko]));
            #pragma unroll
            for (int t = 0; t < 2; t++)
                #pragma unroll
                for (int g = 0; g < 4; g++) {
                    mma16816(acc[t][g * 2],     ah[t], w[g][0], w[g][2]);
                    mma16816(acc[t][g * 2 + 1], ah[t], w[g][1], w[g][3]);
                    mma16816(acc[t][g * 2],     al[t], w[g][0], w[g][2]);
                    mma16816(acc[t][g * 2 + 1], al[t], w[g][1], w[g][3]);
                }
            #pragma unroll
            for (int g = 0; g < 4; g++)
                ldsm4(w[g], smem_u32(&sWl[wn * 64 + g * 16 + lrow][ko]));
            #pragma unroll
            for (int t = 0; t < 2; t++)
                #pragma unroll
                for (int g = 0; g < 4; g++) {
                    mma16816(acc[t][g * 2],     ah[t], w[g][0], w[g][2]);
                    mma16816(acc[t][g * 2 + 1], ah[t], w[g][1], w[g][3]);
                }
        }
        __syncthreads();
    }

    int lr = lane >> 2;
    int lc = (lane & 3) * 2;
    #pragma unroll
    for (int t = 0; t < 2; t++) {
        int r0 = m0 + wm * 32 + t * 16 + lr;
        int r1 = r0 + 8;
        #pragma unroll
        for (int j = 0; j < 8; j++) {
            int gn = n0 + wn * 64 + j * 8 + lc;
            float b0 = bias[gn], b1 = bias[gn + 1];
            float v00 = acc[t][j][0] + b0, v01 = acc[t][j][1] + b1;
            float v10 = acc[t][j][2] + b0, v11 = acc[t][j][3] + b1;
            if (EPI == 1) {
                v00 = 0.5f * v00 * (1.0f + erff(v00 * 0.70710678118654752f));
                v01 = 0.5f * v01 * (1.0f + erff(v01 * 0.70710678118654752f));
                v10 = 0.5f * v10 * (1.0f + erff(v10 * 0.70710678118654752f));
                v11 = 0.5f * v11 * (1.0f + erff(v11 * 0.70710678118654752f));
            }
            if (EPI == 1) {
                if (r0 < M) {
                    size_t i0 = (size_t)r0 * N + gn;
                    bf16 h0, l0, h1, l1;
                    split_bf16(v00, &h0, &l0); split_bf16(v01, &h1, &l1);
                    *(__nv_bfloat162*)&Chi[i0] = __nv_bfloat162(h0, h1);
                    *(__nv_bfloat162*)&Clo[i0] = __nv_bfloat162(l0, l1);
                }
                if (r1 < M) {
                    size_t i1 = (size_t)r1 * N + gn;
                    bf16 h0, l0, h1, l1;
                    split_bf16(v10, &h0, &l0); split_bf16(v11, &h1, &l1);
                    *(__nv_bfloat162*)&Chi[i1] = __nv_bfloat162(h0, h1);
                    *(__nv_bfloat162*)&Clo[i1] = __nv_bfloat162(l0, l1);
                }
            } else {
                if (r0 < M) {
                    size_t i0 = (size_t)r0 * N + gn;
                    if (EPI == 2) { float2 rr = *(const float2*)&res[i0]; v00 += rr.x; v01 += rr.y; }
                    *(float2*)&C[i0] = make_float2(v00, v01);
                }
                if (r1 < M) {
                    size_t i1 = (size_t)r1 * N + gn;
                    if (EPI == 2) { float2 rr = *(const float2*)&res[i1]; v10 += rr.x; v11 += rr.y; }
                    *(float2*)&C[i1] = make_float2(v10, v11);
                }
            }
        }
    }
}

// ---------------- tensor-core flash attention --------------------------------
// grid (16, HH, BB): 64-query tile per CTA, 4 warps (16 q rows each).
// S = Q@K^T in 3 bf16 phases; softmax with fma-pipe exp; P@V single phase.
__global__ __launch_bounds__(128) void attn_mma(
    const float* __restrict__ bqkv_c, const float* __restrict__ bqkv_t)
{
    int qt = blockIdx.x, h = blockIdx.y, b = blockIdx.z;
    int tid = threadIdx.x, wid = tid >> 5, lane = tid & 31;

    __shared__ bf16 sQh[64][SSTR], sQl[64][SSTR];
    __shared__ bf16 sKh[32][SSTR], sKl[32][SSTR], sVt[32][SSTR];
    __shared__ int stok[64], ssel[64];

    if (tid < 64) {
        int tok = g_qidx[b * KK + qt * 64 + tid];
        stok[tid] = tok;
        ssel[tid] = g_isctx[b * KK + tok];
    }
    __syncthreads();

    // stage Q (scaled by 1/sqrt(hd), hi/lo split); row's own bank
    {
        const float scale = 0.1767766952966369f;
        int row = tid >> 1;
        int dg = (tid & 1) * 16;
        const float* src = ssel[row] ? g_qkv_c : g_qkv_t;
        const float* qp = src + ((size_t)(b * LL + RR + stok[row])) * (3 * DD) + h * HD + dg;
        #pragma unroll
        for (int j = 0; j < 16; j++) {
            float v = qp[j] * scale;
            split_bf16(v, &sQh[row][dg + j], &sQl[row][dg + j]);
        }
    }
    __syncthreads();

    int lrow = lane & 15, lcol8 = (lane >> 4) * 8;
    unsigned qhf[2][4], qlf[2][4];
    #pragma unroll
    for (int kc = 0; kc < 2; kc++) {
        ldsm4(qhf[kc], smem_u32(&sQh[wid * 16 + lrow][kc * 16 + lcol8]));
        ldsm4(qlf[kc], smem_u32(&sQl[wid * 16 + lrow][kc * 16 + lcol8]));
    }

    int uni = (ssel[0] == ssel[63]);
    int cnt = g_kcnt[b];
    int cntp1 = cnt + 1;
    int ntiles = (cntp1 + 31) >> 5;
    int npass = uni ? 1 : 2;
    int kc0 = 2 * (lane & 3);

    for (int pass = 0; pass < npass; pass++) {
        int psel = uni ? ssel[0] : (pass == 0 ? 1 : 0);
        int bank = psel ? 0 : 1;
        const float* bq = psel ? bqkv_c : bqkv_t;
        const bf16* khs = g_kh + KVIDX(bank, b, h, 0);
        const bf16* kls = g_kl + KVIDX(bank, b, h, 0);
        const bf16* vs  = g_kv + KVIDX(bank, b, h, 0);

        float O[4][4];
        #pragma unroll
        for (int nb = 0; nb < 4; nb++)
            #pragma unroll
            for (int q = 0; q < 4; q++) O[nb][q] = 0.f;
        float mrow[2] = {-1e30f, -1e30f};
        float ssum[2] = {0.f, 0.f};

        for (int t = 0; t < ntiles; t++) {
            int g0 = t * 32;
            __syncthreads();
            // stage K(hi/lo) and V for 32 key slots
            {
                int slot = tid >> 2, dg = (tid & 3) * 8;
                int gk = g0 + slot;
                if (gk < cnt) {
                    size_t l = (size_t)g_kidx[b * LL + gk] * HD + dg;
                    *(uint4*)&sKh[slot][dg] = *(const uint4*)(khs + l);
                    *(uint4*)&sKl[slot][dg] = *(const uint4*)(kls + l);
                    *(uint4*)&sVt[slot][dg] = *(const uint4*)(vs + l);
                } else if (gk == cnt) {
                    // bias-only key: k = bk, v = bv
                    #pragma unroll
                    for (int j = 0; j < 8; j++) {
                        split_bf16(bq[DD + h * HD + dg + j], &sKh[slot][dg + j], &sKl[slot][dg + j]);
                        sVt[slot][dg + j] = __float2bfloat16(bq[2 * DD + h * HD + dg + j]);
                    }
                } else {
                    uint4 z = make_uint4(0u, 0u, 0u, 0u);
                    *(uint4*)&sKh[slot][dg] = z;
                    *(uint4*)&sKl[slot][dg] = z;
                    *(uint4*)&sVt[slot][dg] = z;
                }
            }
            __syncthreads();

            // S = Q@K^T (3 phases)
            float s[4][4];
            #pragma unroll
            for (int nb = 0; nb < 4; nb++)
                #pragma unroll
                for (int q = 0; q < 4; q++) s[nb][q] = 0.f;
            #pragma unroll
            for (int kc = 0; kc < 2; kc++) {
                int ko = kc * 16 + lcol8;
                unsigned khf[2][4], klf[2][4];
                #pragma unroll
                for (int g = 0; g < 2; g++) {
                    ldsm4(khf[g], smem_u32(&sKh[g * 16 + lrow][ko]));
                    ldsm4(klf[g], smem_u32(&sKl[g * 16 + lrow][ko]));
                }
                #pragma unroll
                for (int g = 0; g < 2; g++) {
                    mma16816(s[g * 2],     qhf[kc], khf[g][0], khf[g][2]);
                    mma16816(s[g * 2 + 1], qhf[kc], khf[g][1], khf[g][3]);
                    mma16816(s[g * 2],     qlf[kc], khf[g][0], khf[g][2]);
                    mma16816(s[g * 2 + 1], qlf[kc], khf[g][1], khf[g][3]);
                    mma16816(s[g * 2],     qhf[kc], klf[g][0], klf[g][2]);
                    mma16816(s[g * 2 + 1], qhf[kc], klf[g][1], klf[g][3]);
                }
            }
            // V fragments (trans): vf[kc][pair] covers dim-blocks pair*2, pair*2+1
            unsigned vf[2][2][4];
            #pragma unroll
            for (int kc = 0; kc < 2; kc++)
                #pragma unroll
                for (int vp = 0; vp < 2; vp++)
                    ldsm4t(vf[kc][vp], smem_u32(&sVt[kc * 16 + lrow][vp * 16 + lcol8]));

            // mask invalid key columns
            #pragma unroll
            for (int nb = 0; nb < 4; nb++) {
                int c0 = g0 + nb * 8 + kc0;
                if (c0 >= cntp1)     { s[nb][0] = -1e30f; s[nb][2] = -1e30f; }
                if (c0 + 1 >= cntp1) { s[nb][1] = -1e30f; s[nb][3] = -1e30f; }
            }

            // online softmax per row-half
            #pragma unroll
            for (int th = 0; th < 2; th++) {
                float lm = s[0][2 * th];
                #pragma unroll
                for (int nb = 0; nb < 4; nb++)
                    lm = fmaxf(lm, fmaxf(s[nb][2 * th], s[nb][2 * th + 1]));
                lm = fmaxf(lm, __shfl_xor_sync(0xffffffffu, lm, 1));
                lm = fmaxf(lm, __shfl_xor_sync(0xffffffffu, lm, 2));
                float mn = fmaxf(mrow[th], lm);
                float corr = expapx(mrow[th] - mn);
                mrow[th] = mn;
                float rs = 0.f;
                #pragma unroll
                for (int nb = 0; nb < 4; nb++) {
                    s[nb][2 * th]     = expapx(s[nb][2 * th] - mn);
                    s[nb][2 * th + 1] = expapx(s[nb][2 * th + 1] - mn);
                    rs += s[nb][2 * th] + s[nb][2 * th + 1];
                }
                rs += __shfl_xor_sync(0xffffffffu, rs, 1);
                rs += __shfl_xor_sync(0xffffffffu, rs, 2);
                ssum[th] = ssum[th] * corr + rs;
                #pragma unroll
                for (int nb = 0; nb < 4; nb++) {
                    O[nb][2 * th]     *= corr;
                    O[nb][2 * th + 1] *= corr;
                }
            }

            // P@V
            #pragma unroll
            for (int kc = 0; kc < 2; kc++) {
                unsigned pa[4];
                pa[0] = bf16pair(s[2 * kc][0],     s[2 * kc][1]);
                pa[1] = bf16pair(s[2 * kc][2],     s[2 * kc][3]);
                pa[2] = bf16pair(s[2 * kc + 1][0], s[2 * kc + 1][1]);
                pa[3] = bf16pair(s[2 * kc + 1][2], s[2 * kc + 1][3]);
                mma16816(O[0], pa, vf[kc][0][0], vf[kc][0][1]);
                mma16816(O[1], pa, vf[kc][0][2], vf[kc][0][3]);
                mma16816(O[2], pa, vf[kc][1][0], vf[kc][1][1]);
                mma16816(O[3], pa, vf[kc][1][2], vf[kc][1][3]);
            }
        }

        // write rows matching this pass's bank
        float inv[2] = {1.f / ssum[0], 1.f / ssum[1]};
        #pragma unroll
        for (int th = 0; th < 2; th++) {
            int rl = wid * 16 + (lane >> 2) + th * 8;
            if (ssel[rl] == psel) {
                size_t base = ((size_t)(b * KK + stok[rl])) * DD + h * HD;
                #pragma unroll
                for (int nb = 0; nb < 4; nb++) {
                    int col = nb * 8 + kc0;
                    float v0 = O[nb][2 * th] * inv[th];
                    float v1 = O[nb][2 * th + 1] * inv[th];
                    bf16 h0, l0, h1, l1;
                    split_bf16(v0, &h0, &l0);
                    split_bf16(v1, &h1, &l1);
                    *(__nv_bfloat162*)&g_at_h[base + col] = __nv_bfloat162(h0, h1);
                    *(__nv_bfloat162*)&g_at_l[base + col] = __nv_bfloat162(l0, l1);
                }
            }
        }
    }
}

// ---------------- residual + LN (reads cat Wo output, selects half) ---------
__global__ __launch_bounds__(256) void resln_kernel(
    const float* __restrict__ gn, const float* __restrict__ bn,
    const float* __restrict__ bo_c, const float* __restrict__ bo_t)
{
    int mrow = blockIdx.x;
    int d = threadIdx.x;
    int b = mrow >> 10, k = mrow & 1023;
    int sel = g_isctx[b * KK + k];

    __shared__ float red[2][8];
    float att = g_tmp2[(size_t)mrow * (2 * DD) + (sel ? 0 : DD) + d]
              + (sel ? bo_c[d] : bo_t[d]);
    float v = g_xfull[((size_t)(b * LL + RR + k)) * DD + d] + att;
    g_x2[(size_t)mrow * DD + d] = v;

    float s1 = v, s2 = v * v;
    #pragma unroll
    for (int o = 16; o; o >>= 1) {
        s1 += __shfl_down_sync(0xffffffffu, s1, o);
        s2 += __shfl_down_sync(0xffffffffu, s2, o);
    }
    int wid = d >> 5, lane = d & 31;
    if (lane == 0) { red[0][wid] = s1; red[1][wid] = s2; }
    __syncthreads();
    if (d == 0) {
        float t1 = 0.f, t2 = 0.f;
        #pragma unroll
        for (int i = 0; i < 8; i++) { t1 += red[0][i]; t2 += red[1][i]; }
        red[0][0] = t1; red[1][0] = t2;
    }
    __syncthreads();
    float mean = red[0][0] * (1.f / DD);
    float var  = red[1][0] * (1.f / DD) - mean * mean;
    float rstd = rsqrtf(var + 1e-5f);
    float xnv = (v - mean) * rstd * gn[d] + bn[d];
    size_t gi = (size_t)mrow * DD + d;
    split_bf16(xnv, g_x2n_h + gi, g_x2n_l + gi);
}

// ---------------- launch ------------------------------------------------------
static void* sym(const void* s)
{
    void* p = nullptr;
    cudaGetSymbolAddress(&p, s);
    return p;
}

extern "C" void kernel_launch(void* const* d_in, const int* in_sizes, int n_in,
                              void* d_out, int out_size)
{
    const float* x          = (const float*)d_in[0];
    const int*   coords     = (const int*)d_in[1];
    const int*   ctxid      = (const int*)d_in[2];
    const float* tgt_e      = (const float*)d_in[3];
    const float* ctx_e      = (const float*)d_in[4];
    const float* regs       = (const float*)d_in[5];
    const float* rope       = (const float*)d_in[6];
    const float* norm_g     = (const float*)d_in[7];
    const float* norm_b     = (const float*)d_in[8];
    const float* ctx_Wqkv   = (const float*)d_in[9];
    const float* ctx_bqkv   = (const float*)d_in[10];
    const float* ctx_Wo     = (const float*)d_in[11];
    const float* ctx_bo     = (const float*)d_in[12];
    const float* tgt_Wqkv   = (const float*)d_in[13];
    const float* tgt_bqkv   = (const float*)d_in[14];
    const float* tgt_Wo     = (const float*)d_in[15];
    const float* tgt_bo     = (const float*)d_in[16];
    const float* mlpn_g     = (const float*)d_in[17];
    const float* mlpn_b     = (const float*)d_in[18];
    const float* mlp_W1     = (const float*)d_in[19];
    const float* mlp_b1     = (const float*)d_in[20];
    const float* mlp_W2     = (const float*)d_in[21];
    const float* mlp_b2     = (const float*)d_in[22];
    float* out = (float*)d_out;

    bf16* wqc_h = (bf16*)sym(g_wqc_h); bf16* wqc_l = (bf16*)sym(g_wqc_l);
    bf16* wqt_h = (bf16*)sym(g_wqt_h); bf16* wqt_l = (bf16*)sym(g_wqt_l);
    bf16* wo_h  = (bf16*)sym(g_wo_h);  bf16* wo_l  = (bf16*)sym(g_wo_l);
    bf16* w1_h  = (bf16*)sym(g_w1_h);  bf16* w1_l  = (bf16*)sym(g_w1_l);
    bf16* w2_h  = (bf16*)sym(g_w2_h);  bf16* w2_l  = (bf16*)sym(g_w2_l);
    bf16* xn_h  = (bf16*)sym(g_xn_h);  bf16* xn_l  = (bf16*)sym(g_xn_l);
    bf16* at_h  = (bf16*)sym(g_at_h);  bf16* at_l  = (bf16*)sym(g_at_l);
    bf16* x2n_h = (bf16*)sym(g_x2n_h); bf16* x2n_l = (bf16*)sym(g_x2n_l);
    bf16* h1_h  = (bf16*)sym(g_h1_h);  bf16* h1_l  = (bf16*)sym(g_h1_l);
    float* p_qc   = (float*)sym(g_qkv_c);
    float* p_qt   = (float*)sym(g_qkv_t);
    float* p_tmp2 = (float*)sym(g_tmp2);
    float* p_x2   = (float*)sym(g_x2);
    float* p_zb   = (float*)sym(g_zerob);

    // 1) embed + rope + LN
    prep_kernel<<<BB * LL, 256>>>(x, coords, ctxid, tgt_e, ctx_e, regs, rope,
                                  norm_g, norm_b);
    // 1b) compaction
    compact_kernel<<<BB, 128>>>();

    // 1c) fused weight conversion (exactly 1M elements)
    convw_all<<<4096, 256>>>(ctx_Wqkv, tgt_Wqkv, ctx_Wo, tgt_Wo, mlp_W1, mlp_W2);

    // 2) QKV GEMMs
    {
        dim3 g(6, (BB * LL + 127) / 128);
        mma_gemm<0><<<g, 256>>>(xn_h, xn_l, wqc_h, wqc_l, ctx_bqkv,
                                nullptr, p_qc, nullptr, nullptr,
                                BB * LL, 3 * DD, DD);
        mma_gemm<0><<<g, 256>>>(xn_h, xn_l, wqt_h, wqt_l, tgt_bqkv,
                                nullptr, p_qt, nullptr, nullptr,
                                BB * LL, 3 * DD, DD);
    }

    // 2b) K/V bf16 bank conversion
    kv_conv<<<2 * BB * LL, 256>>>();

    // 3) tensor-core flash attention
    {
        dim3 g(KK / 64, HH, BB);
        attn_mma<<<g, 128>>>(ctx_bqkv, tgt_bqkv);
    }

    // 4) Wo concatenated GEMM: attn @ [Wo_c; Wo_t]^T
    {
        dim3 g(4, BB * KK / 128);
        mma_gemm<0><<<g, 256>>>(at_h, at_l, wo_h, wo_l, p_zb,
                                nullptr, p_tmp2, nullptr, nullptr,
                                BB * KK, 2 * DD, DD);
    }

    // 5) residual + LN
    resln_kernel<<<BB * KK, 256>>>(mlpn_g, mlpn_b, ctx_bo, tgt_bo);

    // 6) MLP up + gelu
    {
        dim3 g(8, BB * KK / 128);
        mma_gemm<1><<<g, 256>>>(x2n_h, x2n_l, w1_h, w1_l, mlp_b1,
                                nullptr, nullptr, h1_h, h1_l,
                                BB * KK, 4 * DD, DD);
    }

    // 7) MLP down + residual -> out
    {
        dim3 g(2, BB * KK / 128);
        mma_gemm<2><<<g, 256>>>(h1_h, h1_l, w2_h, w2_l, mlp_b2,
                                p_x2, out, nullptr, nullptr,
                                BB * KK, DD, 4 * DD);
    }
}

// round 13
// speedup vs baseline: 3.7403x; 1.1830x over previous
#include <cuda_runtime.h>
#include <cuda_bf16.h>
#include <math.h>

// Problem constants
#define BB 8
#define KK 1024
#define DD 256
#define HH 8
#define RR 4
#define LL 1028      // RR + KK
#define HD 32
#define IMGF 224.0f
#define MAXPF 1023.0f

typedef unsigned long long u64;
typedef __nv_bfloat16 bf16;

// ---------------- mma.sync helpers (base PTX, compute_103-safe) -------------
__device__ __forceinline__ unsigned smem_u32(const void* p) {
    unsigned a;
    asm("{ .reg .u64 t; cvta.to.shared.u64 t, %1; cvt.u32.u64 %0, t; }"
        : "=r"(a) : "l"(p));
    return a;
}
__device__ __forceinline__ void ldsm4(unsigned* r, unsigned addr) {
    asm volatile("ldmatrix.sync.aligned.m8n8.x4.shared.b16 {%0,%1,%2,%3}, [%4];"
                 : "=r"(r[0]), "=r"(r[1]), "=r"(r[2]), "=r"(r[3]) : "r"(addr));
}
__device__ __forceinline__ void ldsm4t(unsigned* r, unsigned addr) {
    asm volatile("ldmatrix.sync.aligned.m8n8.x4.trans.shared.b16 {%0,%1,%2,%3}, [%4];"
                 : "=r"(r[0]), "=r"(r[1]), "=r"(r[2]), "=r"(r[3]) : "r"(addr));
}
__device__ __forceinline__ void mma16816(float* c, const unsigned* a,
                                         unsigned b0, unsigned b1) {
    asm volatile(
        "mma.sync.aligned.m16n8k16.row.col.f32.bf16.bf16.f32 "
        "{%0,%1,%2,%3}, {%4,%5,%6,%7}, {%8,%9}, {%0,%1,%2,%3};"
        : "+f"(c[0]), "+f"(c[1]), "+f"(c[2]), "+f"(c[3])
        : "r"(a[0]), "r"(a[1]), "r"(a[2]), "r"(a[3]), "r"(b0), "r"(b1));
}
__device__ __forceinline__ unsigned bf16pair(float lo, float hi) {
    unsigned r;
    asm("cvt.rn.bf16x2.f32 %0, %1, %2;" : "=r"(r) : "f"(hi), "f"(lo));
    return r;
}
// cp.async 16B with zero-fill when n < 16
__device__ __forceinline__ void cpa16(unsigned dst, const void* src, unsigned n) {
    asm volatile("cp.async.cg.shared.global [%0], [%1], 16, %2;"
                 :: "r"(dst), "l"(src), "r"(n) : "memory");
}
#define CP_COMMIT() asm volatile("cp.async.commit_group;" ::: "memory")
#define CP_WAIT1()  asm volatile("cp.async.wait_group 1;" ::: "memory")
#define CP_WAIT0()  asm volatile("cp.async.wait_group 0;" ::: "memory")

// fast exp for x <= 0 on fma pipe (no MUFU); rel err ~2.4e-6
__device__ __forceinline__ float expapx(float x) {
    x = fmaxf(x, -87.0f);
    float t = x * 1.44269504088896341f;
    float fn = rintf(t);
    int n = (int)fn;
    float r = t - fn;
    float p = fmaf(0.0013333558f, r, 0.0096181291f);
    p = fmaf(p, r, 0.0555041087f);
    p = fmaf(p, r, 0.2402265069f);
    p = fmaf(p, r, 0.6931471806f);
    p = fmaf(p, r, 1.0f);
    return __int_as_float((n + 127) << 23) * p;
}

// ---------------- scratch (device globals; no allocation allowed) ----------
__device__ float g_xfull[BB * LL * DD];
__device__ int   g_allowed[BB * LL];
__device__ int   g_isctx[BB * KK];
__device__ int   g_kidx[BB * LL];
__device__ int   g_kcnt[BB];
__device__ int   g_qidx[BB * KK];
__device__ float g_qkv_c[BB * LL * 3 * DD];
__device__ float g_qkv_t[BB * LL * 3 * DD];
__device__ float g_tmp2[BB * KK * 2 * DD];     // attn @ [Wo_c; Wo_t]
__device__ float g_x2[BB * KK * DD];
__device__ float g_zerob[2 * DD];              // zero bias (never written)

// bf16 hi/lo activation buffers
__device__ bf16 g_xn_h[BB * LL * DD],   g_xn_l[BB * LL * DD];
__device__ bf16 g_at_h[BB * KK * DD],   g_at_l[BB * KK * DD];
__device__ bf16 g_x2n_h[BB * KK * DD],  g_x2n_l[BB * KK * DD];
__device__ bf16 g_h1_h[BB * KK * 4 * DD], g_h1_l[BB * KK * 4 * DD];

// bf16 hi/lo weight buffers
__device__ bf16 g_wqc_h[3 * DD * DD], g_wqc_l[3 * DD * DD];
__device__ bf16 g_wqt_h[3 * DD * DD], g_wqt_l[3 * DD * DD];
__device__ bf16 g_wo_h[2 * DD * DD],  g_wo_l[2 * DD * DD];
__device__ bf16 g_w1_h[4 * DD * DD],  g_w1_l[4 * DD * DD];
__device__ bf16 g_w2_h[4 * DD * DD],  g_w2_l[4 * DD * DD];

// bf16 K/V banks for attention: [bank(0=ctx,1=tgt)][b][h][l][32]
#define KVIDX(bank,b,h,l) (((size_t)(((bank) * BB + (b)) * HH + (h)) * LL + (l)) * HD)
__device__ bf16 g_kh[2 * BB * HH * LL * HD];
__device__ bf16 g_kl[2 * BB * HH * LL * HD];
__device__ bf16 g_kv[2 * BB * HH * LL * HD];

__device__ __forceinline__ void split_bf16(float v, bf16* hp, bf16* lp) {
    bf16 h = __float2bfloat16(v);
    *hp = h;
    *lp = __float2bfloat16(v - __bfloat162float(h));
}

// ---------------- fused weight conversion (all 6 segments, 1M elems) --------
__global__ __launch_bounds__(256) void convw_all(
    const float* __restrict__ s0, const float* __restrict__ s1,
    const float* __restrict__ s2, const float* __restrict__ s3,
    const float* __restrict__ s4, const float* __restrict__ s5)
{
    int i = blockIdx.x * 256 + threadIdx.x;   // < 1048576
    const int N0 = 3 * DD * DD;
    const int N2 = DD * DD;
    const int N4 = 4 * DD * DD;
    if (i < N0) {
        split_bf16(s0[i], g_wqc_h + i, g_wqc_l + i);
    } else if (i < 2 * N0) {
        int j = i - N0;
        split_bf16(s1[j], g_wqt_h + j, g_wqt_l + j);
    } else if (i < 2 * N0 + N2) {
        int j = i - 2 * N0;
        split_bf16(s2[j], g_wo_h + j, g_wo_l + j);
    } else if (i < 2 * N0 + 2 * N2) {
        int j = i - 2 * N0 - N2;
        split_bf16(s3[j], g_wo_h + N2 + j, g_wo_l + N2 + j);
    } else if (i < 2 * N0 + 2 * N2 + N4) {
        int j = i - 2 * N0 - 2 * N2;
        split_bf16(s4[j], g_w1_h + j, g_w1_l + j);
    } else {
        int j = i - 2 * N0 - 2 * N2 - N4;
        split_bf16(s5[j], g_w2_h + j, g_w2_l + j);
    }
}

// ---------------- K/V bank conversion (fp32 qkv -> bf16 banks) --------------
__global__ __launch_bounds__(256) void kv_conv()
{
    int blk = blockIdx.x;                 // bank*BB*LL + b*LL + l
    int bank = blk / (BB * LL);
    int rem = blk - bank * (BB * LL);
    int b = rem / LL;
    int l = rem - b * LL;
    int d = threadIdx.x;                  // 0..255
    const float* src = (bank == 0) ? g_qkv_c : g_qkv_t;
    size_t base = ((size_t)(b * LL + l)) * (3 * DD);
    int h = d >> 5, dd = d & 31;
    size_t o = KVIDX(bank, b, h, l) + dd;
    split_bf16(src[base + DD + d], g_kh + o, g_kl + o);
    g_kv[o] = __float2bfloat16(src[base + 2 * DD + d]);
}

// ---------------- prep: embed add + rope2d + LN (-> bf16 hi/lo) ------------
__global__ __launch_bounds__(256) void prep_kernel(
    const float* __restrict__ x, const int* __restrict__ coords,
    const int* __restrict__ ctxid, const float* __restrict__ tgt_e,
    const float* __restrict__ ctx_e, const float* __restrict__ regs,
    const float* __restrict__ rope, const float* __restrict__ ng,
    const float* __restrict__ nb)
{
    int blk = blockIdx.x;
    int b = blk / LL;
    int l = blk - b * LL;
    int d = threadIdx.x;

    __shared__ float srow[DD];
    __shared__ float red[2][8];

    float v;
    int ic = 1;
    if (l < RR) {
        v = regs[l * DD + d] + ctx_e[d];
    } else {
        int k = l - RR;
        ic = ctxid[b * KK + k] > 0;
        v = x[((size_t)(b * KK + k)) * DD + d] + (ic ? ctx_e[d] : tgt_e[d]);
    }
    srow[d] = v;
    __syncthreads();

    float rv = v;
    if (l >= RR) {
        int k = l - RR;
        int cy = coords[(size_t)(b * KK + k) * 2 + 0];
        int cx = coords[(size_t)(b * KK + k) * 2 + 1];
        float cny = fminf(fmaxf(((float)cy / IMGF) * MAXPF, 0.f), MAXPF);
        float cnx = fminf(fmaxf(((float)cx / IMGF) * MAXPF, 0.f), MAXPF);
        int yi = (int)cny;
        int xi = (int)cnx;
        int j; const float* cp;
        if (d < 128) { j = d >> 1;         cp = rope + ((size_t)xi * 64 + j) * 2; }
        else         { j = (d - 128) >> 1; cp = rope + ((size_t)yi * 64 + j) * 2; }
        float c = cp[0], s = cp[1];
        float p0 = srow[d & ~1];
        float p1 = srow[d | 1];
        rv = (d & 1) ? (p0 * s + p1 * c) : (p0 * c - p1 * s);
    }

    size_t gi = ((size_t)(b * LL + l)) * DD + d;
    g_xfull[gi] = rv;
    if (d == 0) {
        g_allowed[b * LL + l] = (l < RR) ? 1 : ic;
        if (l >= RR) g_isctx[b * KK + (l - RR)] = ic;
    }

    float s1 = rv, s2 = rv * rv;
    #pragma unroll
    for (int o = 16; o; o >>= 1) {
        s1 += __shfl_down_sync(0xffffffffu, s1, o);
        s2 += __shfl_down_sync(0xffffffffu, s2, o);
    }
    int wid = d >> 5, lane = d & 31;
    if (lane == 0) { red[0][wid] = s1; red[1][wid] = s2; }
    __syncthreads();
    if (d == 0) {
        float t1 = 0.f, t2 = 0.f;
        #pragma unroll
        for (int i = 0; i < 8; i++) { t1 += red[0][i]; t2 += red[1][i]; }
        red[0][0] = t1; red[1][0] = t2;
    }
    __syncthreads();
    float mean = red[0][0] * (1.f / DD);
    float var  = red[1][0] * (1.f / DD) - mean * mean;
    float rstd = rsqrtf(var + 1e-5f);
    float xnv = (rv - mean) * rstd * ng[d] + nb[d];
    split_bf16(xnv, g_xn_h + gi, g_xn_l + gi);
}

// ---------------- compaction -------------------------------------------------
__global__ __launch_bounds__(128) void compact_kernel()
{
    int b = blockIdx.x;
    __shared__ int sa[LL];
    __shared__ int si[KK];
    for (int i = threadIdx.x; i < LL; i += blockDim.x) sa[i] = g_allowed[b * LL + i];
    for (int i = threadIdx.x; i < KK; i += blockDim.x) si[i] = g_isctx[b * KK + i];
    __syncthreads();
    if (threadIdx.x == 0) {
        int c = 0;
        for (int l = 0; l < LL; l++)
            if (sa[l]) g_kidx[b * LL + c++] = l;
        g_kcnt[b] = c;
    } else if (threadIdx.x == 32) {
        int c = 0;
        for (int k = 0; k < KK; k++)
            if (si[k]) g_qidx[b * KK + c++] = k;
        for (int k = 0; k < KK; k++)
            if (!si[k]) g_qidx[b * KK + c++] = k;
    }
}

// ---------------- cp.async double-buffered mma.sync bf16-split GEMM ----------
// D[M,N] = A @ W^T via 3 bf16 phases (hi*hi + lo*hi + hi*lo), fp32 reg accum.
// CTA 128x128, 8 warps (4x2), warp tile 32x64, K-chunk 32, 2-stage pipeline.
// EPI 0: C = D + bias; EPI 1: Chi/Clo = split(gelu(D+bias)); EPI 2: C = D+bias+res.
#define SSTR 40                  // smem row stride in bf16 (80B)
#define MATSZ (128 * SSTR)       // elems per staged matrix
#define GEMM_SMEM (8 * MATSZ * 2)  // bytes: 2 stages x 4 matrices

template <int EPI>
__global__ __launch_bounds__(256) void mma_gemm(
    const bf16* __restrict__ Ahi, const bf16* __restrict__ Alo,
    const bf16* __restrict__ Whi, const bf16* __restrict__ Wlo,
    const float* __restrict__ bias, const float* __restrict__ res,
    float* __restrict__ C, bf16* __restrict__ Chi, bf16* __restrict__ Clo,
    int M, int N, int Kd)
{
    extern __shared__ bf16 dsm[];

    int tid = threadIdx.x;
    int wid = tid >> 5, lane = tid & 31;
    int m0 = blockIdx.y * 128;
    int n0 = blockIdx.x * 128;
    int wm = wid >> 1;
    int wn = wid & 1;

    float acc[2][8][4];
    #pragma unroll
    for (int t = 0; t < 2; t++)
        #pragma unroll
        for (int j = 0; j < 8; j++)
            #pragma unroll
            for (int q = 0; q < 4; q++) acc[t][j][q] = 0.f;

    int srow = tid >> 1;
    int scol = (tid & 1) * 16;
    int agm = m0 + srow;
    bool aok = (agm < M);
    int agmc = aok ? agm : (M - 1);
    unsigned abytes = aok ? 16u : 0u;
    unsigned soff = (srow * SSTR + scol) * 2;   // byte offset within a matrix

    int lrow = lane & 15;
    int lcol8 = (lane >> 4) * 8;

    int NC = Kd >> 5;

    // ---- pipeline: stage chunk g into buffer g&1 ----
    auto stage = [&](int g) {
        int k0 = g << 5;
        unsigned base = smem_u32(dsm) + (unsigned)((g & 1) * 4 * MATSZ * 2) + soff;
        const bf16* ga_h = Ahi + (size_t)agmc * Kd + k0 + scol;
        const bf16* ga_l = Alo + (size_t)agmc * Kd + k0 + scol;
        const bf16* gw_h = Whi + (size_t)(n0 + srow) * Kd + k0 + scol;
        const bf16* gw_l = Wlo + (size_t)(n0 + srow) * Kd + k0 + scol;
        cpa16(base,                  ga_h,     abytes);
        cpa16(base + 16,             ga_h + 8, abytes);
        cpa16(base + 2 * MATSZ,      ga_l,     abytes);
        cpa16(base + 2 * MATSZ + 16, ga_l + 8, abytes);
        cpa16(base + 4 * MATSZ,      gw_h,     16u);
        cpa16(base + 4 * MATSZ + 16, gw_h + 8, 16u);
        cpa16(base + 6 * MATSZ,      gw_l,     16u);
        cpa16(base + 6 * MATSZ + 16, gw_l + 8, 16u);
    };

    stage(0);
    CP_COMMIT();

    for (int g = 0; g < NC; g++) {
        if (g + 1 < NC) { stage(g + 1); CP_COMMIT(); CP_WAIT1(); }
        else            { CP_WAIT0(); }
        __syncthreads();

        bf16* bAh = dsm + (g & 1) * 4 * MATSZ;
        bf16* bAl = bAh + MATSZ;
        bf16* bWh = bAl + MATSZ;
        bf16* bWl = bWh + MATSZ;

        #pragma unroll
        for (int ks = 0; ks < 2; ks++) {
            int ko = ks * 16 + lcol8;
            unsigned ah[2][4], al[2][4], w[4][4];
            #pragma unroll
            for (int t = 0; t < 2; t++) {
                ldsm4(ah[t], smem_u32(bAh + (wm * 32 + t * 16 + lrow) * SSTR + ko));
                ldsm4(al[t], smem_u32(bAl + (wm * 32 + t * 16 + lrow) * SSTR + ko));
            }
            #pragma unroll
            for (int gg = 0; gg < 4; gg++)
                ldsm4(w[gg], smem_u32(bWh + (wn * 64 + gg * 16 + lrow) * SSTR + ko));
            #pragma unroll
            for (int t = 0; t < 2; t++)
                #pragma unroll
                for (int gg = 0; gg < 4; gg++) {
                    mma16816(acc[t][gg * 2],     ah[t], w[gg][0], w[gg][2]);
                    mma16816(acc[t][gg * 2 + 1], ah[t], w[gg][1], w[gg][3]);
                    mma16816(acc[t][gg * 2],     al[t], w[gg][0], w[gg][2]);
                    mma16816(acc[t][gg * 2 + 1], al[t], w[gg][1], w[gg][3]);
                }
            #pragma unroll
            for (int gg = 0; gg < 4; gg++)
                ldsm4(w[gg], smem_u32(bWl + (wn * 64 + gg * 16 + lrow) * SSTR + ko));
            #pragma unroll
            for (int t = 0; t < 2; t++)
                #pragma unroll
                for (int gg = 0; gg < 4; gg++) {
                    mma16816(acc[t][gg * 2],     ah[t], w[gg][0], w[gg][2]);
                    mma16816(acc[t][gg * 2 + 1], ah[t], w[gg][1], w[gg][3]);
                }
        }
        __syncthreads();
    }

    // ---- epilogue from c-fragments ----
    int lr = lane >> 2;
    int lc = (lane & 3) * 2;
    #pragma unroll
    for (int t = 0; t < 2; t++) {
        int r0 = m0 + wm * 32 + t * 16 + lr;
        int r1 = r0 + 8;
        #pragma unroll
        for (int j = 0; j < 8; j++) {
            int gn = n0 + wn * 64 + j * 8 + lc;
            float b0 = bias[gn], b1 = bias[gn + 1];
            float v00 = acc[t][j][0] + b0, v01 = acc[t][j][1] + b1;
            float v10 = acc[t][j][2] + b0, v11 = acc[t][j][3] + b1;
            if (EPI == 1) {
                v00 = 0.5f * v00 * (1.0f + erff(v00 * 0.70710678118654752f));
                v01 = 0.5f * v01 * (1.0f + erff(v01 * 0.70710678118654752f));
                v10 = 0.5f * v10 * (1.0f + erff(v10 * 0.70710678118654752f));
                v11 = 0.5f * v11 * (1.0f + erff(v11 * 0.70710678118654752f));
            }
            if (EPI == 1) {
                if (r0 < M) {
                    size_t i0 = (size_t)r0 * N + gn;
                    bf16 h0, l0, h1, l1;
                    split_bf16(v00, &h0, &l0); split_bf16(v01, &h1, &l1);
                    *(__nv_bfloat162*)&Chi[i0] = __nv_bfloat162(h0, h1);
                    *(__nv_bfloat162*)&Clo[i0] = __nv_bfloat162(l0, l1);
                }
                if (r1 < M) {
                    size_t i1 = (size_t)r1 * N + gn;
                    bf16 h0, l0, h1, l1;
                    split_bf16(v10, &h0, &l0); split_bf16(v11, &h1, &l1);
                    *(__nv_bfloat162*)&Chi[i1] = __nv_bfloat162(h0, h1);
                    *(__nv_bfloat162*)&Clo[i1] = __nv_bfloat162(l0, l1);
                }
            } else {
                if (r0 < M) {
                    size_t i0 = (size_t)r0 * N + gn;
                    if (EPI == 2) { float2 rr = *(const float2*)&res[i0]; v00 += rr.x; v01 += rr.y; }
                    *(float2*)&C[i0] = make_float2(v00, v01);
                }
                if (r1 < M) {
                    size_t i1 = (size_t)r1 * N + gn;
                    if (EPI == 2) { float2 rr = *(const float2*)&res[i1]; v10 += rr.x; v11 += rr.y; }
                    *(float2*)&C[i1] = make_float2(v10, v11);
                }
            }
        }
    }
}

// ---------------- tensor-core flash attention --------------------------------
__global__ __launch_bounds__(128) void attn_mma(
    const float* __restrict__ bqkv_c, const float* __restrict__ bqkv_t)
{
    int qt = blockIdx.x, h = blockIdx.y, b = blockIdx.z;
    int tid = threadIdx.x, wid = tid >> 5, lane = tid & 31;

    __shared__ bf16 sQh[64][SSTR], sQl[64][SSTR];
    __shared__ bf16 sKh[32][SSTR], sKl[32][SSTR], sVt[32][SSTR];
    __shared__ int stok[64], ssel[64];

    if (tid < 64) {
        int tok = g_qidx[b * KK + qt * 64 + tid];
        stok[tid] = tok;
        ssel[tid] = g_isctx[b * KK + tok];
    }
    __syncthreads();

    {
        const float scale = 0.1767766952966369f;
        int row = tid >> 1;
        int dg = (tid & 1) * 16;
        const float* src = ssel[row] ? g_qkv_c : g_qkv_t;
        const float* qp = src + ((size_t)(b * LL + RR + stok[row])) * (3 * DD) + h * HD + dg;
        #pragma unroll
        for (int j = 0; j < 16; j++) {
            float v = qp[j] * scale;
            split_bf16(v, &sQh[row][dg + j], &sQl[row][dg + j]);
        }
    }
    __syncthreads();

    int lrow = lane & 15, lcol8 = (lane >> 4) * 8;
    unsigned qhf[2][4], qlf[2][4];
    #pragma unroll
    for (int kc = 0; kc < 2; kc++) {
        ldsm4(qhf[kc], smem_u32(&sQh[wid * 16 + lrow][kc * 16 + lcol8]));
        ldsm4(qlf[kc], smem_u32(&sQl[wid * 16 + lrow][kc * 16 + lcol8]));
    }

    int uni = (ssel[0] == ssel[63]);
    int cnt = g_kcnt[b];
    int cntp1 = cnt + 1;
    int ntiles = (cntp1 + 31) >> 5;
    int npass = uni ? 1 : 2;
    int kc0 = 2 * (lane & 3);

    for (int pass = 0; pass < npass; pass++) {
        int psel = uni ? ssel[0] : (pass == 0 ? 1 : 0);
        int bank = psel ? 0 : 1;
        const float* bq = psel ? bqkv_c : bqkv_t;
        const bf16* khs = g_kh + KVIDX(bank, b, h, 0);
        const bf16* kls = g_kl + KVIDX(bank, b, h, 0);
        const bf16* vs  = g_kv + KVIDX(bank, b, h, 0);

        float O[4][4];
        #pragma unroll
        for (int nb = 0; nb < 4; nb++)
            #pragma unroll
            for (int q = 0; q < 4; q++) O[nb][q] = 0.f;
        float mrow[2] = {-1e30f, -1e30f};
        float ssum[2] = {0.f, 0.f};

        for (int t = 0; t < ntiles; t++) {
            int g0 = t * 32;
            __syncthreads();
            {
                int slot = tid >> 2, dg = (tid & 3) * 8;
                int gk = g0 + slot;
                if (gk < cnt) {
                    size_t l = (size_t)g_kidx[b * LL + gk] * HD + dg;
                    *(uint4*)&sKh[slot][dg] = *(const uint4*)(khs + l);
                    *(uint4*)&sKl[slot][dg] = *(const uint4*)(kls + l);
                    *(uint4*)&sVt[slot][dg] = *(const uint4*)(vs + l);
                } else if (gk == cnt) {
                    #pragma unroll
                    for (int j = 0; j < 8; j++) {
                        split_bf16(bq[DD + h * HD + dg + j], &sKh[slot][dg + j], &sKl[slot][dg + j]);
                        sVt[slot][dg + j] = __float2bfloat16(bq[2 * DD + h * HD + dg + j]);
                    }
                } else {
                    uint4 z = make_uint4(0u, 0u, 0u, 0u);
                    *(uint4*)&sKh[slot][dg] = z;
                    *(uint4*)&sKl[slot][dg] = z;
                    *(uint4*)&sVt[slot][dg] = z;
                }
            }
            __syncthreads();

            float s[4][4];
            #pragma unroll
            for (int nb = 0; nb < 4; nb++)
                #pragma unroll
                for (int q = 0; q < 4; q++) s[nb][q] = 0.f;
            #pragma unroll
            for (int kc = 0; kc < 2; kc++) {
                int ko = kc * 16 + lcol8;
                unsigned khf[2][4], klf[2][4];
                #pragma unroll
                for (int g = 0; g < 2; g++) {
                    ldsm4(khf[g], smem_u32(&sKh[g * 16 + lrow][ko]));
                    ldsm4(klf[g], smem_u32(&sKl[g * 16 + lrow][ko]));
                }
                #pragma unroll
                for (int g = 0; g < 2; g++) {
                    mma16816(s[g * 2],     qhf[kc], khf[g][0], khf[g][2]);
                    mma16816(s[g * 2 + 1], qhf[kc], khf[g][1], khf[g][3]);
                    mma16816(s[g * 2],     qlf[kc], khf[g][0], khf[g][2]);
                    mma16816(s[g * 2 + 1], qlf[kc], khf[g][1], khf[g][3]);
                    mma16816(s[g * 2],     qhf[kc], klf[g][0], klf[g][2]);
                    mma16816(s[g * 2 + 1], qhf[kc], klf[g][1], klf[g][3]);
                }
            }
            unsigned vf[2][2][4];
            #pragma unroll
            for (int kc = 0; kc < 2; kc++)
                #pragma unroll
                for (int vp = 0; vp < 2; vp++)
                    ldsm4t(vf[kc][vp], smem_u32(&sVt[kc * 16 + lrow][vp * 16 + lcol8]));

            #pragma unroll
            for (int nb = 0; nb < 4; nb++) {
                int c0 = g0 + nb * 8 + kc0;
                if (c0 >= cntp1)     { s[nb][0] = -1e30f; s[nb][2] = -1e30f; }
                if (c0 + 1 >= cntp1) { s[nb][1] = -1e30f; s[nb][3] = -1e30f; }
            }

            #pragma unroll
            for (int th = 0; th < 2; th++) {
                float lm = s[0][2 * th];
                #pragma unroll
                for (int nb = 0; nb < 4; nb++)
                    lm = fmaxf(lm, fmaxf(s[nb][2 * th], s[nb][2 * th + 1]));
                lm = fmaxf(lm, __shfl_xor_sync(0xffffffffu, lm, 1));
                lm = fmaxf(lm, __shfl_xor_sync(0xffffffffu, lm, 2));
                float mn = fmaxf(mrow[th], lm);
                float corr = expapx(mrow[th] - mn);
                mrow[th] = mn;
                float rs = 0.f;
                #pragma unroll
                for (int nb = 0; nb < 4; nb++) {
                    s[nb][2 * th]     = expapx(s[nb][2 * th] - mn);
                    s[nb][2 * th + 1] = expapx(s[nb][2 * th + 1] - mn);
                    rs += s[nb][2 * th] + s[nb][2 * th + 1];
                }
                rs += __shfl_xor_sync(0xffffffffu, rs, 1);
                rs += __shfl_xor_sync(0xffffffffu, rs, 2);
                ssum[th] = ssum[th] * corr + rs;
                #pragma unroll
                for (int nb = 0; nb < 4; nb++) {
                    O[nb][2 * th]     *= corr;
                    O[nb][2 * th + 1] *= corr;
                }
            }

            #pragma unroll
            for (int kc = 0; kc < 2; kc++) {
                unsigned pa[4];
                pa[0] = bf16pair(s[2 * kc][0],     s[2 * kc][1]);
                pa[1] = bf16pair(s[2 * kc][2],     s[2 * kc][3]);
                pa[2] = bf16pair(s[2 * kc + 1][0], s[2 * kc + 1][1]);
                pa[3] = bf16pair(s[2 * kc + 1][2], s[2 * kc + 1][3]);
                mma16816(O[0], pa, vf[kc][0][0], vf[kc][0][1]);
                mma16816(O[1], pa, vf[kc][0][2], vf[kc][0][3]);
                mma16816(O[2], pa, vf[kc][1][0], vf[kc][1][1]);
                mma16816(O[3], pa, vf[kc][1][2], vf[kc][1][3]);
            }
        }

        float inv[2] = {1.f / ssum[0], 1.f / ssum[1]};
        #pragma unroll
        for (int th = 0; th < 2; th++) {
            int rl = wid * 16 + (lane >> 2) + th * 8;
            if (ssel[rl] == psel) {
                size_t base = ((size_t)(b * KK + stok[rl])) * DD + h * HD;
                #pragma unroll
                for (int nb = 0; nb < 4; nb++) {
                    int col = nb * 8 + kc0;
                    float v0 = O[nb][2 * th] * inv[th];
                    float v1 = O[nb][2 * th + 1] * inv[th];
                    bf16 h0, l0, h1, l1;
                    split_bf16(v0, &h0, &l0);
                    split_bf16(v1, &h1, &l1);
                    *(__nv_bfloat162*)&g_at_h[base + col] = __nv_bfloat162(h0, h1);
                    *(__nv_bfloat162*)&g_at_l[base + col] = __nv_bfloat162(l0, l1);
                }
            }
        }
    }
}

// ---------------- residual + LN (reads cat Wo output, selects half) ---------
__global__ __launch_bounds__(256) void resln_kernel(
    const float* __restrict__ gn, const float* __restrict__ bn,
    const float* __restrict__ bo_c, const float* __restrict__ bo_t)
{
    int mrow = blockIdx.x;
    int d = threadIdx.x;
    int b = mrow >> 10, k = mrow & 1023;
    int sel = g_isctx[b * KK + k];

    __shared__ float red[2][8];
    float att = g_tmp2[(size_t)mrow * (2 * DD) + (sel ? 0 : DD) + d]
              + (sel ? bo_c[d] : bo_t[d]);
    float v = g_xfull[((size_t)(b * LL + RR + k)) * DD + d] + att;
    g_x2[(size_t)mrow * DD + d] = v;

    float s1 = v, s2 = v * v;
    #pragma unroll
    for (int o = 16; o; o >>= 1) {
        s1 += __shfl_down_sync(0xffffffffu, s1, o);
        s2 += __shfl_down_sync(0xffffffffu, s2, o);
    }
    int wid = d >> 5, lane = d & 31;
    if (lane == 0) { red[0][wid] = s1; red[1][wid] = s2; }
    __syncthreads();
    if (d == 0) {
        float t1 = 0.f, t2 = 0.f;
        #pragma unroll
        for (int i = 0; i < 8; i++) { t1 += red[0][i]; t2 += red[1][i]; }
        red[0][0] = t1; red[1][0] = t2;
    }
    __syncthreads();
    float mean = red[0][0] * (1.f / DD);
    float var  = red[1][0] * (1.f / DD) - mean * mean;
    float rstd = rsqrtf(var + 1e-5f);
    float xnv = (v - mean) * rstd * gn[d] + bn[d];
    size_t gi = (size_t)mrow * DD + d;
    split_bf16(xnv, g_x2n_h + gi, g_x2n_l + gi);
}

// ---------------- launch ------------------------------------------------------
static void* sym(const void* s)
{
    void* p = nullptr;
    cudaGetSymbolAddress(&p, s);
    return p;
}

extern "C" void kernel_launch(void* const* d_in, const int* in_sizes, int n_in,
                              void* d_out, int out_size)
{
    const float* x          = (const float*)d_in[0];
    const int*   coords     = (const int*)d_in[1];
    const int*   ctxid      = (const int*)d_in[2];
    const float* tgt_e      = (const float*)d_in[3];
    const float* ctx_e      = (const float*)d_in[4];
    const float* regs       = (const float*)d_in[5];
    const float* rope       = (const float*)d_in[6];
    const float* norm_g     = (const float*)d_in[7];
    const float* norm_b     = (const float*)d_in[8];
    const float* ctx_Wqkv   = (const float*)d_in[9];
    const float* ctx_bqkv   = (const float*)d_in[10];
    const float* ctx_Wo     = (const float*)d_in[11];
    const float* ctx_bo     = (const float*)d_in[12];
    const float* tgt_Wqkv   = (const float*)d_in[13];
    const float* tgt_bqkv   = (const float*)d_in[14];
    const float* tgt_Wo     = (const float*)d_in[15];
    const float* tgt_bo     = (const float*)d_in[16];
    const float* mlpn_g     = (const float*)d_in[17];
    const float* mlpn_b     = (const float*)d_in[18];
    const float* mlp_W1     = (const float*)d_in[19];
    const float* mlp_b1     = (const float*)d_in[20];
    const float* mlp_W2     = (const float*)d_in[21];
    const float* mlp_b2     = (const float*)d_in[22];
    float* out = (float*)d_out;

    bf16* wqc_h = (bf16*)sym(g_wqc_h); bf16* wqc_l = (bf16*)sym(g_wqc_l);
    bf16* wqt_h = (bf16*)sym(g_wqt_h); bf16* wqt_l = (bf16*)sym(g_wqt_l);
    bf16* wo_h  = (bf16*)sym(g_wo_h);  bf16* wo_l  = (bf16*)sym(g_wo_l);
    bf16* w1_h  = (bf16*)sym(g_w1_h);  bf16* w1_l  = (bf16*)sym(g_w1_l);
    bf16* w2_h  = (bf16*)sym(g_w2_h);  bf16* w2_l  = (bf16*)sym(g_w2_l);
    bf16* xn_h  = (bf16*)sym(g_xn_h);  bf16* xn_l  = (bf16*)sym(g_xn_l);
    bf16* at_h  = (bf16*)sym(g_at_h);  bf16* at_l  = (bf16*)sym(g_at_l);
    bf16* x2n_h = (bf16*)sym(g_x2n_h); bf16* x2n_l = (bf16*)sym(g_x2n_l);
    bf16* h1_h  = (bf16*)sym(g_h1_h);  bf16* h1_l  = (bf16*)sym(g_h1_l);
    float* p_qc   = (float*)sym(g_qkv_c);
    float* p_qt   = (float*)sym(g_qkv_t);
    float* p_tmp2 = (float*)sym(g_tmp2);
    float* p_x2   = (float*)sym(g_x2);
    float* p_zb   = (float*)sym(g_zerob);

    cudaFuncSetAttribute(mma_gemm<0>, cudaFuncAttributeMaxDynamicSharedMemorySize, GEMM_SMEM);
    cudaFuncSetAttribute(mma_gemm<1>, cudaFuncAttributeMaxDynamicSharedMemorySize, GEMM_SMEM);
    cudaFuncSetAttribute(mma_gemm<2>, cudaFuncAttributeMaxDynamicSharedMemorySize, GEMM_SMEM);

    // 1) embed + rope + LN
    prep_kernel<<<BB * LL, 256>>>(x, coords, ctxid, tgt_e, ctx_e, regs, rope,
                                  norm_g, norm_b);
    // 1b) compaction
    compact_kernel<<<BB, 128>>>();

    // 1c) fused weight conversion
    convw_all<<<4096, 256>>>(ctx_Wqkv, tgt_Wqkv, ctx_Wo, tgt_Wo, mlp_W1, mlp_W2);

    // 2) QKV GEMMs (cp.async pipelined, tensor cores)
    {
        dim3 g(6, (BB * LL + 127) / 128);
        mma_gemm<0><<<g, 256, GEMM_SMEM>>>(xn_h, xn_l, wqc_h, wqc_l, ctx_bqkv,
                                           nullptr, p_qc, nullptr, nullptr,
                                           BB * LL, 3 * DD, DD);
        mma_gemm<0><<<g, 256, GEMM_SMEM>>>(xn_h, xn_l, wqt_h, wqt_l, tgt_bqkv,
                                           nullptr, p_qt, nullptr, nullptr,
                                           BB * LL, 3 * DD, DD);
    }

    // 2b) K/V bf16 bank conversion
    kv_conv<<<2 * BB * LL, 256>>>();

    // 3) tensor-core flash attention
    {
        dim3 g(KK / 64, HH, BB);
        attn_mma<<<g, 128>>>(ctx_bqkv, tgt_bqkv);
    }

    // 4) Wo concatenated GEMM
    {
        dim3 g(4, BB * KK / 128);
        mma_gemm<0><<<g, 256, GEMM_SMEM>>>(at_h, at_l, wo_h, wo_l, p_zb,
                                           nullptr, p_tmp2, nullptr, nullptr,
                                           BB * KK, 2 * DD, DD);
    }

    // 5) residual + LN
    resln_kernel<<<BB * KK, 256>>>(mlpn_g, mlpn_b, ctx_bo, tgt_bo);

    // 6) MLP up + gelu
    {
        dim3 g(8, BB * KK / 128);
        mma_gemm<1><<<g, 256, GEMM_SMEM>>>(x2n_h, x2n_l, w1_h, w1_l, mlp_b1,
                                           nullptr, nullptr, h1_h, h1_l,
                                           BB * KK, 4 * DD, DD);
    }

    // 7) MLP down + residual -> out
    {
        dim3 g(2, BB * KK / 128);
        mma_gemm<2><<<g, 256, GEMM_SMEM>>>(h1_h, h1_l, w2_h, w2_l, mlp_b2,
                                           p_x2, out, nullptr, nullptr,
                                           BB * KK, DD, 4 * DD);
    }
}

// round 15
// speedup vs baseline: 3.8268x; 1.0231x over previous
#include <cuda_runtime.h>
#include <cuda_bf16.h>
#include <cuda_fp16.h>
#include <math.h>

// Problem constants
#define BB 8
#define KK 1024
#define DD 256
#define HH 8
#define RR 4
#define LL 1028      // RR + KK
#define HD 32
#define IMGF 224.0f
#define MAXPF 1023.0f

typedef unsigned long long u64;
typedef __nv_bfloat16 bf16;

// ---------------- mma.sync helpers (base PTX, compute_103-safe) -------------
__device__ __forceinline__ unsigned smem_u32(const void* p) {
    unsigned a;
    asm("{ .reg .u64 t; cvta.to.shared.u64 t, %1; cvt.u32.u64 %0, t; }"
        : "=r"(a) : "l"(p));
    return a;
}
__device__ __forceinline__ void ldsm4(unsigned* r, unsigned addr) {
    asm volatile("ldmatrix.sync.aligned.m8n8.x4.shared.b16 {%0,%1,%2,%3}, [%4];"
                 : "=r"(r[0]), "=r"(r[1]), "=r"(r[2]), "=r"(r[3]) : "r"(addr));
}
__device__ __forceinline__ void ldsm4t(unsigned* r, unsigned addr) {
    asm volatile("ldmatrix.sync.aligned.m8n8.x4.trans.shared.b16 {%0,%1,%2,%3}, [%4];"
                 : "=r"(r[0]), "=r"(r[1]), "=r"(r[2]), "=r"(r[3]) : "r"(addr));
}
__device__ __forceinline__ void mma_bf(float* c, const unsigned* a,
                                       unsigned b0, unsigned b1) {
    asm volatile(
        "mma.sync.aligned.m16n8k16.row.col.f32.bf16.bf16.f32 "
        "{%0,%1,%2,%3}, {%4,%5,%6,%7}, {%8,%9}, {%0,%1,%2,%3};"
        : "+f"(c[0]), "+f"(c[1]), "+f"(c[2]), "+f"(c[3])
        : "r"(a[0]), "r"(a[1]), "r"(a[2]), "r"(a[3]), "r"(b0), "r"(b1));
}
__device__ __forceinline__ void mma_fp(float* c, const unsigned* a,
                                       unsigned b0, unsigned b1) {
    asm volatile(
        "mma.sync.aligned.m16n8k16.row.col.f32.f16.f16.f32 "
        "{%0,%1,%2,%3}, {%4,%5,%6,%7}, {%8,%9}, {%0,%1,%2,%3};"
        : "+f"(c[0]), "+f"(c[1]), "+f"(c[2]), "+f"(c[3])
        : "r"(a[0]), "r"(a[1]), "r"(a[2]), "r"(a[3]), "r"(b0), "r"(b1));
}
__device__ __forceinline__ unsigned bf16pair(float lo, float hi) {
    unsigned r;
    asm("cvt.rn.bf16x2.f32 %0, %1, %2;" : "=r"(r) : "f"(hi), "f"(lo));
    return r;
}
// cp.async 16B with zero-fill when n < 16
__device__ __forceinline__ void cpa16(unsigned dst, const void* src, unsigned n) {
    asm volatile("cp.async.cg.shared.global [%0], [%1], 16, %2;"
                 :: "r"(dst), "l"(src), "r"(n) : "memory");
}
#define CP_COMMIT() asm volatile("cp.async.commit_group;" ::: "memory")
#define CP_WAIT1()  asm volatile("cp.async.wait_group 1;" ::: "memory")
#define CP_WAIT0()  asm volatile("cp.async.wait_group 0;" ::: "memory")

// fast exp for x <= 0 on fma pipe (no MUFU); rel err ~2.4e-6
__device__ __forceinline__ float expapx(float x) {
    x = fmaxf(x, -87.0f);
    float t = x * 1.44269504088896341f;
    float fn = rintf(t);
    int n = (int)fn;
    float r = t - fn;
    float p = fmaf(0.0013333558f, r, 0.0096181291f);
    p = fmaf(p, r, 0.0555041087f);
    p = fmaf(p, r, 0.2402265069f);
    p = fmaf(p, r, 0.6931471806f);
    p = fmaf(p, r, 1.0f);
    return __int_as_float((n + 127) << 23) * p;
}

// ---------------- scratch (device globals; no allocation allowed) ----------
__device__ float g_xfull[BB * LL * DD];
__device__ int   g_allowed[BB * LL];
__device__ int   g_isctx[BB * KK];
__device__ int   g_kidx[BB * LL];
__device__ int   g_kcnt[BB];
__device__ int   g_qidx[BB * KK];
__device__ int   g_qpos[BB * KK];              // token -> sorted position
__device__ int   g_nctx[BB];                   // ctx token count per batch
__device__ float g_qkv2[BB * LL * 6 * DD];     // merged QKV: [ctx 768 | tgt 768]
__device__ float g_bq2[6 * DD];                // merged QKV bias
__device__ float g_tmp2[BB * KK * 2 * DD];     // Wo out (sorted rows, N=256 used)
__device__ float g_x2[BB * KK * DD];
__device__ float g_zerob[2 * DD];              // zero bias (never written)

// bf16 hi/lo activation buffers (QKV path)
__device__ bf16 g_xn_h[BB * LL * DD],   g_xn_l[BB * LL * DD];
__device__ bf16 g_at_h[BB * KK * DD],   g_at_l[BB * KK * DD];   // sorted rows
// fp16 hi/lo activation buffers (MLP path)
__device__ __half g_x2n_h[BB * KK * DD],  g_x2n_l[BB * KK * DD];
__device__ __half g_h1_h[BB * KK * 4 * DD], g_h1_l[BB * KK * 4 * DD];

// weight buffers
__device__ bf16 g_wq_h[6 * DD * DD], g_wq_l[6 * DD * DD];    // [ctx;tgt] qkv
__device__ bf16 g_wo_h[2 * DD * DD], g_wo_l[2 * DD * DD];    // [ctx;tgt] wo
__device__ __half g_w1_h[4 * DD * DD], g_w1_l[4 * DD * DD];
__device__ __half g_w2_h[4 * DD * DD], g_w2_l[4 * DD * DD];

// bf16 K/V banks: [bank(0=ctx,1=tgt)][b][h][l][32]
#define KVIDX(bank,b,h,l) (((size_t)(((bank) * BB + (b)) * HH + (h)) * LL + (l)) * HD)
__device__ bf16 g_kh[2 * BB * HH * LL * HD];
__device__ bf16 g_kl[2 * BB * HH * LL * HD];
__device__ bf16 g_kv[2 * BB * HH * LL * HD];

__device__ __forceinline__ void split_bf16(float v, bf16* hp, bf16* lp) {
    bf16 h = __float2bfloat16(v);
    *hp = h;
    *lp = __float2bfloat16(v - __bfloat162float(h));
}
__device__ __forceinline__ void split_f16(float v, __half* hp, __half* lp) {
    __half h = __float2half_rn(v);
    *hp = h;
    *lp = __float2half_rn(v - __half2float(h));
}

// ---------------- fused weight conversion (1M elems) ------------------------
__global__ __launch_bounds__(256) void convw_all(
    const float* __restrict__ s0, const float* __restrict__ s1,
    const float* __restrict__ s2, const float* __restrict__ s3,
    const float* __restrict__ s4, const float* __restrict__ s5)
{
    int i = blockIdx.x * 256 + threadIdx.x;   // < 1048576
    const int N0 = 3 * DD * DD;
    const int N2 = DD * DD;
    const int N4 = 4 * DD * DD;
    if (i < N0) {
        split_bf16(s0[i], g_wq_h + i, g_wq_l + i);
    } else if (i < 2 * N0) {
        int j = i - N0;
        split_bf16(s1[j], g_wq_h + N0 + j, g_wq_l + N0 + j);
    } else if (i < 2 * N0 + N2) {
        int j = i - 2 * N0;
        split_bf16(s2[j], g_wo_h + j, g_wo_l + j);
    } else if (i < 2 * N0 + 2 * N2) {
        int j = i - 2 * N0 - N2;
        split_bf16(s3[j], g_wo_h + N2 + j, g_wo_l + N2 + j);
    } else if (i < 2 * N0 + 2 * N2 + N4) {
        int j = i - 2 * N0 - 2 * N2;
        split_f16(s4[j], g_w1_h + j, g_w1_l + j);
    } else {
        int j = i - 2 * N0 - 2 * N2 - N4;
        split_f16(s5[j], g_w2_h + j, g_w2_l + j);
    }
}

// merged QKV bias
__global__ __launch_bounds__(256) void biascat(
    const float* __restrict__ bc, const float* __restrict__ bt)
{
    int i = blockIdx.x * 256 + threadIdx.x;   // < 1536
    g_bq2[i] = (i < 3 * DD) ? bc[i] : bt[i - 3 * DD];
}

// ---------------- K/V bank conversion ---------------------------------------
__global__ __launch_bounds__(256) void kv_conv()
{
    int blk = blockIdx.x;                 // bank*BB*LL + b*LL + l
    int bank = blk / (BB * LL);
    int rem = blk - bank * (BB * LL);
    int b = rem / LL;
    int l = rem - b * LL;
    int d = threadIdx.x;
    size_t base = ((size_t)(b * LL + l)) * (6 * DD) + (bank ? 3 * DD : 0);
    int h = d >> 5, dd = d & 31;
    size_t o = KVIDX(bank, b, h, l) + dd;
    split_bf16(g_qkv2[base + DD + d], g_kh + o, g_kl + o);
    g_kv[o] = __float2bfloat16(g_qkv2[base + 2 * DD + d]);
}

// ---------------- prep: embed add + rope2d + LN -----------------------------
__global__ __launch_bounds__(256) void prep_kernel(
    const float* __restrict__ x, const int* __restrict__ coords,
    const int* __restrict__ ctxid, const float* __restrict__ tgt_e,
    const float* __restrict__ ctx_e, const float* __restrict__ regs,
    const float* __restrict__ rope, const float* __restrict__ ng,
    const float* __restrict__ nb)
{
    int blk = blockIdx.x;
    int b = blk / LL;
    int l = blk - b * LL;
    int d = threadIdx.x;

    __shared__ float srow[DD];
    __shared__ float red[2][8];

    float v;
    int ic = 1;
    if (l < RR) {
        v = regs[l * DD + d] + ctx_e[d];
    } else {
        int k = l - RR;
        ic = ctxid[b * KK + k] > 0;
        v = x[((size_t)(b * KK + k)) * DD + d] + (ic ? ctx_e[d] : tgt_e[d]);
    }
    srow[d] = v;
    __syncthreads();

    float rv = v;
    if (l >= RR) {
        int k = l - RR;
        int cy = coords[(size_t)(b * KK + k) * 2 + 0];
        int cx = coords[(size_t)(b * KK + k) * 2 + 1];
        float cny = fminf(fmaxf(((float)cy / IMGF) * MAXPF, 0.f), MAXPF);
        float cnx = fminf(fmaxf(((float)cx / IMGF) * MAXPF, 0.f), MAXPF);
        int yi = (int)cny;
        int xi = (int)cnx;
        int j; const float* cp;
        if (d < 128) { j = d >> 1;         cp = rope + ((size_t)xi * 64 + j) * 2; }
        else         { j = (d - 128) >> 1; cp = rope + ((size_t)yi * 64 + j) * 2; }
        float c = cp[0], s = cp[1];
        float p0 = srow[d & ~1];
        float p1 = srow[d | 1];
        rv = (d & 1) ? (p0 * s + p1 * c) : (p0 * c - p1 * s);
    }

    size_t gi = ((size_t)(b * LL + l)) * DD + d;
    g_xfull[gi] = rv;
    if (d == 0) {
        g_allowed[b * LL + l] = (l < RR) ? 1 : ic;
        if (l >= RR) g_isctx[b * KK + (l - RR)] = ic;
    }

    float s1 = rv, s2 = rv * rv;
    #pragma unroll
    for (int o = 16; o; o >>= 1) {
        s1 += __shfl_down_sync(0xffffffffu, s1, o);
        s2 += __shfl_down_sync(0xffffffffu, s2, o);
    }
    int wid = d >> 5, lane = d & 31;
    if (lane == 0) { red[0][wid] = s1; red[1][wid] = s2; }
    __syncthreads();
    if (d == 0) {
        float t1 = 0.f, t2 = 0.f;
        #pragma unroll
        for (int i = 0; i < 8; i++) { t1 += red[0][i]; t2 += red[1][i]; }
        red[0][0] = t1; red[1][0] = t2;
    }
    __syncthreads();
    float mean = red[0][0] * (1.f / DD);
    float var  = red[1][0] * (1.f / DD) - mean * mean;
    float rstd = rsqrtf(var + 1e-5f);
    float xnv = (rv - mean) * rstd * ng[d] + nb[d];
    split_bf16(xnv, g_xn_h + gi, g_xn_l + gi);
}

// ---------------- compaction (+ qpos inverse, nctx) --------------------------
__global__ __launch_bounds__(128) void compact_kernel()
{
    int b = blockIdx.x;
    __shared__ int sa[LL];
    __shared__ int si[KK];
    for (int i = threadIdx.x; i < LL; i += blockDim.x) sa[i] = g_allowed[b * LL + i];
    for (int i = threadIdx.x; i < KK; i += blockDim.x) si[i] = g_isctx[b * KK + i];
    __syncthreads();
    if (threadIdx.x == 0) {
        int c = 0;
        for (int l = 0; l < LL; l++)
            if (sa[l]) g_kidx[b * LL + c++] = l;
        g_kcnt[b] = c;
    } else if (threadIdx.x == 32) {
        int c = 0;
        for (int k = 0; k < KK; k++)
            if (si[k]) { g_qidx[b * KK + c] = k; g_qpos[b * KK + k] = c; c++; }
        g_nctx[b] = c;
        for (int k = 0; k < KK; k++)
            if (!si[k]) { g_qidx[b * KK + c] = k; g_qpos[b * KK + k] = c; c++; }
    }
}

// ---------------- cp.async pipelined mma.sync split GEMM ---------------------
// FP=0: bf16 3-phase (hi*hi + lo*hi + hi*lo). FP=1: fp16 2-phase (hi*hi + lo*hi).
// WO=1: sorted-row Wo mode — blockIdx.z selects weight bank, tiles filtered.
// EPI 0: C = D + bias; EPI 1: Chi/Clo = split(gelu(D+bias)); EPI 2: C = D+bias+res.
#define SSTR 40
#define MATSZ (128 * SSTR)
#define GEMM_SMEM (8 * MATSZ * 2)

template <int EPI, int FP, int WO>
__global__ __launch_bounds__(256) void mma_gemm(
    const bf16* __restrict__ Ahi, const bf16* __restrict__ Alo,
    const bf16* __restrict__ Whi_, const bf16* __restrict__ Wlo_,
    const float* __restrict__ bias, const float* __restrict__ res,
    float* __restrict__ C, void* __restrict__ Chi, void* __restrict__ Clo,
    int M, int N, int Kd, const int* __restrict__ nctxArr)
{
    extern __shared__ bf16 dsm[];

    int m0 = blockIdx.y * 128;
    int n0 = blockIdx.x * 128;

    const bf16* Whi = Whi_;
    const bf16* Wlo = Wlo_;
    int nct = 0;
    if (WO) {
        int b = m0 >> 10;
        nct = nctxArr[b];
        int lo = m0 & 1023;
        if (blockIdx.z) { if (lo >= nct) return; }
        else { if (lo + 128 <= nct) return; Whi += DD * DD; Wlo += DD * DD; }
    }

    int tid = threadIdx.x;
    int wid = tid >> 5, lane = tid & 31;
    int wm = wid >> 1;
    int wn = wid & 1;

    float acc[2][8][4];
    #pragma unroll
    for (int t = 0; t < 2; t++)
        #pragma unroll
        for (int j = 0; j < 8; j++)
            #pragma unroll
            for (int q = 0; q < 4; q++) acc[t][j][q] = 0.f;

    int srow = tid >> 1;
    int scol = (tid & 1) * 16;
    int agm = m0 + srow;
    bool aok = (agm < M);
    int agmc = aok ? agm : (M - 1);
    unsigned abytes = aok ? 16u : 0u;
    unsigned soff = (srow * SSTR + scol) * 2;

    int lrow = lane & 15;
    int lcol8 = (lane >> 4) * 8;

    int NC = Kd >> 5;

    auto stage = [&](int g) {
        int k0 = g << 5;
        unsigned base = smem_u32(dsm) + (unsigned)((g & 1) * 4 * MATSZ * 2) + soff;
        const bf16* ga_h = Ahi + (size_t)agmc * Kd + k0 + scol;
        const bf16* ga_l = Alo + (size_t)agmc * Kd + k0 + scol;
        const bf16* gw_h = Whi + (size_t)(n0 + srow) * Kd + k0 + scol;
        cpa16(base,                  ga_h,     abytes);
        cpa16(base + 16,             ga_h + 8, abytes);
        cpa16(base + 2 * MATSZ,      ga_l,     abytes);
        cpa16(base + 2 * MATSZ + 16, ga_l + 8, abytes);
        cpa16(base + 4 * MATSZ,      gw_h,     16u);
        cpa16(base + 4 * MATSZ + 16, gw_h + 8, 16u);
        if (!FP) {
            const bf16* gw_l = Wlo + (size_t)(n0 + srow) * Kd + k0 + scol;
            cpa16(base + 6 * MATSZ,      gw_l,     16u);
            cpa16(base + 6 * MATSZ + 16, gw_l + 8, 16u);
        }
    };

    stage(0);
    CP_COMMIT();

    for (int g = 0; g < NC; g++) {
        if (g + 1 < NC) { stage(g + 1); CP_COMMIT(); CP_WAIT1(); }
        else            { CP_WAIT0(); }
        __syncthreads();

        bf16* bAh = dsm + (g & 1) * 4 * MATSZ;
        bf16* bAl = bAh + MATSZ;
        bf16* bWh = bAl + MATSZ;
        bf16* bWl = bWh + MATSZ;

        #pragma unroll
        for (int ks = 0; ks < 2; ks++) {
            int ko = ks * 16 + lcol8;
            unsigned ah[2][4], al[2][4], w[4][4];
            #pragma unroll
            for (int t = 0; t < 2; t++) {
                ldsm4(ah[t], smem_u32(bAh + (wm * 32 + t * 16 + lrow) * SSTR + ko));
                ldsm4(al[t], smem_u32(bAl + (wm * 32 + t * 16 + lrow) * SSTR + ko));
            }
            #pragma unroll
            for (int gg = 0; gg < 4; gg++)
                ldsm4(w[gg], smem_u32(bWh + (wn * 64 + gg * 16 + lrow) * SSTR + ko));
            #pragma unroll
            for (int t = 0; t < 2; t++)
                #pragma unroll
                for (int gg = 0; gg < 4; gg++) {
                    if (FP) {
                        mma_fp(acc[t][gg * 2],     ah[t], w[gg][0], w[gg][2]);
                        mma_fp(acc[t][gg * 2 + 1], ah[t], w[gg][1], w[gg][3]);
                        mma_fp(acc[t][gg * 2],     al[t], w[gg][0], w[gg][2]);
                        mma_fp(acc[t][gg * 2 + 1], al[t], w[gg][1], w[gg][3]);
                    } else {
                        mma_bf(acc[t][gg * 2],     ah[t], w[gg][0], w[gg][2]);
                        mma_bf(acc[t][gg * 2 + 1], ah[t], w[gg][1], w[gg][3]);
                        mma_bf(acc[t][gg * 2],     al[t], w[gg][0], w[gg][2]);
                        mma_bf(acc[t][gg * 2 + 1], al[t], w[gg][1], w[gg][3]);
                    }
                }
            if (!FP) {
                #pragma unroll
                for (int gg = 0; gg < 4; gg++)
                    ldsm4(w[gg], smem_u32(bWl + (wn * 64 + gg * 16 + lrow) * SSTR + ko));
                #pragma unroll
                for (int t = 0; t < 2; t++)
                    #pragma unroll
                    for (int gg = 0; gg < 4; gg++) {
                        mma_bf(acc[t][gg * 2],     ah[t], w[gg][0], w[gg][2]);
                        mma_bf(acc[t][gg * 2 + 1], ah[t], w[gg][1], w[gg][3]);
                    }
            }
        }
        __syncthreads();
    }

    // ---- epilogue ----
    int lr = lane >> 2;
    int lc = (lane & 3) * 2;
    #pragma unroll
    for (int t = 0; t < 2; t++) {
        int r0 = m0 + wm * 32 + t * 16 + lr;
        int r1 = r0 + 8;
        bool w0 = r0 < M, w1 = r1 < M;
        if (WO) {
            int p0 = r0 & 1023, p1 = r1 & 1023;
            if (blockIdx.z) { w0 &= (p0 < nct);  w1 &= (p1 < nct); }
            else            { w0 &= (p0 >= nct); w1 &= (p1 >= nct); }
        }
        #pragma unroll
        for (int j = 0; j < 8; j++) {
            int gn = n0 + wn * 64 + j * 8 + lc;
            float b0 = bias[gn], b1 = bias[gn + 1];
            float v00 = acc[t][j][0] + b0, v01 = acc[t][j][1] + b1;
            float v10 = acc[t][j][2] + b0, v11 = acc[t][j][3] + b1;
            if (EPI == 1) {
                v00 = 0.5f * v00 * (1.0f + erff(v00 * 0.70710678118654752f));
                v01 = 0.5f * v01 * (1.0f + erff(v01 * 0.70710678118654752f));
                v10 = 0.5f * v10 * (1.0f + erff(v10 * 0.70710678118654752f));
                v11 = 0.5f * v11 * (1.0f + erff(v11 * 0.70710678118654752f));
            }
            if (EPI == 1) {
                if (w0) {
                    size_t i0 = (size_t)r0 * N + gn;
                    __half h0, l0, h1, l1;
                    split_f16(v00, &h0, &l0); split_f16(v01, &h1, &l1);
                    *(__half2*)&((__half*)Chi)[i0] = __halves2half2(h0, h1);
                    *(__half2*)&((__half*)Clo)[i0] = __halves2half2(l0, l1);
                }
                if (w1) {
                    size_t i1 = (size_t)r1 * N + gn;
                    __half h0, l0, h1, l1;
                    split_f16(v10, &h0, &l0); split_f16(v11, &h1, &l1);
                    *(__half2*)&((__half*)Chi)[i1] = __halves2half2(h0, h1);
                    *(__half2*)&((__half*)Clo)[i1] = __halves2half2(l0, l1);
                }
            } else {
                if (w0) {
                    size_t i0 = (size_t)r0 * N + gn;
                    if (EPI == 2) { float2 rr = *(const float2*)&res[i0]; v00 += rr.x; v01 += rr.y; }
                    *(float2*)&C[i0] = make_float2(v00, v01);
                }
                if (w1) {
                    size_t i1 = (size_t)r1 * N + gn;
                    if (EPI == 2) { float2 rr = *(const float2*)&res[i1]; v10 += rr.x; v11 += rr.y; }
                    *(float2*)&C[i1] = make_float2(v10, v11);
                }
            }
        }
    }
}

// ---------------- tensor-core flash attention (sorted-row output) ------------
__global__ __launch_bounds__(128) void attn_mma(
    const float* __restrict__ bqkv_c, const float* __restrict__ bqkv_t)
{
    int qt = blockIdx.x, h = blockIdx.y, b = blockIdx.z;
    int tid = threadIdx.x, wid = tid >> 5, lane = tid & 31;

    __shared__ bf16 sQh[64][SSTR], sQl[64][SSTR];
    __shared__ bf16 sKh[32][SSTR], sKl[32][SSTR], sVt[32][SSTR];
    __shared__ int stok[64], ssel[64];

    if (tid < 64) {
        int tok = g_qidx[b * KK + qt * 64 + tid];
        stok[tid] = tok;
        ssel[tid] = g_isctx[b * KK + tok];
    }
    __syncthreads();

    {
        const float scale = 0.1767766952966369f;
        int row = tid >> 1;
        int dg = (tid & 1) * 16;
        const float* qp = g_qkv2 + ((size_t)(b * LL + RR + stok[row])) * (6 * DD)
                        + (ssel[row] ? 0 : 3 * DD) + h * HD + dg;
        #pragma unroll
        for (int j = 0; j < 16; j++) {
            float v = qp[j] * scale;
            split_bf16(v, &sQh[row][dg + j], &sQl[row][dg + j]);
        }
    }
    __syncthreads();

    int lrow = lane & 15, lcol8 = (lane >> 4) * 8;
    unsigned qhf[2][4], qlf[2][4];
    #pragma unroll
    for (int kc = 0; kc < 2; kc++) {
        ldsm4(qhf[kc], smem_u32(&sQh[wid * 16 + lrow][kc * 16 + lcol8]));
        ldsm4(qlf[kc], smem_u32(&sQl[wid * 16 + lrow][kc * 16 + lcol8]));
    }

    int uni = (ssel[0] == ssel[63]);
    int cnt = g_kcnt[b];
    int cntp1 = cnt + 1;
    int ntiles = (cntp1 + 31) >> 5;
    int npass = uni ? 1 : 2;
    int kc0 = 2 * (lane & 3);

    for (int pass = 0; pass < npass; pass++) {
        int psel = uni ? ssel[0] : (pass == 0 ? 1 : 0);
        int bank = psel ? 0 : 1;
        const float* bq = psel ? bqkv_c : bqkv_t;
        const bf16* khs = g_kh + KVIDX(bank, b, h, 0);
        const bf16* kls = g_kl + KVIDX(bank, b, h, 0);
        const bf16* vs  = g_kv + KVIDX(bank, b, h, 0);

        float O[4][4];
        #pragma unroll
        for (int nb = 0; nb < 4; nb++)
            #pragma unroll
            for (int q = 0; q < 4; q++) O[nb][q] = 0.f;
        float mrow[2] = {-1e30f, -1e30f};
        float ssum[2] = {0.f, 0.f};

        for (int t = 0; t < ntiles; t++) {
            int g0 = t * 32;
            __syncthreads();
            {
                int slot = tid >> 2, dg = (tid & 3) * 8;
                int gk = g0 + slot;
                if (gk < cnt) {
                    size_t l = (size_t)g_kidx[b * LL + gk] * HD + dg;
                    *(uint4*)&sKh[slot][dg] = *(const uint4*)(khs + l);
                    *(uint4*)&sKl[slot][dg] = *(const uint4*)(kls + l);
                    *(uint4*)&sVt[slot][dg] = *(const uint4*)(vs + l);
                } else if (gk == cnt) {
                    #pragma unroll
                    for (int j = 0; j < 8; j++) {
                        split_bf16(bq[DD + h * HD + dg + j], &sKh[slot][dg + j], &sKl[slot][dg + j]);
                        sVt[slot][dg + j] = __float2bfloat16(bq[2 * DD + h * HD + dg + j]);
                    }
                } else {
                    uint4 z = make_uint4(0u, 0u, 0u, 0u);
                    *(uint4*)&sKh[slot][dg] = z;
                    *(uint4*)&sKl[slot][dg] = z;
                    *(uint4*)&sVt[slot][dg] = z;
                }
            }
            __syncthreads();

            float s[4][4];
            #pragma unroll
            for (int nb = 0; nb < 4; nb++)
                #pragma unroll
                for (int q = 0; q < 4; q++) s[nb][q] = 0.f;
            #pragma unroll
            for (int kc = 0; kc < 2; kc++) {
                int ko = kc * 16 + lcol8;
                unsigned khf[2][4], klf[2][4];
                #pragma unroll
                for (int g = 0; g < 2; g++) {
                    ldsm4(khf[g], smem_u32(&sKh[g * 16 + lrow][ko]));
                    ldsm4(klf[g], smem_u32(&sKl[g * 16 + lrow][ko]));
                }
                #pragma unroll
                for (int g = 0; g < 2; g++) {
                    mma_bf(s[g * 2],     qhf[kc], khf[g][0], khf[g][2]);
                    mma_bf(s[g * 2 + 1], qhf[kc], khf[g][1], khf[g][3]);
                    mma_bf(s[g * 2],     qlf[kc], khf[g][0], khf[g][2]);
                    mma_bf(s[g * 2 + 1], qlf[kc], khf[g][1], khf[g][3]);
                    mma_bf(s[g * 2],     qhf[kc], klf[g][0], klf[g][2]);
                    mma_bf(s[g * 2 + 1], qhf[kc], klf[g][1], klf[g][3]);
                }
            }
            unsigned vf[2][2][4];
            #pragma unroll
            for (int kc = 0; kc < 2; kc++)
                #pragma unroll
                for (int vp = 0; vp < 2; vp++)
                    ldsm4t(vf[kc][vp], smem_u32(&sVt[kc * 16 + lrow][vp * 16 + lcol8]));

            #pragma unroll
            for (int nb = 0; nb < 4; nb++) {
                int c0 = g0 + nb * 8 + kc0;
                if (c0 >= cntp1)     { s[nb][0] = -1e30f; s[nb][2] = -1e30f; }
                if (c0 + 1 >= cntp1) { s[nb][1] = -1e30f; s[nb][3] = -1e30f; }
            }

            #pragma unroll
            for (int th = 0; th < 2; th++) {
                float lm = s[0][2 * th];
                #pragma unroll
                for (int nb = 0; nb < 4; nb++)
                    lm = fmaxf(lm, fmaxf(s[nb][2 * th], s[nb][2 * th + 1]));
                lm = fmaxf(lm, __shfl_xor_sync(0xffffffffu, lm, 1));
                lm = fmaxf(lm, __shfl_xor_sync(0xffffffffu, lm, 2));
                float mn = fmaxf(mrow[th], lm);
                float corr = expapx(mrow[th] - mn);
                mrow[th] = mn;
                float rs = 0.f;
                #pragma unroll
                for (int nb = 0; nb < 4; nb++) {
                    s[nb][2 * th]     = expapx(s[nb][2 * th] - mn);
                    s[nb][2 * th + 1] = expapx(s[nb][2 * th + 1] - mn);
                    rs += s[nb][2 * th] + s[nb][2 * th + 1];
                }
                rs += __shfl_xor_sync(0xffffffffu, rs, 1);
                rs += __shfl_xor_sync(0xffffffffu, rs, 2);
                ssum[th] = ssum[th] * corr + rs;
                #pragma unroll
                for (int nb = 0; nb < 4; nb++) {
                    O[nb][2 * th]     *= corr;
                    O[nb][2 * th + 1] *= corr;
                }
            }

            #pragma unroll
            for (int kc = 0; kc < 2; kc++) {
                unsigned pa[4];
                pa[0] = bf16pair(s[2 * kc][0],     s[2 * kc][1]);
                pa[1] = bf16pair(s[2 * kc][2],     s[2 * kc][3]);
                pa[2] = bf16pair(s[2 * kc + 1][0], s[2 * kc + 1][1]);
                pa[3] = bf16pair(s[2 * kc + 1][2], s[2 * kc + 1][3]);
                mma_bf(O[0], pa, vf[kc][0][0], vf[kc][0][1]);
                mma_bf(O[1], pa, vf[kc][0][2], vf[kc][0][3]);
                mma_bf(O[2], pa, vf[kc][1][0], vf[kc][1][1]);
                mma_bf(O[3], pa, vf[kc][1][2], vf[kc][1][3]);
            }
        }

        float inv[2] = {1.f / ssum[0], 1.f / ssum[1]};
        #pragma unroll
        for (int th = 0; th < 2; th++) {
            int rl = wid * 16 + (lane >> 2) + th * 8;
            if (ssel[rl] == psel) {
                // write at SORTED position (qt*64 + rl)
                size_t base = ((size_t)(b * KK + qt * 64 + rl)) * DD + h * HD;
                #pragma unroll
                for (int nb = 0; nb < 4; nb++) {
                    int col = nb * 8 + kc0;
                    float v0 = O[nb][2 * th] * inv[th];
                    float v1 = O[nb][2 * th + 1] * inv[th];
                    bf16 h0, l0, h1, l1;
                    split_bf16(v0, &h0, &l0);
                    split_bf16(v1, &h1, &l1);
                    *(__nv_bfloat162*)&g_at_h[base + col] = __nv_bfloat162(h0, h1);
                    *(__nv_bfloat162*)&g_at_l[base + col] = __nv_bfloat162(l0, l1);
                }
            }
        }
    }
}

// ---------------- residual + LN (unsort via qpos) ----------------------------
__global__ __launch_bounds__(256) void resln_kernel(
    const float* __restrict__ gn, const float* __restrict__ bn,
    const float* __restrict__ bo_c, const float* __restrict__ bo_t)
{
    int mrow = blockIdx.x;
    int d = threadIdx.x;
    int b = mrow >> 10, k = mrow & 1023;
    int sel = g_isctx[b * KK + k];
    int pos = g_qpos[b * KK + k];

    __shared__ float red[2][8];
    float att = g_tmp2[((size_t)(b * 1024 + pos)) * DD + d]
              + (sel ? bo_c[d] : bo_t[d]);
    float v = g_xfull[((size_t)(b * LL + RR + k)) * DD + d] + att;
    g_x2[(size_t)mrow * DD + d] = v;

    float s1 = v, s2 = v * v;
    #pragma unroll
    for (int o = 16; o; o >>= 1) {
        s1 += __shfl_down_sync(0xffffffffu, s1, o);
        s2 += __shfl_down_sync(0xffffffffu, s2, o);
    }
    int wid = d >> 5, lane = d & 31;
    if (lane == 0) { red[0][wid] = s1; red[1][wid] = s2; }
    __syncthreads();
    if (d == 0) {
        float t1 = 0.f, t2 = 0.f;
        #pragma unroll
        for (int i = 0; i < 8; i++) { t1 += red[0][i]; t2 += red[1][i]; }
        red[0][0] = t1; red[1][0] = t2;
    }
    __syncthreads();
    float mean = red[0][0] * (1.f / DD);
    float var  = red[1][0] * (1.f / DD) - mean * mean;
    float rstd = rsqrtf(var + 1e-5f);
    float xnv = (v - mean) * rstd * gn[d] + bn[d];
    size_t gi = (size_t)mrow * DD + d;
    split_f16(xnv, g_x2n_h + gi, g_x2n_l + gi);
}

// ---------------- launch ------------------------------------------------------
static void* sym(const void* s)
{
    void* p = nullptr;
    cudaGetSymbolAddress(&p, s);
    return p;
}

extern "C" void kernel_launch(void* const* d_in, const int* in_sizes, int n_in,
                              void* d_out, int out_size)
{
    const float* x          = (const float*)d_in[0];
    const int*   coords     = (const int*)d_in[1];
    const int*   ctxid      = (const int*)d_in[2];
    const float* tgt_e      = (const float*)d_in[3];
    const float* ctx_e      = (const float*)d_in[4];
    const float* regs       = (const float*)d_in[5];
    const float* rope       = (const float*)d_in[6];
    const float* norm_g     = (const float*)d_in[7];
    const float* norm_b     = (const float*)d_in[8];
    const float* ctx_Wqkv   = (const float*)d_in[9];
    const float* ctx_bqkv   = (const float*)d_in[10];
    const float* ctx_Wo     = (const float*)d_in[11];
    const float* ctx_bo     = (const float*)d_in[12];
    const float* tgt_Wqkv   = (const float*)d_in[13];
    const float* tgt_bqkv   = (const float*)d_in[14];
    const float* tgt_Wo     = (const float*)d_in[15];
    const float* tgt_bo     = (const float*)d_in[16];
    const float* mlpn_g     = (const float*)d_in[17];
    const float* mlpn_b     = (const float*)d_in[18];
    const float* mlp_W1     = (const float*)d_in[19];
    const float* mlp_b1     = (const float*)d_in[20];
    const float* mlp_W2     = (const float*)d_in[21];
    const float* mlp_b2     = (const float*)d_in[22];
    float* out = (float*)d_out;

    bf16* wq_h  = (bf16*)sym(g_wq_h);  bf16* wq_l  = (bf16*)sym(g_wq_l);
    bf16* wo_h  = (bf16*)sym(g_wo_h);  bf16* wo_l  = (bf16*)sym(g_wo_l);
    __half* w1_h = (__half*)sym(g_w1_h); __half* w1_l = (__half*)sym(g_w1_l);
    __half* w2_h = (__half*)sym(g_w2_h); __half* w2_l = (__half*)sym(g_w2_l);
    bf16* xn_h  = (bf16*)sym(g_xn_h);  bf16* xn_l  = (bf16*)sym(g_xn_l);
    bf16* at_h  = (bf16*)sym(g_at_h);  bf16* at_l  = (bf16*)sym(g_at_l);
    __half* x2n_h = (__half*)sym(g_x2n_h); __half* x2n_l = (__half*)sym(g_x2n_l);
    __half* h1_h  = (__half*)sym(g_h1_h);  __half* h1_l  = (__half*)sym(g_h1_l);
    float* p_qkv2 = (float*)sym(g_qkv2);
    float* p_bq2  = (float*)sym(g_bq2);
    float* p_tmp2 = (float*)sym(g_tmp2);
    float* p_x2   = (float*)sym(g_x2);
    float* p_zb   = (float*)sym(g_zerob);
    int*   p_nctx = (int*)sym(g_nctx);

    cudaFuncSetAttribute(mma_gemm<0,0,0>, cudaFuncAttributeMaxDynamicSharedMemorySize, GEMM_SMEM);
    cudaFuncSetAttribute(mma_gemm<0,0,1>, cudaFuncAttributeMaxDynamicSharedMemorySize, GEMM_SMEM);
    cudaFuncSetAttribute(mma_gemm<1,1,0>, cudaFuncAttributeMaxDynamicSharedMemorySize, GEMM_SMEM);
    cudaFuncSetAttribute(mma_gemm<2,1,0>, cudaFuncAttributeMaxDynamicSharedMemorySize, GEMM_SMEM);

    // 1) embed + rope + LN
    prep_kernel<<<BB * LL, 256>>>(x, coords, ctxid, tgt_e, ctx_e, regs, rope,
                                  norm_g, norm_b);
    // 1b) compaction (+ qpos, nctx)
    compact_kernel<<<BB, 128>>>();

    // 1c) weight conversion + merged QKV bias
    convw_all<<<4096, 256>>>(ctx_Wqkv, tgt_Wqkv, ctx_Wo, tgt_Wo, mlp_W1, mlp_W2);
    biascat<<<6, 256>>>(ctx_bqkv, tgt_bqkv);

    // 2) merged QKV GEMM (N=1536)
    {
        dim3 g(12, (BB * LL + 127) / 128);
        mma_gemm<0,0,0><<<g, 256, GEMM_SMEM>>>(xn_h, xn_l, wq_h, wq_l, p_bq2,
                                               nullptr, p_qkv2, nullptr, nullptr,
                                               BB * LL, 6 * DD, DD, nullptr);
    }

    // 2b) K/V bf16 bank conversion
    kv_conv<<<2 * BB * LL, 256>>>();

    // 3) tensor-core flash attention (sorted-row output)
    {
        dim3 g(KK / 64, HH, BB);
        attn_mma<<<g, 128>>>(ctx_bqkv, tgt_bqkv);
    }

    // 4) Wo GEMM on sorted rows, per-tile weight bank (z = sel pass)
    {
        dim3 g(2, BB * KK / 128, 2);
        mma_gemm<0,0,1><<<g, 256, GEMM_SMEM>>>(at_h, at_l, wo_h, wo_l, p_zb,
                                               nullptr, p_tmp2, nullptr, nullptr,
                                               BB * KK, DD, DD, p_nctx);
    }

    // 5) residual + LN (unsort) -> fp16 hi/lo
    resln_kernel<<<BB * KK, 256>>>(mlpn_g, mlpn_b, ctx_bo, tgt_bo);

    // 6) MLP up + gelu (fp16 2-phase)
    {
        dim3 g(8, BB * KK / 128);
        mma_gemm<1,1,0><<<g, 256, GEMM_SMEM>>>((bf16*)x2n_h, (bf16*)x2n_l,
                                               (bf16*)w1_h, (bf16*)w1_l, mlp_b1,
                                               nullptr, nullptr, h1_h, h1_l,
                                               BB * KK, 4 * DD, DD, nullptr);
    }

    // 7) MLP down + residual -> out (fp16 2-phase)
    {
        dim3 g(2, BB * KK / 128);
        mma_gemm<2,1,0><<<g, 256, GEMM_SMEM>>>((bf16*)h1_h, (bf16*)h1_l,
                                               (bf16*)w2_h, (bf16*)w2_l, mlp_b2,
                                               p_x2, out, nullptr, nullptr,
                                               BB * KK, DD, 4 * DD, nullptr);
    }
}

// round 16
// speedup vs baseline: 4.3902x; 1.1472x over previous
#include <cuda_runtime.h>
#include <cuda_bf16.h>
#include <cuda_fp16.h>
#include <math.h>

// Problem constants
#define BB 8
#define KK 1024
#define DD 256
#define HH 8
#define RR 4
#define LL 1028      // RR + KK
#define HD 32
#define IMGF 224.0f
#define MAXPF 1023.0f

typedef unsigned long long u64;
typedef __nv_bfloat16 bf16;

// ---------------- mma.sync helpers (base PTX, compute_103-safe) -------------
__device__ __forceinline__ unsigned smem_u32(const void* p) {
    unsigned a;
    asm("{ .reg .u64 t; cvta.to.shared.u64 t, %1; cvt.u32.u64 %0, t; }"
        : "=r"(a) : "l"(p));
    return a;
}
__device__ __forceinline__ void ldsm4(unsigned* r, unsigned addr) {
    asm volatile("ldmatrix.sync.aligned.m8n8.x4.shared.b16 {%0,%1,%2,%3}, [%4];"
                 : "=r"(r[0]), "=r"(r[1]), "=r"(r[2]), "=r"(r[3]) : "r"(addr));
}
__device__ __forceinline__ void ldsm4t(unsigned* r, unsigned addr) {
    asm volatile("ldmatrix.sync.aligned.m8n8.x4.trans.shared.b16 {%0,%1,%2,%3}, [%4];"
                 : "=r"(r[0]), "=r"(r[1]), "=r"(r[2]), "=r"(r[3]) : "r"(addr));
}
__device__ __forceinline__ void mma_bf(float* c, const unsigned* a,
                                       unsigned b0, unsigned b1) {
    asm volatile(
        "mma.sync.aligned.m16n8k16.row.col.f32.bf16.bf16.f32 "
        "{%0,%1,%2,%3}, {%4,%5,%6,%7}, {%8,%9}, {%0,%1,%2,%3};"
        : "+f"(c[0]), "+f"(c[1]), "+f"(c[2]), "+f"(c[3])
        : "r"(a[0]), "r"(a[1]), "r"(a[2]), "r"(a[3]), "r"(b0), "r"(b1));
}
__device__ __forceinline__ void mma_fp(float* c, const unsigned* a,
                                       unsigned b0, unsigned b1) {
    asm volatile(
        "mma.sync.aligned.m16n8k16.row.col.f32.f16.f16.f32 "
        "{%0,%1,%2,%3}, {%4,%5,%6,%7}, {%8,%9}, {%0,%1,%2,%3};"
        : "+f"(c[0]), "+f"(c[1]), "+f"(c[2]), "+f"(c[3])
        : "r"(a[0]), "r"(a[1]), "r"(a[2]), "r"(a[3]), "r"(b0), "r"(b1));
}
__device__ __forceinline__ unsigned bf16pair(float lo, float hi) {
    unsigned r;
    asm("cvt.rn.bf16x2.f32 %0, %1, %2;" : "=r"(r) : "f"(hi), "f"(lo));
    return r;
}
// cp.async 16B with zero-fill when n < 16
__device__ __forceinline__ void cpa16(unsigned dst, const void* src, unsigned n) {
    asm volatile("cp.async.cg.shared.global [%0], [%1], 16, %2;"
                 :: "r"(dst), "l"(src), "r"(n) : "memory");
}
#define CP_COMMIT() asm volatile("cp.async.commit_group;" ::: "memory")
#define CP_WAIT1()  asm volatile("cp.async.wait_group 1;" ::: "memory")
#define CP_WAIT0()  asm volatile("cp.async.wait_group 0;" ::: "memory")

// fast exp for x <= 0 on fma pipe (no MUFU); rel err ~2.4e-6
__device__ __forceinline__ float expapx(float x) {
    x = fmaxf(x, -87.0f);
    float t = x * 1.44269504088896341f;
    float fn = rintf(t);
    int n = (int)fn;
    float r = t - fn;
    float p = fmaf(0.0013333558f, r, 0.0096181291f);
    p = fmaf(p, r, 0.0555041087f);
    p = fmaf(p, r, 0.2402265069f);
    p = fmaf(p, r, 0.6931471806f);
    p = fmaf(p, r, 1.0f);
    return __int_as_float((n + 127) << 23) * p;
}

// ---------------- scratch (device globals; no allocation allowed) ----------
__device__ float g_xfull[BB * LL * DD];
__device__ int   g_allowed[BB * LL];
__device__ int   g_isctx[BB * KK];
__device__ int   g_kidx[BB * LL];
__device__ int   g_kcnt[BB];
__device__ int   g_qidx[BB * KK];
__device__ int   g_qpos[BB * KK];              // token -> sorted position
__device__ int   g_nctx[BB];                   // ctx token count per batch
__device__ float g_bq2[6 * DD];                // merged QKV bias
__device__ float g_tmp2[BB * KK * 2 * DD];     // Wo out (sorted rows, N=256 used)
__device__ float g_x2[BB * KK * DD];
__device__ float g_zerob[2 * DD];              // zero bias (never written)

// bf16 hi/lo activation buffers
__device__ bf16 g_xn_h[BB * LL * DD],   g_xn_l[BB * LL * DD];
__device__ bf16 g_at_h[BB * KK * DD],   g_at_l[BB * KK * DD];   // sorted rows
__device__ __half g_x2n_h[BB * KK * DD],  g_x2n_l[BB * KK * DD];
__device__ __half g_h1_h[BB * KK * 4 * DD], g_h1_l[BB * KK * 4 * DD];

// weight buffers
__device__ bf16 g_wq_h[6 * DD * DD], g_wq_l[6 * DD * DD];    // [ctx;tgt] qkv
__device__ bf16 g_wo_h[2 * DD * DD], g_wo_l[2 * DD * DD];    // [ctx;tgt] wo
__device__ __half g_w1_h[4 * DD * DD], g_w1_l[4 * DD * DD];
__device__ __half g_w2_h[4 * DD * DD], g_w2_l[4 * DD * DD];

// bf16 Q/K/V banks: [bank(0=ctx,1=tgt)][b][...][l][...]
#define KVIDX(bank,b,h,l) (((size_t)(((bank) * BB + (b)) * HH + (h)) * LL + (l)) * HD)
#define QIDX(bank,b,l)    (((size_t)(((bank) * BB + (b)) * LL + (l))) * DD)
__device__ bf16 g_kh[2 * BB * HH * LL * HD];
__device__ bf16 g_kl[2 * BB * HH * LL * HD];
__device__ bf16 g_kv[2 * BB * HH * LL * HD];
__device__ bf16 g_qh[2 * BB * LL * DD];
__device__ bf16 g_ql[2 * BB * LL * DD];

__device__ __forceinline__ void split_bf16(float v, bf16* hp, bf16* lp) {
    bf16 h = __float2bfloat16(v);
    *hp = h;
    *lp = __float2bfloat16(v - __bfloat162float(h));
}
__device__ __forceinline__ void split_f16(float v, __half* hp, __half* lp) {
    __half h = __float2half_rn(v);
    *hp = h;
    *lp = __float2half_rn(v - __half2float(h));
}

// ---------------- fused weight conversion + QKV bias concat ------------------
__global__ __launch_bounds__(256) void convw_all(
    const float* __restrict__ s0, const float* __restrict__ s1,
    const float* __restrict__ s2, const float* __restrict__ s3,
    const float* __restrict__ s4, const float* __restrict__ s5,
    const float* __restrict__ bc, const float* __restrict__ bt)
{
    int i = blockIdx.x * 256 + threadIdx.x;
    const int N0 = 3 * DD * DD;
    const int N2 = DD * DD;
    const int N4 = 4 * DD * DD;
    const int TOT = 2 * N0 + 2 * N2 + 2 * N4;   // 1048576
    if (i < N0) {
        split_bf16(s0[i], g_wq_h + i, g_wq_l + i);
    } else if (i < 2 * N0) {
        int j = i - N0;
        split_bf16(s1[j], g_wq_h + N0 + j, g_wq_l + N0 + j);
    } else if (i < 2 * N0 + N2) {
        int j = i - 2 * N0;
        split_bf16(s2[j], g_wo_h + j, g_wo_l + j);
    } else if (i < 2 * N0 + 2 * N2) {
        int j = i - 2 * N0 - N2;
        split_bf16(s3[j], g_wo_h + N2 + j, g_wo_l + N2 + j);
    } else if (i < 2 * N0 + 2 * N2 + N4) {
        int j = i - 2 * N0 - 2 * N2;
        split_f16(s4[j], g_w1_h + j, g_w1_l + j);
    } else if (i < TOT) {
        int j = i - 2 * N0 - 2 * N2 - N4;
        split_f16(s5[j], g_w2_h + j, g_w2_l + j);
    } else if (i < TOT + 6 * DD) {
        int j = i - TOT;
        g_bq2[j] = (j < 3 * DD) ? bc[j] : bt[j - 3 * DD];
    }
}

// ---------------- prep: embed add + rope2d + LN -----------------------------
__global__ __launch_bounds__(256) void prep_kernel(
    const float* __restrict__ x, const int* __restrict__ coords,
    const int* __restrict__ ctxid, const float* __restrict__ tgt_e,
    const float* __restrict__ ctx_e, const float* __restrict__ regs,
    const float* __restrict__ rope, const float* __restrict__ ng,
    const float* __restrict__ nb)
{
    int blk = blockIdx.x;
    int b = blk / LL;
    int l = blk - b * LL;
    int d = threadIdx.x;

    __shared__ float srow[DD];
    __shared__ float red[2][8];

    float v;
    int ic = 1;
    if (l < RR) {
        v = regs[l * DD + d] + ctx_e[d];
    } else {
        int k = l - RR;
        ic = ctxid[b * KK + k] > 0;
        v = x[((size_t)(b * KK + k)) * DD + d] + (ic ? ctx_e[d] : tgt_e[d]);
    }
    srow[d] = v;
    __syncthreads();

    float rv = v;
    if (l >= RR) {
        int k = l - RR;
        int cy = coords[(size_t)(b * KK + k) * 2 + 0];
        int cx = coords[(size_t)(b * KK + k) * 2 + 1];
        float cny = fminf(fmaxf(((float)cy / IMGF) * MAXPF, 0.f), MAXPF);
        float cnx = fminf(fmaxf(((float)cx / IMGF) * MAXPF, 0.f), MAXPF);
        int yi = (int)cny;
        int xi = (int)cnx;
        int j; const float* cp;
        if (d < 128) { j = d >> 1;         cp = rope + ((size_t)xi * 64 + j) * 2; }
        else         { j = (d - 128) >> 1; cp = rope + ((size_t)yi * 64 + j) * 2; }
        float c = cp[0], s = cp[1];
        float p0 = srow[d & ~1];
        float p1 = srow[d | 1];
        rv = (d & 1) ? (p0 * s + p1 * c) : (p0 * c - p1 * s);
    }

    size_t gi = ((size_t)(b * LL + l)) * DD + d;
    g_xfull[gi] = rv;
    if (d == 0) {
        g_allowed[b * LL + l] = (l < RR) ? 1 : ic;
        if (l >= RR) g_isctx[b * KK + (l - RR)] = ic;
    }

    float s1 = rv, s2 = rv * rv;
    #pragma unroll
    for (int o = 16; o; o >>= 1) {
        s1 += __shfl_down_sync(0xffffffffu, s1, o);
        s2 += __shfl_down_sync(0xffffffffu, s2, o);
    }
    int wid = d >> 5, lane = d & 31;
    if (lane == 0) { red[0][wid] = s1; red[1][wid] = s2; }
    __syncthreads();
    if (d == 0) {
        float t1 = 0.f, t2 = 0.f;
        #pragma unroll
        for (int i = 0; i < 8; i++) { t1 += red[0][i]; t2 += red[1][i]; }
        red[0][0] = t1; red[1][0] = t2;
    }
    __syncthreads();
    float mean = red[0][0] * (1.f / DD);
    float var  = red[1][0] * (1.f / DD) - mean * mean;
    float rstd = rsqrtf(var + 1e-5f);
    float xnv = (rv - mean) * rstd * ng[d] + nb[d];
    split_bf16(xnv, g_xn_h + gi, g_xn_l + gi);
}

// ---------------- compaction (parallel scans) --------------------------------
__device__ __forceinline__ int excl_scan128(int v, int* sb, int t, int* total) {
    sb[t] = v;
    __syncthreads();
    #pragma unroll
    for (int d = 1; d < 128; d <<= 1) {
        int x = (t >= d) ? sb[t - d] : 0;
        __syncthreads();
        sb[t] += x;
        __syncthreads();
    }
    int incl = sb[t];
    *total = sb[127];
    __syncthreads();
    return incl - v;
}

__global__ __launch_bounds__(128) void compact_kernel()
{
    int b = blockIdx.x, t = threadIdx.x;
    __shared__ int sb[128];

    // allowed-key list over LL items, chunk 9 (order-preserving)
    int a[9]; int cnt = 0;
    #pragma unroll
    for (int i = 0; i < 9; i++) {
        int idx = t * 9 + i;
        a[i] = (idx < LL) ? g_allowed[b * LL + idx] : 0;
        cnt += a[i];
    }
    int tot;
    int off = excl_scan128(cnt, sb, t, &tot);
    #pragma unroll
    for (int i = 0; i < 9; i++) {
        int idx = t * 9 + i;
        if (idx < LL && a[i]) g_kidx[b * LL + off++] = idx;
    }
    if (t == 0) g_kcnt[b] = tot;

    // ctx-first query order over KK items, chunk 8
    int s[8]; int cc = 0;
    #pragma unroll
    for (int i = 0; i < 8; i++) {
        s[i] = g_isctx[b * KK + t * 8 + i];
        cc += s[i];
    }
    int nct;
    int offc = excl_scan128(cc, sb, t, &nct);
    int offt = t * 8 - offc;
    #pragma unroll
    for (int i = 0; i < 8; i++) {
        int idx = t * 8 + i;
        int pos = s[i] ? (offc++) : (nct + offt++);
        g_qidx[b * KK + pos] = idx;
        g_qpos[b * KK + idx] = pos;
    }
    if (t == 0) g_nctx[b] = nct;
}

// ---------------- cp.async pipelined mma.sync split GEMM ---------------------
// FP=0: bf16 3-phase. FP=1: fp16 2-phase.
// WO=1: sorted-row Wo mode. EPI 0: C=D+bias; 1: fp16 split(gelu); 2: +res;
// EPI 3: QKV scatter epilogue (Q scaled+split to g_qh/g_ql; K/V to banks).
#define SSTR 40
#define MATSZ (128 * SSTR)
#define GEMM_SMEM (8 * MATSZ * 2)

template <int EPI, int FP, int WO>
__global__ __launch_bounds__(256) void mma_gemm(
    const bf16* __restrict__ Ahi, const bf16* __restrict__ Alo,
    const bf16* __restrict__ Whi_, const bf16* __restrict__ Wlo_,
    const float* __restrict__ bias, const float* __restrict__ res,
    float* __restrict__ C, void* __restrict__ Chi, void* __restrict__ Clo,
    int M, int N, int Kd, const int* __restrict__ nctxArr)
{
    extern __shared__ bf16 dsm[];

    int m0 = blockIdx.y * 128;
    int n0 = blockIdx.x * 128;

    const bf16* Whi = Whi_;
    const bf16* Wlo = Wlo_;
    int nct = 0;
    if (WO) {
        int b = m0 >> 10;
        nct = nctxArr[b];
        int lo = m0 & 1023;
        if (blockIdx.z) { if (lo >= nct) return; }
        else { if (lo + 128 <= nct) return; Whi += DD * DD; Wlo += DD * DD; }
    }

    int tid = threadIdx.x;
    int wid = tid >> 5, lane = tid & 31;
    int wm = wid >> 1;
    int wn = wid & 1;

    float acc[2][8][4];
    #pragma unroll
    for (int t = 0; t < 2; t++)
        #pragma unroll
        for (int j = 0; j < 8; j++)
            #pragma unroll
            for (int q = 0; q < 4; q++) acc[t][j][q] = 0.f;

    int srow = tid >> 1;
    int scol = (tid & 1) * 16;
    int agm = m0 + srow;
    bool aok = (agm < M);
    int agmc = aok ? agm : (M - 1);
    unsigned abytes = aok ? 16u : 0u;
    unsigned soff = (srow * SSTR + scol) * 2;

    int lrow = lane & 15;
    int lcol8 = (lane >> 4) * 8;

    int NC = Kd >> 5;

    auto stage = [&](int g) {
        int k0 = g << 5;
        unsigned base = smem_u32(dsm) + (unsigned)((g & 1) * 4 * MATSZ * 2) + soff;
        const bf16* ga_h = Ahi + (size_t)agmc * Kd + k0 + scol;
        const bf16* ga_l = Alo + (size_t)agmc * Kd + k0 + scol;
        const bf16* gw_h = Whi + (size_t)(n0 + srow) * Kd + k0 + scol;
        cpa16(base,                  ga_h,     abytes);
        cpa16(base + 16,             ga_h + 8, abytes);
        cpa16(base + 2 * MATSZ,      ga_l,     abytes);
        cpa16(base + 2 * MATSZ + 16, ga_l + 8, abytes);
        cpa16(base + 4 * MATSZ,      gw_h,     16u);
        cpa16(base + 4 * MATSZ + 16, gw_h + 8, 16u);
        if (!FP) {
            const bf16* gw_l = Wlo + (size_t)(n0 + srow) * Kd + k0 + scol;
            cpa16(base + 6 * MATSZ,      gw_l,     16u);
            cpa16(base + 6 * MATSZ + 16, gw_l + 8, 16u);
        }
    };

    stage(0);
    CP_COMMIT();

    for (int g = 0; g < NC; g++) {
        if (g + 1 < NC) { stage(g + 1); CP_COMMIT(); CP_WAIT1(); }
        else            { CP_WAIT0(); }
        __syncthreads();

        bf16* bAh = dsm + (g & 1) * 4 * MATSZ;
        bf16* bAl = bAh + MATSZ;
        bf16* bWh = bAl + MATSZ;
        bf16* bWl = bWh + MATSZ;

        #pragma unroll
        for (int ks = 0; ks < 2; ks++) {
            int ko = ks * 16 + lcol8;
            unsigned ah[2][4], al[2][4], w[4][4];
            #pragma unroll
            for (int t = 0; t < 2; t++) {
                ldsm4(ah[t], smem_u32(bAh + (wm * 32 + t * 16 + lrow) * SSTR + ko));
                ldsm4(al[t], smem_u32(bAl + (wm * 32 + t * 16 + lrow) * SSTR + ko));
            }
            #pragma unroll
            for (int gg = 0; gg < 4; gg++)
                ldsm4(w[gg], smem_u32(bWh + (wn * 64 + gg * 16 + lrow) * SSTR + ko));
            #pragma unroll
            for (int t = 0; t < 2; t++)
                #pragma unroll
                for (int gg = 0; gg < 4; gg++) {
                    if (FP) {
                        mma_fp(acc[t][gg * 2],     ah[t], w[gg][0], w[gg][2]);
                        mma_fp(acc[t][gg * 2 + 1], ah[t], w[gg][1], w[gg][3]);
                        mma_fp(acc[t][gg * 2],     al[t], w[gg][0], w[gg][2]);
                        mma_fp(acc[t][gg * 2 + 1], al[t], w[gg][1], w[gg][3]);
                    } else {
                        mma_bf(acc[t][gg * 2],     ah[t], w[gg][0], w[gg][2]);
                        mma_bf(acc[t][gg * 2 + 1], ah[t], w[gg][1], w[gg][3]);
                        mma_bf(acc[t][gg * 2],     al[t], w[gg][0], w[gg][2]);
                        mma_bf(acc[t][gg * 2 + 1], al[t], w[gg][1], w[gg][3]);
                    }
                }
            if (!FP) {
                #pragma unroll
                for (int gg = 0; gg < 4; gg++)
                    ldsm4(w[gg], smem_u32(bWl + (wn * 64 + gg * 16 + lrow) * SSTR + ko));
                #pragma unroll
                for (int t = 0; t < 2; t++)
                    #pragma unroll
                    for (int gg = 0; gg < 4; gg++) {
                        mma_bf(acc[t][gg * 2],     ah[t], w[gg][0], w[gg][2]);
                        mma_bf(acc[t][gg * 2 + 1], ah[t], w[gg][1], w[gg][3]);
                    }
            }
        }
        __syncthreads();
    }

    // ---- epilogue ----
    int lr = lane >> 2;
    int lc = (lane & 3) * 2;

    if (EPI == 3) {
        // QKV scatter: cols [0,768)=ctx bank, [768,1536)=tgt bank.
        // Within bank: [0,256)=Q (scale+split), [256,512)=K, [512,768)=V.
        const float qs = 0.1767766952966369f;
        #pragma unroll
        for (int t = 0; t < 2; t++) {
            #pragma unroll
            for (int rI = 0; rI < 2; rI++) {
                int r = m0 + wm * 32 + t * 16 + lr + rI * 8;
                if (r >= M) continue;
                int bb = r / LL, ll = r - bb * LL;
                #pragma unroll
                for (int j = 0; j < 8; j++) {
                    int gn = n0 + wn * 64 + j * 8 + lc;
                    float v0 = acc[t][j][rI * 2 + 0] + bias[gn];
                    float v1 = acc[t][j][rI * 2 + 1] + bias[gn + 1];
                    int bank = gn >= 768;
                    int c = gn - (bank ? 768 : 0);
                    if (c < 256) {
                        bf16 h0, l0, h1, l1;
                        split_bf16(v0 * qs, &h0, &l0);
                        split_bf16(v1 * qs, &h1, &l1);
                        size_t o = QIDX(bank, bb, ll) + c;
                        *(__nv_bfloat162*)&g_qh[o] = __nv_bfloat162(h0, h1);
                        *(__nv_bfloat162*)&g_ql[o] = __nv_bfloat162(l0, l1);
                    } else if (c < 512) {
                        int h = (c - 256) >> 5, dd = (c - 256) & 31;
                        size_t o = KVIDX(bank, bb, h, ll) + dd;
                        bf16 h0, l0, h1, l1;
                        split_bf16(v0, &h0, &l0);
                        split_bf16(v1, &h1, &l1);
                        *(__nv_bfloat162*)&g_kh[o] = __nv_bfloat162(h0, h1);
                        *(__nv_bfloat162*)&g_kl[o] = __nv_bfloat162(l0, l1);
                    } else {
                        int h = (c - 512) >> 5, dd = (c - 512) & 31;
                        size_t o = KVIDX(bank, bb, h, ll) + dd;
                        *(__nv_bfloat162*)&g_kv[o] =
                            __nv_bfloat162(__float2bfloat16(v0), __float2bfloat16(v1));
                    }
                }
            }
        }
        return;
    }

    #pragma unroll
    for (int t = 0; t < 2; t++) {
        int r0 = m0 + wm * 32 + t * 16 + lr;
        int r1 = r0 + 8;
        bool w0 = r0 < M, w1 = r1 < M;
        if (WO) {
            int p0 = r0 & 1023, p1 = r1 & 1023;
            if (blockIdx.z) { w0 &= (p0 < nct);  w1 &= (p1 < nct); }
            else            { w0 &= (p0 >= nct); w1 &= (p1 >= nct); }
        }
        #pragma unroll
        for (int j = 0; j < 8; j++) {
            int gn = n0 + wn * 64 + j * 8 + lc;
            float b0 = bias[gn], b1 = bias[gn + 1];
            float v00 = acc[t][j][0] + b0, v01 = acc[t][j][1] + b1;
            float v10 = acc[t][j][2] + b0, v11 = acc[t][j][3] + b1;
            if (EPI == 1) {
                v00 = 0.5f * v00 * (1.0f + erff(v00 * 0.70710678118654752f));
                v01 = 0.5f * v01 * (1.0f + erff(v01 * 0.70710678118654752f));
                v10 = 0.5f * v10 * (1.0f + erff(v10 * 0.70710678118654752f));
                v11 = 0.5f * v11 * (1.0f + erff(v11 * 0.70710678118654752f));
            }
            if (EPI == 1) {
                if (w0) {
                    size_t i0 = (size_t)r0 * N + gn;
                    __half h0, l0, h1, l1;
                    split_f16(v00, &h0, &l0); split_f16(v01, &h1, &l1);
                    *(__half2*)&((__half*)Chi)[i0] = __halves2half2(h0, h1);
                    *(__half2*)&((__half*)Clo)[i0] = __halves2half2(l0, l1);
                }
                if (w1) {
                    size_t i1 = (size_t)r1 * N + gn;
                    __half h0, l0, h1, l1;
                    split_f16(v10, &h0, &l0); split_f16(v11, &h1, &l1);
                    *(__half2*)&((__half*)Chi)[i1] = __halves2half2(h0, h1);
                    *(__half2*)&((__half*)Clo)[i1] = __halves2half2(l0, l1);
                }
            } else {
                if (w0) {
                    size_t i0 = (size_t)r0 * N + gn;
                    if (EPI == 2) { float2 rr = *(const float2*)&res[i0]; v00 += rr.x; v01 += rr.y; }
                    *(float2*)&C[i0] = make_float2(v00, v01);
                }
                if (w1) {
                    size_t i1 = (size_t)r1 * N + gn;
                    if (EPI == 2) { float2 rr = *(const float2*)&res[i1]; v10 += rr.x; v11 += rr.y; }
                    *(float2*)&C[i1] = make_float2(v10, v11);
                }
            }
        }
    }
}

// ---------------- tensor-core flash attention (sorted-row output) ------------
__global__ __launch_bounds__(128) void attn_mma(
    const float* __restrict__ bqkv_c, const float* __restrict__ bqkv_t)
{
    int qt = blockIdx.x, h = blockIdx.y, b = blockIdx.z;
    int tid = threadIdx.x, wid = tid >> 5, lane = tid & 31;

    __shared__ bf16 sQh[64][SSTR], sQl[64][SSTR];
    __shared__ bf16 sKh[32][SSTR], sKl[32][SSTR], sVt[32][SSTR];
    __shared__ int stok[64], ssel[64];

    if (tid < 64) {
        int tok = g_qidx[b * KK + qt * 64 + tid];
        stok[tid] = tok;
        ssel[tid] = g_isctx[b * KK + tok];
    }
    __syncthreads();

    // stage Q (already scaled + split by QKV epilogue): pure 16B copies
    {
        int row = tid >> 1;
        int dg = (tid & 1) * 16;
        int qbank = ssel[row] ? 0 : 1;
        size_t o = QIDX(qbank, b, RR + stok[row]) + h * HD + dg;
        *(uint4*)&sQh[row][dg]     = *(const uint4*)&g_qh[o];
        *(uint4*)&sQh[row][dg + 8] = *(const uint4*)&g_qh[o + 8];
        *(uint4*)&sQl[row][dg]     = *(const uint4*)&g_ql[o];
        *(uint4*)&sQl[row][dg + 8] = *(const uint4*)&g_ql[o + 8];
    }
    __syncthreads();

    int lrow = lane & 15, lcol8 = (lane >> 4) * 8;
    unsigned qhf[2][4], qlf[2][4];
    #pragma unroll
    for (int kc = 0; kc < 2; kc++) {
        ldsm4(qhf[kc], smem_u32(&sQh[wid * 16 + lrow][kc * 16 + lcol8]));
        ldsm4(qlf[kc], smem_u32(&sQl[wid * 16 + lrow][kc * 16 + lcol8]));
    }

    int uni = (ssel[0] == ssel[63]);
    int cnt = g_kcnt[b];
    int cntp1 = cnt + 1;
    int ntiles = (cntp1 + 31) >> 5;
    int npass = uni ? 1 : 2;
    int kc0 = 2 * (lane & 3);

    for (int pass = 0; pass < npass; pass++) {
        int psel = uni ? ssel[0] : (pass == 0 ? 1 : 0);
        int bank = psel ? 0 : 1;
        const float* bq = psel ? bqkv_c : bqkv_t;
        const bf16* khs = g_kh + KVIDX(bank, b, h, 0);
        const bf16* kls = g_kl + KVIDX(bank, b, h, 0);
        const bf16* vs  = g_kv + KVIDX(bank, b, h, 0);

        float O[4][4];
        #pragma unroll
        for (int nb = 0; nb < 4; nb++)
            #pragma unroll
            for (int q = 0; q < 4; q++) O[nb][q] = 0.f;
        float mrow[2] = {-1e30f, -1e30f};
        float ssum[2] = {0.f, 0.f};

        for (int t = 0; t < ntiles; t++) {
            int g0 = t * 32;
            __syncthreads();
            {
                int slot = tid >> 2, dg = (tid & 3) * 8;
                int gk = g0 + slot;
                if (gk < cnt) {
                    size_t l = (size_t)g_kidx[b * LL + gk] * HD + dg;
                    *(uint4*)&sKh[slot][dg] = *(const uint4*)(khs + l);
                    *(uint4*)&sKl[slot][dg] = *(const uint4*)(kls + l);
                    *(uint4*)&sVt[slot][dg] = *(const uint4*)(vs + l);
                } else if (gk == cnt) {
                    #pragma unroll
                    for (int j = 0; j < 8; j++) {
                        split_bf16(bq[DD + h * HD + dg + j], &sKh[slot][dg + j], &sKl[slot][dg + j]);
                        sVt[slot][dg + j] = __float2bfloat16(bq[2 * DD + h * HD + dg + j]);
                    }
                } else {
                    uint4 z = make_uint4(0u, 0u, 0u, 0u);
                    *(uint4*)&sKh[slot][dg] = z;
                    *(uint4*)&sKl[slot][dg] = z;
                    *(uint4*)&sVt[slot][dg] = z;
                }
            }
            __syncthreads();

            float s[4][4];
            #pragma unroll
            for (int nb = 0; nb < 4; nb++)
                #pragma unroll
                for (int q = 0; q < 4; q++) s[nb][q] = 0.f;
            #pragma unroll
            for (int kc = 0; kc < 2; kc++) {
                int ko = kc * 16 + lcol8;
                unsigned khf[2][4], klf[2][4];
                #pragma unroll
                for (int g = 0; g < 2; g++) {
                    ldsm4(khf[g], smem_u32(&sKh[g * 16 + lrow][ko]));
                    ldsm4(klf[g], smem_u32(&sKl[g * 16 + lrow][ko]));
                }
                #pragma unroll
                for (int g = 0; g < 2; g++) {
                    mma_bf(s[g * 2],     qhf[kc], khf[g][0], khf[g][2]);
                    mma_bf(s[g * 2 + 1], qhf[kc], khf[g][1], khf[g][3]);
                    mma_bf(s[g * 2],     qlf[kc], khf[g][0], khf[g][2]);
                    mma_bf(s[g * 2 + 1], qlf[kc], khf[g][1], khf[g][3]);
                    mma_bf(s[g * 2],     qhf[kc], klf[g][0], klf[g][2]);
                    mma_bf(s[g * 2 + 1], qhf[kc], klf[g][1], klf[g][3]);
                }
            }
            unsigned vf[2][2][4];
            #pragma unroll
            for (int kc = 0; kc < 2; kc++)
                #pragma unroll
                for (int vp = 0; vp < 2; vp++)
                    ldsm4t(vf[kc][vp], smem_u32(&sVt[kc * 16 + lrow][vp * 16 + lcol8]));

            #pragma unroll
            for (int nb = 0; nb < 4; nb++) {
                int c0 = g0 + nb * 8 + kc0;
                if (c0 >= cntp1)     { s[nb][0] = -1e30f; s[nb][2] = -1e30f; }
                if (c0 + 1 >= cntp1) { s[nb][1] = -1e30f; s[nb][3] = -1e30f; }
            }

            #pragma unroll
            for (int th = 0; th < 2; th++) {
                float lm = s[0][2 * th];
                #pragma unroll
                for (int nb = 0; nb < 4; nb++)
                    lm = fmaxf(lm, fmaxf(s[nb][2 * th], s[nb][2 * th + 1]));
                lm = fmaxf(lm, __shfl_xor_sync(0xffffffffu, lm, 1));
                lm = fmaxf(lm, __shfl_xor_sync(0xffffffffu, lm, 2));
                float mn = fmaxf(mrow[th], lm);
                float corr = expapx(mrow[th] - mn);
                mrow[th] = mn;
                float rs = 0.f;
                #pragma unroll
                for (int nb = 0; nb < 4; nb++) {
                    s[nb][2 * th]     = expapx(s[nb][2 * th] - mn);
                    s[nb][2 * th + 1] = expapx(s[nb][2 * th + 1] - mn);
                    rs += s[nb][2 * th] + s[nb][2 * th + 1];
                }
                rs += __shfl_xor_sync(0xffffffffu, rs, 1);
                rs += __shfl_xor_sync(0xffffffffu, rs, 2);
                ssum[th] = ssum[th] * corr + rs;
                #pragma unroll
                for (int nb = 0; nb < 4; nb++) {
                    O[nb][2 * th]     *= corr;
                    O[nb][2 * th + 1] *= corr;
                }
            }

            #pragma unroll
            for (int kc = 0; kc < 2; kc++) {
                unsigned pa[4];
                pa[0] = bf16pair(s[2 * kc][0],     s[2 * kc][1]);
                pa[1] = bf16pair(s[2 * kc][2],     s[2 * kc][3]);
                pa[2] = bf16pair(s[2 * kc + 1][0], s[2 * kc + 1][1]);
                pa[3] = bf16pair(s[2 * kc + 1][2], s[2 * kc + 1][3]);
                mma_bf(O[0], pa, vf[kc][0][0], vf[kc][0][1]);
                mma_bf(O[1], pa, vf[kc][0][2], vf[kc][0][3]);
                mma_bf(O[2], pa, vf[kc][1][0], vf[kc][1][1]);
                mma_bf(O[3], pa, vf[kc][1][2], vf[kc][1][3]);
            }
        }

        float inv[2] = {1.f / ssum[0], 1.f / ssum[1]};
        #pragma unroll
        for (int th = 0; th < 2; th++) {
            int rl = wid * 16 + (lane >> 2) + th * 8;
            if (ssel[rl] == psel) {
                size_t base = ((size_t)(b * KK + qt * 64 + rl)) * DD + h * HD;
                #pragma unroll
                for (int nb = 0; nb < 4; nb++) {
                    int col = nb * 8 + kc0;
                    float v0 = O[nb][2 * th] * inv[th];
                    float v1 = O[nb][2 * th + 1] * inv[th];
                    bf16 h0, l0, h1, l1;
                    split_bf16(v0, &h0, &l0);
                    split_bf16(v1, &h1, &l1);
                    *(__nv_bfloat162*)&g_at_h[base + col] = __nv_bfloat162(h0, h1);
                    *(__nv_bfloat162*)&g_at_l[base + col] = __nv_bfloat162(l0, l1);
                }
            }
        }
    }
}

// ---------------- residual + LN (unsort via qpos) ----------------------------
__global__ __launch_bounds__(256) void resln_kernel(
    const float* __restrict__ gn, const float* __restrict__ bn,
    const float* __restrict__ bo_c, const float* __restrict__ bo_t)
{
    int mrow = blockIdx.x;
    int d = threadIdx.x;
    int b = mrow >> 10, k = mrow & 1023;
    int sel = g_isctx[b * KK + k];
    int pos = g_qpos[b * KK + k];

    __shared__ float red[2][8];
    float att = g_tmp2[((size_t)(b * 1024 + pos)) * DD + d]
              + (sel ? bo_c[d] : bo_t[d]);
    float v = g_xfull[((size_t)(b * LL + RR + k)) * DD + d] + att;
    g_x2[(size_t)mrow * DD + d] = v;

    float s1 = v, s2 = v * v;
    #pragma unroll
    for (int o = 16; o; o >>= 1) {
        s1 += __shfl_down_sync(0xffffffffu, s1, o);
        s2 += __shfl_down_sync(0xffffffffu, s2, o);
    }
    int wid = d >> 5, lane = d & 31;
    if (lane == 0) { red[0][wid] = s1; red[1][wid] = s2; }
    __syncthreads();
    if (d == 0) {
        float t1 = 0.f, t2 = 0.f;
        #pragma unroll
        for (int i = 0; i < 8; i++) { t1 += red[0][i]; t2 += red[1][i]; }
        red[0][0] = t1; red[1][0] = t2;
    }
    __syncthreads();
    float mean = red[0][0] * (1.f / DD);
    float var  = red[1][0] * (1.f / DD) - mean * mean;
    float rstd = rsqrtf(var + 1e-5f);
    float xnv = (v - mean) * rstd * gn[d] + bn[d];
    size_t gi = (size_t)mrow * DD + d;
    split_f16(xnv, g_x2n_h + gi, g_x2n_l + gi);
}

// ---------------- launch ------------------------------------------------------
static void* sym(const void* s)
{
    void* p = nullptr;
    cudaGetSymbolAddress(&p, s);
    return p;
}

extern "C" void kernel_launch(void* const* d_in, const int* in_sizes, int n_in,
                              void* d_out, int out_size)
{
    const float* x          = (const float*)d_in[0];
    const int*   coords     = (const int*)d_in[1];
    const int*   ctxid      = (const int*)d_in[2];
    const float* tgt_e      = (const float*)d_in[3];
    const float* ctx_e      = (const float*)d_in[4];
    const float* regs       = (const float*)d_in[5];
    const float* rope       = (const float*)d_in[6];
    const float* norm_g     = (const float*)d_in[7];
    const float* norm_b     = (const float*)d_in[8];
    const float* ctx_Wqkv   = (const float*)d_in[9];
    const float* ctx_bqkv   = (const float*)d_in[10];
    const float* ctx_Wo     = (const float*)d_in[11];
    const float* ctx_bo     = (const float*)d_in[12];
    const float* tgt_Wqkv   = (const float*)d_in[13];
    const float* tgt_bqkv   = (const float*)d_in[14];
    const float* tgt_Wo     = (const float*)d_in[15];
    const float* tgt_bo     = (const float*)d_in[16];
    const float* mlpn_g     = (const float*)d_in[17];
    const float* mlpn_b     = (const float*)d_in[18];
    const float* mlp_W1     = (const float*)d_in[19];
    const float* mlp_b1     = (const float*)d_in[20];
    const float* mlp_W2     = (const float*)d_in[21];
    const float* mlp_b2     = (const float*)d_in[22];
    float* out = (float*)d_out;

    bf16* wq_h  = (bf16*)sym(g_wq_h);  bf16* wq_l  = (bf16*)sym(g_wq_l);
    bf16* wo_h  = (bf16*)sym(g_wo_h);  bf16* wo_l  = (bf16*)sym(g_wo_l);
    __half* w1_h = (__half*)sym(g_w1_h); __half* w1_l = (__half*)sym(g_w1_l);
    __half* w2_h = (__half*)sym(g_w2_h); __half* w2_l = (__half*)sym(g_w2_l);
    bf16* xn_h  = (bf16*)sym(g_xn_h);  bf16* xn_l  = (bf16*)sym(g_xn_l);
    bf16* at_h  = (bf16*)sym(g_at_h);  bf16* at_l  = (bf16*)sym(g_at_l);
    __half* x2n_h = (__half*)sym(g_x2n_h); __half* x2n_l = (__half*)sym(g_x2n_l);
    __half* h1_h  = (__half*)sym(g_h1_h);  __half* h1_l  = (__half*)sym(g_h1_l);
    float* p_bq2  = (float*)sym(g_bq2);
    float* p_tmp2 = (float*)sym(g_tmp2);
    float* p_x2   = (float*)sym(g_x2);
    float* p_zb   = (float*)sym(g_zerob);
    int*   p_nctx = (int*)sym(g_nctx);

    cudaFuncSetAttribute(mma_gemm<3,0,0>, cudaFuncAttributeMaxDynamicSharedMemorySize, GEMM_SMEM);
    cudaFuncSetAttribute(mma_gemm<0,0,1>, cudaFuncAttributeMaxDynamicSharedMemorySize, GEMM_SMEM);
    cudaFuncSetAttribute(mma_gemm<1,1,0>, cudaFuncAttributeMaxDynamicSharedMemorySize, GEMM_SMEM);
    cudaFuncSetAttribute(mma_gemm<2,1,0>, cudaFuncAttributeMaxDynamicSharedMemorySize, GEMM_SMEM);

    // 1) embed + rope + LN
    prep_kernel<<<BB * LL, 256>>>(x, coords, ctxid, tgt_e, ctx_e, regs, rope,
                                  norm_g, norm_b);
    // 1b) compaction (parallel scans)
    compact_kernel<<<BB, 128>>>();

    // 1c) weight conversion + QKV bias concat (fused)
    convw_all<<<4102, 256>>>(ctx_Wqkv, tgt_Wqkv, ctx_Wo, tgt_Wo, mlp_W1, mlp_W2,
                             ctx_bqkv, tgt_bqkv);

    // 2) merged QKV GEMM (N=1536) with fused Q/K/V bank scatter epilogue
    {
        dim3 g(12, (BB * LL + 127) / 128);
        mma_gemm<3,0,0><<<g, 256, GEMM_SMEM>>>(xn_h, xn_l, wq_h, wq_l, p_bq2,
                                               nullptr, nullptr, nullptr, nullptr,
                                               BB * LL, 6 * DD, DD, nullptr);
    }

    // 3) tensor-core flash attention (sorted-row output)
    {
        dim3 g(KK / 64, HH, BB);
        attn_mma<<<g, 128>>>(ctx_bqkv, tgt_bqkv);
    }

    // 4) Wo GEMM on sorted rows, per-tile weight bank (z = sel pass)
    {
        dim3 g(2, BB * KK / 128, 2);
        mma_gemm<0,0,1><<<g, 256, GEMM_SMEM>>>(at_h, at_l, wo_h, wo_l, p_zb,
                                               nullptr, p_tmp2, nullptr, nullptr,
                                               BB * KK, DD, DD, p_nctx);
    }

    // 5) residual + LN (unsort) -> fp16 hi/lo
    resln_kernel<<<BB * KK, 256>>>(mlpn_g, mlpn_b, ctx_bo, tgt_bo);

    // 6) MLP up + gelu (fp16 2-phase)
    {
        dim3 g(8, BB * KK / 128);
        mma_gemm<1,1,0><<<g, 256, GEMM_SMEM>>>((bf16*)x2n_h, (bf16*)x2n_l,
                                               (bf16*)w1_h, (bf16*)w1_l, mlp_b1,
                                               nullptr, nullptr, h1_h, h1_l,
                                               BB * KK, 4 * DD, DD, nullptr);
    }

    // 7) MLP down + residual -> out (fp16 2-phase)
    {
        dim3 g(2, BB * KK / 128);
        mma_gemm<2,1,0><<<g, 256, GEMM_SMEM>>>((bf16*)h1_h, (bf16*)h1_l,
                                               (bf16*)w2_h, (bf16*)w2_l, mlp_b2,
                                               p_x2, out, nullptr, nullptr,
                                               BB * KK, DD, 4 * DD, nullptr);
    }
}

// round 17
// speedup vs baseline: 4.8066x; 1.0949x over previous
#include <cuda_runtime.h>
#include <cuda_bf16.h>
#include <cuda_fp16.h>
#include <math.h>

// Problem constants
#define BB 8
#define KK 1024
#define DD 256
#define HH 8
#define RR 4
#define LL 1028      // RR + KK
#define HD 32
#define IMGF 224.0f
#define MAXPF 1023.0f

typedef unsigned long long u64;
typedef __half f16;

// ---------------- mma.sync helpers (base PTX, compute_103-safe) -------------
__device__ __forceinline__ unsigned smem_u32(const void* p) {
    unsigned a;
    asm("{ .reg .u64 t; cvta.to.shared.u64 t, %1; cvt.u32.u64 %0, t; }"
        : "=r"(a) : "l"(p));
    return a;
}
__device__ __forceinline__ void ldsm4(unsigned* r, unsigned addr) {
    asm volatile("ldmatrix.sync.aligned.m8n8.x4.shared.b16 {%0,%1,%2,%3}, [%4];"
                 : "=r"(r[0]), "=r"(r[1]), "=r"(r[2]), "=r"(r[3]) : "r"(addr));
}
__device__ __forceinline__ void ldsm4t(unsigned* r, unsigned addr) {
    asm volatile("ldmatrix.sync.aligned.m8n8.x4.trans.shared.b16 {%0,%1,%2,%3}, [%4];"
                 : "=r"(r[0]), "=r"(r[1]), "=r"(r[2]), "=r"(r[3]) : "r"(addr));
}
__device__ __forceinline__ void mma_fp(float* c, const unsigned* a,
                                       unsigned b0, unsigned b1) {
    asm volatile(
        "mma.sync.aligned.m16n8k16.row.col.f32.f16.f16.f32 "
        "{%0,%1,%2,%3}, {%4,%5,%6,%7}, {%8,%9}, {%0,%1,%2,%3};"
        : "+f"(c[0]), "+f"(c[1]), "+f"(c[2]), "+f"(c[3])
        : "r"(a[0]), "r"(a[1]), "r"(a[2]), "r"(a[3]), "r"(b0), "r"(b1));
}
__device__ __forceinline__ unsigned f16pair(float lo, float hi) {
    __half2 h = __floats2half2_rn(lo, hi);
    return *(unsigned*)&h;
}
// cp.async 16B with zero-fill when n < 16
__device__ __forceinline__ void cpa16(unsigned dst, const void* src, unsigned n) {
    asm volatile("cp.async.cg.shared.global [%0], [%1], 16, %2;"
                 :: "r"(dst), "l"(src), "r"(n) : "memory");
}
#define CP_COMMIT() asm volatile("cp.async.commit_group;" ::: "memory")
#define CP_WAIT1()  asm volatile("cp.async.wait_group 1;" ::: "memory")
#define CP_WAIT0()  asm volatile("cp.async.wait_group 0;" ::: "memory")

// fast exp for x <= 0 on fma pipe (no MUFU); rel err ~2.4e-6
__device__ __forceinline__ float expapx(float x) {
    x = fmaxf(x, -87.0f);
    float t = x * 1.44269504088896341f;
    float fn = rintf(t);
    int n = (int)fn;
    float r = t - fn;
    float p = fmaf(0.0013333558f, r, 0.0096181291f);
    p = fmaf(p, r, 0.0555041087f);
    p = fmaf(p, r, 0.2402265069f);
    p = fmaf(p, r, 0.6931471806f);
    p = fmaf(p, r, 1.0f);
    return __int_as_float((n + 127) << 23) * p;
}

// ---------------- scratch (device globals; no allocation allowed) ----------
__device__ float g_xfull[BB * LL * DD];
__device__ int   g_allowed[BB * LL];
__device__ int   g_isctx[BB * KK];
__device__ int   g_kidx[BB * LL];
__device__ int   g_kcnt[BB];
__device__ int   g_qidx[BB * KK];
__device__ int   g_qpos[BB * KK];              // token -> sorted position
__device__ int   g_nctx[BB];                   // ctx token count per batch
__device__ float g_bq2[6 * DD];                // merged QKV bias
__device__ float g_tmp2[BB * KK * 2 * DD];     // Wo out (sorted rows, N=256 used)
__device__ float g_x2[BB * KK * DD];
__device__ float g_zerob[2 * DD];              // zero bias (never written)

// fp16 hi/lo activation buffers
__device__ f16 g_xn_h[BB * LL * DD],   g_xn_l[BB * LL * DD];
__device__ f16 g_at_h[BB * KK * DD],   g_at_l[BB * KK * DD];   // sorted rows
__device__ f16 g_x2n_h[BB * KK * DD],  g_x2n_l[BB * KK * DD];
__device__ f16 g_h1_h[BB * KK * 4 * DD], g_h1_l[BB * KK * 4 * DD];

// fp16 hi/lo weight buffers
__device__ f16 g_wq_h[6 * DD * DD], g_wq_l[6 * DD * DD];    // [ctx;tgt] qkv
__device__ f16 g_wo_h[2 * DD * DD], g_wo_l[2 * DD * DD];    // [ctx;tgt] wo
__device__ f16 g_w1_h[4 * DD * DD], g_w1_l[4 * DD * DD];
__device__ f16 g_w2_h[4 * DD * DD], g_w2_l[4 * DD * DD];

// fp16 Q/K/V banks: [bank(0=ctx,1=tgt)][b][...][l][...]
#define KVIDX(bank,b,h,l) (((size_t)(((bank) * BB + (b)) * HH + (h)) * LL + (l)) * HD)
#define QIDX(bank,b,l)    (((size_t)(((bank) * BB + (b)) * LL + (l))) * DD)
__device__ f16 g_kh[2 * BB * HH * LL * HD];
__device__ f16 g_kl[2 * BB * HH * LL * HD];
__device__ f16 g_kv[2 * BB * HH * LL * HD];
__device__ f16 g_qh[2 * BB * LL * DD];
__device__ f16 g_ql[2 * BB * LL * DD];

__device__ __forceinline__ void split_f16(float v, f16* hp, f16* lp) {
    f16 h = __float2half_rn(v);
    *hp = h;
    *lp = __float2half_rn(v - __half2float(h));
}

// ---------------- fused weight conversion + QKV bias concat ------------------
__global__ __launch_bounds__(256) void convw_all(
    const float* __restrict__ s0, const float* __restrict__ s1,
    const float* __restrict__ s2, const float* __restrict__ s3,
    const float* __restrict__ s4, const float* __restrict__ s5,
    const float* __restrict__ bc, const float* __restrict__ bt)
{
    int i = blockIdx.x * 256 + threadIdx.x;
    const int N0 = 3 * DD * DD;
    const int N2 = DD * DD;
    const int N4 = 4 * DD * DD;
    const int TOT = 2 * N0 + 2 * N2 + 2 * N4;   // 1048576
    if (i < N0) {
        split_f16(s0[i], g_wq_h + i, g_wq_l + i);
    } else if (i < 2 * N0) {
        int j = i - N0;
        split_f16(s1[j], g_wq_h + N0 + j, g_wq_l + N0 + j);
    } else if (i < 2 * N0 + N2) {
        int j = i - 2 * N0;
        split_f16(s2[j], g_wo_h + j, g_wo_l + j);
    } else if (i < 2 * N0 + 2 * N2) {
        int j = i - 2 * N0 - N2;
        split_f16(s3[j], g_wo_h + N2 + j, g_wo_l + N2 + j);
    } else if (i < 2 * N0 + 2 * N2 + N4) {
        int j = i - 2 * N0 - 2 * N2;
        split_f16(s4[j], g_w1_h + j, g_w1_l + j);
    } else if (i < TOT) {
        int j = i - 2 * N0 - 2 * N2 - N4;
        split_f16(s5[j], g_w2_h + j, g_w2_l + j);
    } else if (i < TOT + 6 * DD) {
        int j = i - TOT;
        g_bq2[j] = (j < 3 * DD) ? bc[j] : bt[j - 3 * DD];
    }
}

// ---------------- prep: embed add + rope2d + LN -----------------------------
__global__ __launch_bounds__(256) void prep_kernel(
    const float* __restrict__ x, const int* __restrict__ coords,
    const int* __restrict__ ctxid, const float* __restrict__ tgt_e,
    const float* __restrict__ ctx_e, const float* __restrict__ regs,
    const float* __restrict__ rope, const float* __restrict__ ng,
    const float* __restrict__ nb)
{
    int blk = blockIdx.x;
    int b = blk / LL;
    int l = blk - b * LL;
    int d = threadIdx.x;

    __shared__ float srow[DD];
    __shared__ float red[2][8];

    float v;
    int ic = 1;
    if (l < RR) {
        v = regs[l * DD + d] + ctx_e[d];
    } else {
        int k = l - RR;
        ic = ctxid[b * KK + k] > 0;
        v = x[((size_t)(b * KK + k)) * DD + d] + (ic ? ctx_e[d] : tgt_e[d]);
    }
    srow[d] = v;
    __syncthreads();

    float rv = v;
    if (l >= RR) {
        int k = l - RR;
        int cy = coords[(size_t)(b * KK + k) * 2 + 0];
        int cx = coords[(size_t)(b * KK + k) * 2 + 1];
        float cny = fminf(fmaxf(((float)cy / IMGF) * MAXPF, 0.f), MAXPF);
        float cnx = fminf(fmaxf(((float)cx / IMGF) * MAXPF, 0.f), MAXPF);
        int yi = (int)cny;
        int xi = (int)cnx;
        int j; const float* cp;
        if (d < 128) { j = d >> 1;         cp = rope + ((size_t)xi * 64 + j) * 2; }
        else         { j = (d - 128) >> 1; cp = rope + ((size_t)yi * 64 + j) * 2; }
        float c = cp[0], s = cp[1];
        float p0 = srow[d & ~1];
        float p1 = srow[d | 1];
        rv = (d & 1) ? (p0 * s + p1 * c) : (p0 * c - p1 * s);
    }

    size_t gi = ((size_t)(b * LL + l)) * DD + d;
    g_xfull[gi] = rv;
    if (d == 0) {
        g_allowed[b * LL + l] = (l < RR) ? 1 : ic;
        if (l >= RR) g_isctx[b * KK + (l - RR)] = ic;
    }

    float s1 = rv, s2 = rv * rv;
    #pragma unroll
    for (int o = 16; o; o >>= 1) {
        s1 += __shfl_down_sync(0xffffffffu, s1, o);
        s2 += __shfl_down_sync(0xffffffffu, s2, o);
    }
    int wid = d >> 5, lane = d & 31;
    if (lane == 0) { red[0][wid] = s1; red[1][wid] = s2; }
    __syncthreads();
    if (d == 0) {
        float t1 = 0.f, t2 = 0.f;
        #pragma unroll
        for (int i = 0; i < 8; i++) { t1 += red[0][i]; t2 += red[1][i]; }
        red[0][0] = t1; red[1][0] = t2;
    }
    __syncthreads();
    float mean = red[0][0] * (1.f / DD);
    float var  = red[1][0] * (1.f / DD) - mean * mean;
    float rstd = rsqrtf(var + 1e-5f);
    float xnv = (rv - mean) * rstd * ng[d] + nb[d];
    split_f16(xnv, g_xn_h + gi, g_xn_l + gi);
}

// ---------------- compaction (parallel scans) --------------------------------
__device__ __forceinline__ int excl_scan128(int v, int* sb, int t, int* total) {
    sb[t] = v;
    __syncthreads();
    #pragma unroll
    for (int d = 1; d < 128; d <<= 1) {
        int x = (t >= d) ? sb[t - d] : 0;
        __syncthreads();
        sb[t] += x;
        __syncthreads();
    }
    int incl = sb[t];
    *total = sb[127];
    __syncthreads();
    return incl - v;
}

__global__ __launch_bounds__(128) void compact_kernel()
{
    int b = blockIdx.x, t = threadIdx.x;
    __shared__ int sb[128];

    int a[9]; int cnt = 0;
    #pragma unroll
    for (int i = 0; i < 9; i++) {
        int idx = t * 9 + i;
        a[i] = (idx < LL) ? g_allowed[b * LL + idx] : 0;
        cnt += a[i];
    }
    int tot;
    int off = excl_scan128(cnt, sb, t, &tot);
    #pragma unroll
    for (int i = 0; i < 9; i++) {
        int idx = t * 9 + i;
        if (idx < LL && a[i]) g_kidx[b * LL + off++] = idx;
    }
    if (t == 0) g_kcnt[b] = tot;

    int s[8]; int cc = 0;
    #pragma unroll
    for (int i = 0; i < 8; i++) {
        s[i] = g_isctx[b * KK + t * 8 + i];
        cc += s[i];
    }
    int nct;
    int offc = excl_scan128(cc, sb, t, &nct);
    int offt = t * 8 - offc;
    #pragma unroll
    for (int i = 0; i < 8; i++) {
        int idx = t * 8 + i;
        int pos = s[i] ? (offc++) : (nct + offt++);
        g_qidx[b * KK + pos] = idx;
        g_qpos[b * KK + idx] = pos;
    }
    if (t == 0) g_nctx[b] = nct;
}

// ---------------- cp.async pipelined fp16 2-phase mma.sync GEMM --------------
// All GEMMs: fp16 2-phase (a_hi*w_hi + a_lo*w_hi), fp32 reg accum.
// WO=1: sorted-row Wo mode. EPI 0: C=D+bias; 1: fp16 split(gelu); 2: +res;
// EPI 3: QKV scatter epilogue (Q scaled+split to g_qh/g_ql; K/V to banks).
#define SSTR 40
#define MATSZ (128 * SSTR)
#define GEMM_SMEM (8 * MATSZ * 2)

template <int EPI, int WO>
__global__ __launch_bounds__(256) void mma_gemm(
    const f16* __restrict__ Ahi, const f16* __restrict__ Alo,
    const f16* __restrict__ Whi_,
    const float* __restrict__ bias, const float* __restrict__ res,
    float* __restrict__ C, f16* __restrict__ Chi, f16* __restrict__ Clo,
    int M, int N, int Kd, const int* __restrict__ nctxArr)
{
    extern __shared__ f16 dsm[];

    int m0 = blockIdx.y * 128;
    int n0 = blockIdx.x * 128;

    const f16* Whi = Whi_;
    int nct = 0;
    if (WO) {
        int b = m0 >> 10;
        nct = nctxArr[b];
        int lo = m0 & 1023;
        if (blockIdx.z) { if (lo >= nct) return; }
        else { if (lo + 128 <= nct) return; Whi += DD * DD; }
    }

    int tid = threadIdx.x;
    int wid = tid >> 5, lane = tid & 31;
    int wm = wid >> 1;
    int wn = wid & 1;

    float acc[2][8][4];
    #pragma unroll
    for (int t = 0; t < 2; t++)
        #pragma unroll
        for (int j = 0; j < 8; j++)
            #pragma unroll
            for (int q = 0; q < 4; q++) acc[t][j][q] = 0.f;

    int srow = tid >> 1;
    int scol = (tid & 1) * 16;
    int agm = m0 + srow;
    bool aok = (agm < M);
    int agmc = aok ? agm : (M - 1);
    unsigned abytes = aok ? 16u : 0u;
    unsigned soff = (srow * SSTR + scol) * 2;

    int lrow = lane & 15;
    int lcol8 = (lane >> 4) * 8;

    int NC = Kd >> 5;

    auto stage = [&](int g) {
        int k0 = g << 5;
        unsigned base = smem_u32(dsm) + (unsigned)((g & 1) * 3 * MATSZ * 2) + soff;
        const f16* ga_h = Ahi + (size_t)agmc * Kd + k0 + scol;
        const f16* ga_l = Alo + (size_t)agmc * Kd + k0 + scol;
        const f16* gw_h = Whi + (size_t)(n0 + srow) * Kd + k0 + scol;
        cpa16(base,                  ga_h,     abytes);
        cpa16(base + 16,             ga_h + 8, abytes);
        cpa16(base + 2 * MATSZ,      ga_l,     abytes);
        cpa16(base + 2 * MATSZ + 16, ga_l + 8, abytes);
        cpa16(base + 4 * MATSZ,      gw_h,     16u);
        cpa16(base + 4 * MATSZ + 16, gw_h + 8, 16u);
    };

    stage(0);
    CP_COMMIT();

    for (int g = 0; g < NC; g++) {
        if (g + 1 < NC) { stage(g + 1); CP_COMMIT(); CP_WAIT1(); }
        else            { CP_WAIT0(); }
        __syncthreads();

        f16* bAh = dsm + (g & 1) * 3 * MATSZ;
        f16* bAl = bAh + MATSZ;
        f16* bWh = bAl + MATSZ;

        #pragma unroll
        for (int ks = 0; ks < 2; ks++) {
            int ko = ks * 16 + lcol8;
            unsigned ah[2][4], al[2][4], w[4][4];
            #pragma unroll
            for (int t = 0; t < 2; t++) {
                ldsm4(ah[t], smem_u32(bAh + (wm * 32 + t * 16 + lrow) * SSTR + ko));
                ldsm4(al[t], smem_u32(bAl + (wm * 32 + t * 16 + lrow) * SSTR + ko));
            }
            #pragma unroll
            for (int gg = 0; gg < 4; gg++)
                ldsm4(w[gg], smem_u32(bWh + (wn * 64 + gg * 16 + lrow) * SSTR + ko));
            #pragma unroll
            for (int t = 0; t < 2; t++)
                #pragma unroll
                for (int gg = 0; gg < 4; gg++) {
                    mma_fp(acc[t][gg * 2],     ah[t], w[gg][0], w[gg][2]);
                    mma_fp(acc[t][gg * 2 + 1], ah[t], w[gg][1], w[gg][3]);
                    mma_fp(acc[t][gg * 2],     al[t], w[gg][0], w[gg][2]);
                    mma_fp(acc[t][gg * 2 + 1], al[t], w[gg][1], w[gg][3]);
                }
        }
        __syncthreads();
    }

    // ---- epilogue ----
    int lr = lane >> 2;
    int lc = (lane & 3) * 2;

    if (EPI == 3) {
        // QKV scatter: cols [0,768)=ctx bank, [768,1536)=tgt bank.
        // Within bank: [0,256)=Q (scale+split), [256,512)=K, [512,768)=V.
        const float qs = 0.1767766952966369f;
        #pragma unroll
        for (int t = 0; t < 2; t++) {
            #pragma unroll
            for (int rI = 0; rI < 2; rI++) {
                int r = m0 + wm * 32 + t * 16 + lr + rI * 8;
                if (r >= M) continue;
                int bb = r / LL, ll = r - bb * LL;
                #pragma unroll
                for (int j = 0; j < 8; j++) {
                    int gn = n0 + wn * 64 + j * 8 + lc;
                    float v0 = acc[t][j][rI * 2 + 0] + bias[gn];
                    float v1 = acc[t][j][rI * 2 + 1] + bias[gn + 1];
                    int bank = gn >= 768;
                    int c = gn - (bank ? 768 : 0);
                    if (c < 256) {
                        f16 h0, l0, h1, l1;
                        split_f16(v0 * qs, &h0, &l0);
                        split_f16(v1 * qs, &h1, &l1);
                        size_t o = QIDX(bank, bb, ll) + c;
                        *(__half2*)&g_qh[o] = __halves2half2(h0, h1);
                        *(__half2*)&g_ql[o] = __halves2half2(l0, l1);
                    } else if (c < 512) {
                        int h = (c - 256) >> 5, dd = (c - 256) & 31;
                        size_t o = KVIDX(bank, bb, h, ll) + dd;
                        f16 h0, l0, h1, l1;
                        split_f16(v0, &h0, &l0);
                        split_f16(v1, &h1, &l1);
                        *(__half2*)&g_kh[o] = __halves2half2(h0, h1);
                        *(__half2*)&g_kl[o] = __halves2half2(l0, l1);
                    } else {
                        int h = (c - 512) >> 5, dd = (c - 512) & 31;
                        size_t o = KVIDX(bank, bb, h, ll) + dd;
                        *(__half2*)&g_kv[o] = __floats2half2_rn(v0, v1);
                    }
                }
            }
        }
        return;
    }

    #pragma unroll
    for (int t = 0; t < 2; t++) {
        int r0 = m0 + wm * 32 + t * 16 + lr;
        int r1 = r0 + 8;
        bool w0 = r0 < M, w1 = r1 < M;
        if (WO) {
            int p0 = r0 & 1023, p1 = r1 & 1023;
            if (blockIdx.z) { w0 &= (p0 < nct);  w1 &= (p1 < nct); }
            else            { w0 &= (p0 >= nct); w1 &= (p1 >= nct); }
        }
        #pragma unroll
        for (int j = 0; j < 8; j++) {
            int gn = n0 + wn * 64 + j * 8 + lc;
            float b0 = bias[gn], b1 = bias[gn + 1];
            float v00 = acc[t][j][0] + b0, v01 = acc[t][j][1] + b1;
            float v10 = acc[t][j][2] + b0, v11 = acc[t][j][3] + b1;
            if (EPI == 1) {
                v00 = 0.5f * v00 * (1.0f + erff(v00 * 0.70710678118654752f));
                v01 = 0.5f * v01 * (1.0f + erff(v01 * 0.70710678118654752f));
                v10 = 0.5f * v10 * (1.0f + erff(v10 * 0.70710678118654752f));
                v11 = 0.5f * v11 * (1.0f + erff(v11 * 0.70710678118654752f));
            }
            if (EPI == 1) {
                if (w0) {
                    size_t i0 = (size_t)r0 * N + gn;
                    f16 h0, l0, h1, l1;
                    split_f16(v00, &h0, &l0); split_f16(v01, &h1, &l1);
                    *(__half2*)&Chi[i0] = __halves2half2(h0, h1);
                    *(__half2*)&Clo[i0] = __halves2half2(l0, l1);
                }
                if (w1) {
                    size_t i1 = (size_t)r1 * N + gn;
                    f16 h0, l0, h1, l1;
                    split_f16(v10, &h0, &l0); split_f16(v11, &h1, &l1);
                    *(__half2*)&Chi[i1] = __halves2half2(h0, h1);
                    *(__half2*)&Clo[i1] = __halves2half2(l0, l1);
                }
            } else {
                if (w0) {
                    size_t i0 = (size_t)r0 * N + gn;
                    if (EPI == 2) { float2 rr = *(const float2*)&res[i0]; v00 += rr.x; v01 += rr.y; }
                    *(float2*)&C[i0] = make_float2(v00, v01);
                }
                if (w1) {
                    size_t i1 = (size_t)r1 * N + gn;
                    if (EPI == 2) { float2 rr = *(const float2*)&res[i1]; v10 += rr.x; v11 += rr.y; }
                    *(float2*)&C[i1] = make_float2(v10, v11);
                }
            }
        }
    }
}

// ---------------- tensor-core flash attention (fp16, sorted-row output) ------
__global__ __launch_bounds__(128) void attn_mma(
    const float* __restrict__ bqkv_c, const float* __restrict__ bqkv_t)
{
    int qt = blockIdx.x, h = blockIdx.y, b = blockIdx.z;
    int tid = threadIdx.x, wid = tid >> 5, lane = tid & 31;

    __shared__ f16 sQh[64][SSTR], sQl[64][SSTR];
    __shared__ f16 sKh[32][SSTR], sKl[32][SSTR], sVt[32][SSTR];
    __shared__ int stok[64], ssel[64];

    if (tid < 64) {
        int tok = g_qidx[b * KK + qt * 64 + tid];
        stok[tid] = tok;
        ssel[tid] = g_isctx[b * KK + tok];
    }
    __syncthreads();

    // stage Q (already scaled + split by QKV epilogue): pure 16B copies
    {
        int row = tid >> 1;
        int dg = (tid & 1) * 16;
        int qbank = ssel[row] ? 0 : 1;
        size_t o = QIDX(qbank, b, RR + stok[row]) + h * HD + dg;
        *(uint4*)&sQh[row][dg]     = *(const uint4*)&g_qh[o];
        *(uint4*)&sQh[row][dg + 8] = *(const uint4*)&g_qh[o + 8];
        *(uint4*)&sQl[row][dg]     = *(const uint4*)&g_ql[o];
        *(uint4*)&sQl[row][dg + 8] = *(const uint4*)&g_ql[o + 8];
    }
    __syncthreads();

    int lrow = lane & 15, lcol8 = (lane >> 4) * 8;
    unsigned qhf[2][4], qlf[2][4];
    #pragma unroll
    for (int kc = 0; kc < 2; kc++) {
        ldsm4(qhf[kc], smem_u32(&sQh[wid * 16 + lrow][kc * 16 + lcol8]));
        ldsm4(qlf[kc], smem_u32(&sQl[wid * 16 + lrow][kc * 16 + lcol8]));
    }

    int uni = (ssel[0] == ssel[63]);
    int cnt = g_kcnt[b];
    int cntp1 = cnt + 1;
    int ntiles = (cntp1 + 31) >> 5;
    int npass = uni ? 1 : 2;
    int kc0 = 2 * (lane & 3);

    for (int pass = 0; pass < npass; pass++) {
        int psel = uni ? ssel[0] : (pass == 0 ? 1 : 0);
        int bank = psel ? 0 : 1;
        const float* bq = psel ? bqkv_c : bqkv_t;
        const f16* khs = g_kh + KVIDX(bank, b, h, 0);
        const f16* kls = g_kl + KVIDX(bank, b, h, 0);
        const f16* vs  = g_kv + KVIDX(bank, b, h, 0);

        float O[4][4];
        #pragma unroll
        for (int nb = 0; nb < 4; nb++)
            #pragma unroll
            for (int q = 0; q < 4; q++) O[nb][q] = 0.f;
        float mrow[2] = {-1e30f, -1e30f};
        float ssum[2] = {0.f, 0.f};

        for (int t = 0; t < ntiles; t++) {
            int g0 = t * 32;
            __syncthreads();
            {
                int slot = tid >> 2, dg = (tid & 3) * 8;
                int gk = g0 + slot;
                if (gk < cnt) {
                    size_t l = (size_t)g_kidx[b * LL + gk] * HD + dg;
                    *(uint4*)&sKh[slot][dg] = *(const uint4*)(khs + l);
                    *(uint4*)&sKl[slot][dg] = *(const uint4*)(kls + l);
                    *(uint4*)&sVt[slot][dg] = *(const uint4*)(vs + l);
                } else if (gk == cnt) {
                    #pragma unroll
                    for (int j = 0; j < 8; j++) {
                        split_f16(bq[DD + h * HD + dg + j], &sKh[slot][dg + j], &sKl[slot][dg + j]);
                        sVt[slot][dg + j] = __float2half_rn(bq[2 * DD + h * HD + dg + j]);
                    }
                } else {
                    uint4 z = make_uint4(0u, 0u, 0u, 0u);
                    *(uint4*)&sKh[slot][dg] = z;
                    *(uint4*)&sKl[slot][dg] = z;
                    *(uint4*)&sVt[slot][dg] = z;
                }
            }
            __syncthreads();

            float s[4][4];
            #pragma unroll
            for (int nb = 0; nb < 4; nb++)
                #pragma unroll
                for (int q = 0; q < 4; q++) s[nb][q] = 0.f;
            #pragma unroll
            for (int kc = 0; kc < 2; kc++) {
                int ko = kc * 16 + lcol8;
                unsigned khf[2][4], klf[2][4];
                #pragma unroll
                for (int g = 0; g < 2; g++) {
                    ldsm4(khf[g], smem_u32(&sKh[g * 16 + lrow][ko]));
                    ldsm4(klf[g], smem_u32(&sKl[g * 16 + lrow][ko]));
                }
                #pragma unroll
                for (int g = 0; g < 2; g++) {
                    mma_fp(s[g * 2],     qhf[kc], khf[g][0], khf[g][2]);
                    mma_fp(s[g * 2 + 1], qhf[kc], khf[g][1], khf[g][3]);
                    mma_fp(s[g * 2],     qlf[kc], khf[g][0], khf[g][2]);
                    mma_fp(s[g * 2 + 1], qlf[kc], khf[g][1], khf[g][3]);
                    mma_fp(s[g * 2],     qhf[kc], klf[g][0], klf[g][2]);
                    mma_fp(s[g * 2 + 1], qhf[kc], klf[g][1], klf[g][3]);
                }
            }
            unsigned vf[2][2][4];
            #pragma unroll
            for (int kc = 0; kc < 2; kc++)
                #pragma unroll
                for (int vp = 0; vp < 2; vp++)
                    ldsm4t(vf[kc][vp], smem_u32(&sVt[kc * 16 + lrow][vp * 16 + lcol8]));

            #pragma unroll
            for (int nb = 0; nb < 4; nb++) {
                int c0 = g0 + nb * 8 + kc0;
                if (c0 >= cntp1)     { s[nb][0] = -1e30f; s[nb][2] = -1e30f; }
                if (c0 + 1 >= cntp1) { s[nb][1] = -1e30f; s[nb][3] = -1e30f; }
            }

            #pragma unroll
            for (int th = 0; th < 2; th++) {
                float lm = s[0][2 * th];
                #pragma unroll
                for (int nb = 0; nb < 4; nb++)
                    lm = fmaxf(lm, fmaxf(s[nb][2 * th], s[nb][2 * th + 1]));
                lm = fmaxf(lm, __shfl_xor_sync(0xffffffffu, lm, 1));
                lm = fmaxf(lm, __shfl_xor_sync(0xffffffffu, lm, 2));
                float mn = fmaxf(mrow[th], lm);
                float corr = expapx(mrow[th] - mn);
                mrow[th] = mn;
                float rs = 0.f;
                #pragma unroll
                for (int nb = 0; nb < 4; nb++) {
                    s[nb][2 * th]     = expapx(s[nb][2 * th] - mn);
                    s[nb][2 * th + 1] = expapx(s[nb][2 * th + 1] - mn);
                    rs += s[nb][2 * th] + s[nb][2 * th + 1];
                }
                rs += __shfl_xor_sync(0xffffffffu, rs, 1);
                rs += __shfl_xor_sync(0xffffffffu, rs, 2);
                ssum[th] = ssum[th] * corr + rs;
                #pragma unroll
                for (int nb = 0; nb < 4; nb++) {
                    O[nb][2 * th]     *= corr;
                    O[nb][2 * th + 1] *= corr;
                }
            }

            #pragma unroll
            for (int kc = 0; kc < 2; kc++) {
                unsigned pa[4];
                pa[0] = f16pair(s[2 * kc][0],     s[2 * kc][1]);
                pa[1] = f16pair(s[2 * kc][2],     s[2 * kc][3]);
                pa[2] = f16pair(s[2 * kc + 1][0], s[2 * kc + 1][1]);
                pa[3] = f16pair(s[2 * kc + 1][2], s[2 * kc + 1][3]);
                mma_fp(O[0], pa, vf[kc][0][0], vf[kc][0][1]);
                mma_fp(O[1], pa, vf[kc][0][2], vf[kc][0][3]);
                mma_fp(O[2], pa, vf[kc][1][0], vf[kc][1][1]);
                mma_fp(O[3], pa, vf[kc][1][2], vf[kc][1][3]);
            }
        }

        float inv[2] = {1.f / ssum[0], 1.f / ssum[1]};
        #pragma unroll
        for (int th = 0; th < 2; th++) {
            int rl = wid * 16 + (lane >> 2) + th * 8;
            if (ssel[rl] == psel) {
                size_t base = ((size_t)(b * KK + qt * 64 + rl)) * DD + h * HD;
                #pragma unroll
                for (int nb = 0; nb < 4; nb++) {
                    int col = nb * 8 + kc0;
                    float v0 = O[nb][2 * th] * inv[th];
                    float v1 = O[nb][2 * th + 1] * inv[th];
                    f16 h0, l0, h1, l1;
                    split_f16(v0, &h0, &l0);
                    split_f16(v1, &h1, &l1);
                    *(__half2*)&g_at_h[base + col] = __halves2half2(h0, h1);
                    *(__half2*)&g_at_l[base + col] = __halves2half2(l0, l1);
                }
            }
        }
    }
}

// ---------------- residual + LN (unsort via qpos) ----------------------------
__global__ __launch_bounds__(256) void resln_kernel(
    const float* __restrict__ gn, const float* __restrict__ bn,
    const float* __restrict__ bo_c, const float* __restrict__ bo_t)
{
    int mrow = blockIdx.x;
    int d = threadIdx.x;
    int b = mrow >> 10, k = mrow & 1023;
    int sel = g_isctx[b * KK + k];
    int pos = g_qpos[b * KK + k];

    __shared__ float red[2][8];
    float att = g_tmp2[((size_t)(b * 1024 + pos)) * DD + d]
              + (sel ? bo_c[d] : bo_t[d]);
    float v = g_xfull[((size_t)(b * LL + RR + k)) * DD + d] + att;
    g_x2[(size_t)mrow * DD + d] = v;

    float s1 = v, s2 = v * v;
    #pragma unroll
    for (int o = 16; o; o >>= 1) {
        s1 += __shfl_down_sync(0xffffffffu, s1, o);
        s2 += __shfl_down_sync(0xffffffffu, s2, o);
    }
    int wid = d >> 5, lane = d & 31;
    if (lane == 0) { red[0][wid] = s1; red[1][wid] = s2; }
    __syncthreads();
    if (d == 0) {
        float t1 = 0.f, t2 = 0.f;
        #pragma unroll
        for (int i = 0; i < 8; i++) { t1 += red[0][i]; t2 += red[1][i]; }
        red[0][0] = t1; red[1][0] = t2;
    }
    __syncthreads();
    float mean = red[0][0] * (1.f / DD);
    float var  = red[1][0] * (1.f / DD) - mean * mean;
    float rstd = rsqrtf(var + 1e-5f);
    float xnv = (v - mean) * rstd * gn[d] + bn[d];
    size_t gi = (size_t)mrow * DD + d;
    split_f16(xnv, g_x2n_h + gi, g_x2n_l + gi);
}

// ---------------- launch ------------------------------------------------------
static void* sym(const void* s)
{
    void* p = nullptr;
    cudaGetSymbolAddress(&p, s);
    return p;
}

extern "C" void kernel_launch(void* const* d_in, const int* in_sizes, int n_in,
                              void* d_out, int out_size)
{
    const float* x          = (const float*)d_in[0];
    const int*   coords     = (const int*)d_in[1];
    const int*   ctxid      = (const int*)d_in[2];
    const float* tgt_e      = (const float*)d_in[3];
    const float* ctx_e      = (const float*)d_in[4];
    const float* regs       = (const float*)d_in[5];
    const float* rope       = (const float*)d_in[6];
    const float* norm_g     = (const float*)d_in[7];
    const float* norm_b     = (const float*)d_in[8];
    const float* ctx_Wqkv   = (const float*)d_in[9];
    const float* ctx_bqkv   = (const float*)d_in[10];
    const float* ctx_Wo     = (const float*)d_in[11];
    const float* ctx_bo     = (const float*)d_in[12];
    const float* tgt_Wqkv   = (const float*)d_in[13];
    const float* tgt_bqkv   = (const float*)d_in[14];
    const float* tgt_Wo     = (const float*)d_in[15];
    const float* tgt_bo     = (const float*)d_in[16];
    const float* mlpn_g     = (const float*)d_in[17];
    const float* mlpn_b     = (const float*)d_in[18];
    const float* mlp_W1     = (const float*)d_in[19];
    const float* mlp_b1     = (const float*)d_in[20];
    const float* mlp_W2     = (const float*)d_in[21];
    const float* mlp_b2     = (const float*)d_in[22];
    float* out = (float*)d_out;

    f16* wq_h  = (f16*)sym(g_wq_h);
    f16* wo_h  = (f16*)sym(g_wo_h);
    f16* w1_h  = (f16*)sym(g_w1_h);
    f16* w2_h  = (f16*)sym(g_w2_h);
    f16* xn_h  = (f16*)sym(g_xn_h);  f16* xn_l  = (f16*)sym(g_xn_l);
    f16* at_h  = (f16*)sym(g_at_h);  f16* at_l  = (f16*)sym(g_at_l);
    f16* x2n_h = (f16*)sym(g_x2n_h); f16* x2n_l = (f16*)sym(g_x2n_l);
    f16* h1_h  = (f16*)sym(g_h1_h);  f16* h1_l  = (f16*)sym(g_h1_l);
    float* p_bq2  = (float*)sym(g_bq2);
    float* p_tmp2 = (float*)sym(g_tmp2);
    float* p_x2   = (float*)sym(g_x2);
    float* p_zb   = (float*)sym(g_zerob);
    int*   p_nctx = (int*)sym(g_nctx);

    cudaFuncSetAttribute(mma_gemm<3,0>, cudaFuncAttributeMaxDynamicSharedMemorySize, GEMM_SMEM);
    cudaFuncSetAttribute(mma_gemm<0,1>, cudaFuncAttributeMaxDynamicSharedMemorySize, GEMM_SMEM);
    cudaFuncSetAttribute(mma_gemm<1,0>, cudaFuncAttributeMaxDynamicSharedMemorySize, GEMM_SMEM);
    cudaFuncSetAttribute(mma_gemm<2,0>, cudaFuncAttributeMaxDynamicSharedMemorySize, GEMM_SMEM);

    // 1) embed + rope + LN
    prep_kernel<<<BB * LL, 256>>>(x, coords, ctxid, tgt_e, ctx_e, regs, rope,
                                  norm_g, norm_b);
    // 1b) compaction (parallel scans)
    compact_kernel<<<BB, 128>>>();

    // 1c) weight conversion + QKV bias concat (fused)
    convw_all<<<4102, 256>>>(ctx_Wqkv, tgt_Wqkv, ctx_Wo, tgt_Wo, mlp_W1, mlp_W2,
                             ctx_bqkv, tgt_bqkv);

    // 2) merged QKV GEMM (N=1536, fp16 2-phase) with fused Q/K/V scatter
    {
        dim3 g(12, (BB * LL + 127) / 128);
        mma_gemm<3,0><<<g, 256, GEMM_SMEM>>>(xn_h, xn_l, wq_h, p_bq2,
                                             nullptr, nullptr, nullptr, nullptr,
                                             BB * LL, 6 * DD, DD, nullptr);
    }

    // 3) tensor-core flash attention (fp16, sorted-row output)
    {
        dim3 g(KK / 64, HH, BB);
        attn_mma<<<g, 128>>>(ctx_bqkv, tgt_bqkv);
    }

    // 4) Wo GEMM on sorted rows (fp16 2-phase), per-tile weight bank
    {
        dim3 g(2, BB * KK / 128, 2);
        mma_gemm<0,1><<<g, 256, GEMM_SMEM>>>(at_h, at_l, wo_h, p_zb,
                                             nullptr, p_tmp2, nullptr, nullptr,
                                             BB * KK, DD, DD, p_nctx);
    }

    // 5) residual + LN (unsort) -> fp16 hi/lo
    resln_kernel<<<BB * KK, 256>>>(mlpn_g, mlpn_b, ctx_bo, tgt_bo);

    // 6) MLP up + gelu (fp16 2-phase)
    {
        dim3 g(8, BB * KK / 128);
        mma_gemm<1,0><<<g, 256, GEMM_SMEM>>>(x2n_h, x2n_l, w1_h, mlp_b1,
                                             nullptr, nullptr, h1_h, h1_l,
                                             BB * KK, 4 * DD, DD, nullptr);
    }

    // 7) MLP down + residual -> out (fp16 2-phase)
    {
        dim3 g(2, BB * KK / 128);
        mma_gemm<2,0><<<g, 256, GEMM_SMEM>>>(h1_h, h1_l, w2_h, mlp_b2,
                                             p_x2, out, nullptr, nullptr,
                                             BB * KK, DD, 4 * DD, nullptr);
    }
}